// round 5
// baseline (speedup 1.0000x reference)
#include <cuda_runtime.h>
#include <cuda_bf16.h>
#include <math.h>
#include <stdint.h>

#define BATCH 4
#define CH    64
#define HH    192
#define WWID  192
#define HW    (HH*WWID)
#define BHW   (BATCH*HW)

// ---------------- device scratch (allocation-free) ----------------
__device__ float    g_x1 [BHW*CH];      // NHWC
__device__ float    g_x2 [BHW*CH];      // NHWC
__device__ float    g_y  [BHW*CH];      // NHWC ping-pong
__device__ float    g_off[98*BHW];      // PLANAR offsets [ch][pixel]
__device__ uint32_t g_wA [25*32*128];   // packed offset-conv weights [tap][kpair][ocPad]
__device__ uint32_t g_wB [49*32*64];    // packed deform weights      [tap][kpair][oc]
__device__ uint32_t g_wC [32*64];       // packed w_out               [kpair][oc]

// ---------------- bf16 helpers --------------------------------------------
static __device__ __forceinline__ uint32_t packbf2(float lo, float hi) {
    uint32_t r;
    asm("cvt.rn.bf16x2.f32 %0, %1, %2;" : "=r"(r) : "f"(hi), "f"(lo));
    return r;
}
static __device__ __forceinline__ void mma_bf16(float* d, const uint32_t* a,
                                                const uint32_t* b) {
    asm volatile(
        "mma.sync.aligned.m16n8k16.row.col.f32.bf16.bf16.f32 "
        "{%0,%1,%2,%3},{%4,%5,%6,%7},{%8,%9},{%0,%1,%2,%3};"
        : "+f"(d[0]), "+f"(d[1]), "+f"(d[2]), "+f"(d[3])
        : "r"(a[0]), "r"(a[1]), "r"(a[2]), "r"(a[3]), "r"(b[0]), "r"(b[1]));
}

// ---------------- weight transpose+pack: w[O][C][K2] -> out[tap][kp][ocPad] -
__global__ void k_transpose_bf(const float* __restrict__ w, uint32_t* __restrict__ out,
                               int K2, int KOUT, int KOUTP) {
    int n = K2 * 32 * KOUTP;
    for (int idx = blockIdx.x * blockDim.x + threadIdx.x; idx < n;
         idx += gridDim.x * blockDim.x) {
        int oc  = idx % KOUTP;
        int kp  = (idx / KOUTP) % 32;
        int tap = idx / (KOUTP * 32);
        float lo = 0.f, hi = 0.f;
        if (oc < KOUT) {
            lo = w[(oc * 64 + 2 * kp)     * K2 + tap];
            hi = w[(oc * 64 + 2 * kp + 1) * K2 + tap];
        }
        out[idx] = packbf2(lo, hi);
    }
}

// ---------------- fused LayerNorm + 1x1 conv (w_in: 64 -> 128) -------------
__global__ __launch_bounds__(256) void k_ln_win(
    const float* __restrict__ x, const float* __restrict__ ln_w,
    const float* __restrict__ ln_b, const float* __restrict__ w_in,
    const float* __restrict__ b_in, float* __restrict__ out1,
    float* __restrict__ out2)
{
    __shared__ float wT[64 * 128];   // [c][o]
    __shared__ float hb[8][64];
    int tid = threadIdx.x;
    for (int idx = tid; idx < 8192; idx += 256) {
        int o = idx >> 6, c = idx & 63;
        wT[c * 128 + o] = w_in[idx];
    }
    int wp = tid >> 5, lane = tid & 31;
    int pg = blockIdx.x * 8 + wp;
    int b = pg / HW, hw = pg % HW;
    const float* xb = x + (size_t)b * CH * HW + hw;
    float v0 = xb[(size_t)lane * HW];
    float v1 = xb[(size_t)(lane + 32) * HW];
    float s = v0 + v1, q = v0 * v0 + v1 * v1;
    #pragma unroll
    for (int o = 16; o; o >>= 1) {
        s += __shfl_xor_sync(0xffffffffu, s, o);
        q += __shfl_xor_sync(0xffffffffu, q, o);
    }
    float mu  = s * (1.f / 64.f);
    float var = q * (1.f / 64.f) - mu * mu;
    float rs  = rsqrtf(var + 1e-5f);
    hb[wp][lane]      = (v0 - mu) * rs * ln_w[lane]      + ln_b[lane];
    hb[wp][lane + 32] = (v1 - mu) * rs * ln_w[lane + 32] + ln_b[lane + 32];
    __syncthreads();
    float a0 = b_in[lane], a1 = b_in[lane + 32];
    float a2 = b_in[lane + 64], a3 = b_in[lane + 96];
    #pragma unroll 8
    for (int c = 0; c < 64; c++) {
        float hv = hb[wp][c];
        const float* wr = &wT[c * 128 + lane];
        a0 += hv * wr[0];  a1 += hv * wr[32];
        a2 += hv * wr[64]; a3 += hv * wr[96];
    }
    float* o1 = out1 + (size_t)pg * 64;
    float* o2 = out2 + (size_t)pg * 64;
    o1[lane] = a0; o1[lane + 32] = a1;
    o2[lane] = a2; o2[lane + 32] = a3;
}

// ---------------- dense KxK conv, bf16 MMA, HALO-tiled ----------------------
template<int K, int PAD, int KOUT, int KOUTP, int SPAN>
__global__ __launch_bounds__(256) void k_conv_tc(
    const float* __restrict__ in, const uint32_t* __restrict__ wT,
    const float* __restrict__ bias, float* __restrict__ out)
{
    constexpr int HX = 16 + K - 1, HY = 8 + K - 1, HPX = HX * HY;
    constexpr int NT = SPAN / 16;
    constexpr int SPANP = SPAN + 4;
    extern __shared__ uint32_t sm[];
    uint32_t* As = sm;                 // [HPX][36] bf16x2 words (c-pairs)
    uint32_t* Bs = sm + HPX * 36;      // [32 kpair][SPANP] bf16x2 words
    int tid = threadIdx.x, lane = tid & 31, w = tid >> 5;
    int q = lane >> 2, r = lane & 3;
    int pxg = w >> 1, ocg = w & 1;
    int b = blockIdx.z;
    int ty0 = blockIdx.y * 8, tx0 = blockIdx.x * 16;
    float acc[2][NT][4] = {};

    // halo fill (once)
    for (int idx = tid; idx < HPX * 32; idx += 256) {
        int hp = idx >> 5, c2 = idx & 31;
        int hy = hp / HX, hx = hp % HX;
        int yy = ty0 + hy - PAD, xx = tx0 + hx - PAD;
        float2 val = make_float2(0.f, 0.f);
        if (yy >= 0 && yy < HH && xx >= 0 && xx < WWID)
            val = *(const float2*)(in + ((size_t)((b * HH + yy) * WWID + xx)) * 64 + 2 * c2);
        As[hp * 36 + c2] = packbf2(val.x, val.y);
    }

    for (int tap = 0; tap < K * K; tap++) {
        int ki = tap / K, kj = tap % K;
        __syncthreads();
        for (int idx = tid; idx < 32 * SPAN; idx += 256) {
            int kp = idx / SPAN, oc = idx % SPAN;
            Bs[kp * SPANP + oc] = wT[((size_t)tap * 32 + kp) * KOUTP + oc];
        }
        __syncthreads();
        #pragma unroll
        for (int kc = 0; kc < 4; kc++) {
            uint32_t a[2][4];
            #pragma unroll
            for (int m = 0; m < 2; m++) {
                int hbase = (pxg * 2 + m + ki) * HX + kj;
                const uint32_t* Ap = As + (hbase + q) * 36 + kc * 8 + r;
                a[m][0] = Ap[0];
                a[m][1] = Ap[8 * 36];
                a[m][2] = Ap[4];
                a[m][3] = Ap[8 * 36 + 4];
            }
            #pragma unroll
            for (int nt = 0; nt < NT; nt++) {
                uint32_t bb[2];
                int ocb = ocg * (SPAN / 2) + nt * 8 + q;
                bb[0] = Bs[(kc * 8 + r)     * SPANP + ocb];
                bb[1] = Bs[(kc * 8 + r + 4) * SPANP + ocb];
                mma_bf16(acc[0][nt], a[0], bb);
                mma_bf16(acc[1][nt], a[1], bb);
            }
        }
    }
    // store PLANAR [oc][pixel] with bias
    #pragma unroll
    for (int m = 0; m < 2; m++) {
        #pragma unroll
        for (int nt = 0; nt < NT; nt++) {
            #pragma unroll
            for (int hh = 0; hh < 2; hh++) {
                int p  = pxg * 32 + m * 16 + q + hh * 8;
                int pg = (b * HH + ty0 + (p >> 4)) * WWID + tx0 + (p & 15);
                int oc = ocg * (SPAN / 2) + nt * 8 + 2 * r;
                float v0 = acc[m][nt][hh * 2 + 0];
                float v1 = acc[m][nt][hh * 2 + 1];
                if (oc     < KOUT) out[(size_t)oc       * BHW + pg] = v0 + bias[oc];
                if (oc + 1 < KOUT) out[(size_t)(oc + 1) * BHW + pg] = v1 + bias[oc + 1];
            }
        }
    }
}

// ---------------- deformable KxK conv (Cout=64), bf16 MMA + smem halo -------
template<int K, int PAD>
__global__ __launch_bounds__(256) void k_deform_tc(
    const float* __restrict__ in, const float* __restrict__ off,
    const uint32_t* __restrict__ wT, const float* __restrict__ bias,
    float* __restrict__ out)
{
    constexpr int M  = PAD + 1;
    constexpr int HX = 16 + 2 * M, HY = 8 + 2 * M, HPX = HX * HY;
    extern __shared__ uint32_t sm[];
    uint32_t* Hs = sm;                  // [HPX][32] bf16x2 halo
    uint32_t* As = sm + HPX * 32;       // [128][36]
    uint32_t* Bs = As + 128 * 36;       // [32][68]

    int tid = threadIdx.x, lane = tid & 31, w = tid >> 5;
    int q = lane >> 2, r = lane & 3;
    int pxg = w >> 1, ocg = w & 1;
    int b = blockIdx.z;
    int ty0 = blockIdx.y * 8, tx0 = blockIdx.x * 16;
    const float* base = in + (size_t)b * HW * 64;
    float acc[2][4][4] = {};

    // halo fill (once); out-of-image cells = 0 (matches reference masking)
    for (int idx = tid; idx < HPX * 32; idx += 256) {
        int hp = idx >> 5, c2 = idx & 31;
        int hy = hp / HX, hx = hp % HX;
        int yy = ty0 + hy - M, xx = tx0 + hx - M;
        float2 val = make_float2(0.f, 0.f);
        if (yy >= 0 && yy < HH && xx >= 0 && xx < WWID)
            val = *(const float2*)(base + ((size_t)(yy * WWID + xx)) * 64 + 2 * c2);
        Hs[hp * 32 + c2] = packbf2(val.x, val.y);
    }

    for (int tap = 0; tap < K * K; tap++) {
        int ki = tap / K, kj = tap % K;
        __syncthreads();
        for (int idx = tid; idx < 2048; idx += 256) {
            int kp = idx >> 6, oc = idx & 63;
            Bs[kp * 68 + oc] = wT[((size_t)tap * 32 + kp) * 64 + oc];
        }
        // bilinear sampling -> As[p][c2]; warp handles one pixel per iter
        #pragma unroll 4
        for (int it = 0; it < 16; it++) {
            int p  = it * 8 + w;
            int c2 = lane;
            int yy = ty0 + (p >> 4), xx = tx0 + (p & 15);
            int pg = (b * HH + yy) * WWID + xx;
            float oy = __ldg(off + (size_t)(2 * tap)     * BHW + pg);
            float ox = __ldg(off + (size_t)(2 * tap + 1) * BHW + pg);
            float py = (float)(yy + ki - PAD) + oy;
            float px = (float)(xx + kj - PAD) + ox;
            float fy = floorf(py), fx = floorf(px);
            int y0 = (int)fy, x0 = (int)fx;
            float wy = py - fy, wx = px - fx;
            float f00 = (1.f - wy) * (1.f - wx);
            float f01 = (1.f - wy) * wx;
            float f10 = wy * (1.f - wx);
            float f11 = wy * wx;
            int hy = y0 - ty0 + M, hx = x0 - tx0 + M;
            uint32_t res;
            if (hy >= 0 && hy < HY - 1 && hx >= 0 && hx < HX - 1) {
                const __nv_bfloat162* Hp =
                    (const __nv_bfloat162*)(Hs + (hy * HX + hx) * 32 + c2);
                __nv_bfloat162 v00 = Hp[0];
                __nv_bfloat162 v01 = Hp[32];
                __nv_bfloat162 v10 = Hp[HX * 32];
                __nv_bfloat162 v11 = Hp[HX * 32 + 32];
                __nv_bfloat162 acc2 = __hmul2(__float2bfloat162_rn(f00), v00);
                acc2 = __hfma2(__float2bfloat162_rn(f01), v01, acc2);
                acc2 = __hfma2(__float2bfloat162_rn(f10), v10, acc2);
                acc2 = __hfma2(__float2bfloat162_rn(f11), v11, acc2);
                res = *(uint32_t*)&acc2;
            } else {
                bool yv0 = (unsigned)y0       < HH;
                bool yv1 = (unsigned)(y0 + 1) < HH;
                bool xv0 = (unsigned)x0       < WWID;
                bool xv1 = (unsigned)(x0 + 1) < WWID;
                long long r0 = ((long long)y0 * WWID + x0) * 64 + 2 * c2;
                float2 v00 = make_float2(0.f, 0.f), v01 = v00, v10 = v00, v11 = v00;
                if (yv0 && xv0) v00 = *(const float2*)(base + r0);
                if (yv0 && xv1) v01 = *(const float2*)(base + r0 + 64);
                if (yv1 && xv0) v10 = *(const float2*)(base + r0 + 64 * WWID);
                if (yv1 && xv1) v11 = *(const float2*)(base + r0 + 64 * WWID + 64);
                float rx = f00 * v00.x + f01 * v01.x + f10 * v10.x + f11 * v11.x;
                float ry = f00 * v00.y + f01 * v01.y + f10 * v10.y + f11 * v11.y;
                res = packbf2(rx, ry);
            }
            As[p * 36 + c2] = res;
        }
        __syncthreads();
        #pragma unroll
        for (int kc = 0; kc < 4; kc++) {
            uint32_t a[2][4];
            #pragma unroll
            for (int m = 0; m < 2; m++) {
                int pr = pxg * 32 + m * 16;
                const uint32_t* Ap = As + (pr + q) * 36 + kc * 8 + r;
                a[m][0] = Ap[0];
                a[m][1] = Ap[8 * 36];
                a[m][2] = Ap[4];
                a[m][3] = Ap[8 * 36 + 4];
            }
            #pragma unroll
            for (int nt = 0; nt < 4; nt++) {
                uint32_t bb[2];
                int ocb = ocg * 32 + nt * 8 + q;
                bb[0] = Bs[(kc * 8 + r)     * 68 + ocb];
                bb[1] = Bs[(kc * 8 + r + 4) * 68 + ocb];
                mma_bf16(acc[0][nt], a[0], bb);
                mma_bf16(acc[1][nt], a[1], bb);
            }
        }
    }
    #pragma unroll
    for (int m = 0; m < 2; m++) {
        #pragma unroll
        for (int nt = 0; nt < 4; nt++) {
            #pragma unroll
            for (int hh = 0; hh < 2; hh++) {
                int p  = pxg * 32 + m * 16 + q + hh * 8;
                int pg = (b * HH + ty0 + (p >> 4)) * WWID + tx0 + (p & 15);
                int oc = ocg * 32 + nt * 8 + 2 * r;
                float2 v;
                v.x = acc[m][nt][hh * 2 + 0] + bias[oc];
                v.y = acc[m][nt][hh * 2 + 1] + bias[oc + 1];
                *(float2*)(out + (size_t)pg * 64 + oc) = v;
            }
        }
    }
}

// ---------------- final: (x1+x2) @ w_out^T + b_out + residual, bf16 MMA ----
__global__ __launch_bounds__(256) void k_final_tc(
    const float* __restrict__ x1, const float* __restrict__ x2,
    const float* __restrict__ xin, const uint32_t* __restrict__ wC,
    const float* __restrict__ b_out, float* __restrict__ out)
{
    __shared__ uint32_t As[128 * 36];
    __shared__ uint32_t Bs[32 * 68];
    int tid = threadIdx.x, lane = tid & 31, w = tid >> 5;
    int q = lane >> 2, r = lane & 3;
    int pxg = w >> 1, ocg = w & 1;
    size_t p0 = (size_t)blockIdx.x * 128;
    for (int idx = tid; idx < 2048; idx += 256) {
        int kp = idx >> 6, oc = idx & 63;
        Bs[kp * 68 + oc] = wC[kp * 64 + oc];
    }
    for (int idx = tid; idx < 128 * 32; idx += 256) {
        int p = idx >> 5, c2 = idx & 31;
        float2 a = *(const float2*)(x1 + (p0 + p) * 64 + 2 * c2);
        float2 bb = *(const float2*)(x2 + (p0 + p) * 64 + 2 * c2);
        As[p * 36 + c2] = packbf2(a.x + bb.x, a.y + bb.y);
    }
    __syncthreads();
    float acc[2][4][4] = {};
    #pragma unroll
    for (int kc = 0; kc < 4; kc++) {
        uint32_t a[2][4];
        #pragma unroll
        for (int m = 0; m < 2; m++) {
            int pr = pxg * 32 + m * 16;
            const uint32_t* Ap = As + (pr + q) * 36 + kc * 8 + r;
            a[m][0] = Ap[0];
            a[m][1] = Ap[8 * 36];
            a[m][2] = Ap[4];
            a[m][3] = Ap[8 * 36 + 4];
        }
        #pragma unroll
        for (int nt = 0; nt < 4; nt++) {
            uint32_t bb[2];
            int ocb = ocg * 32 + nt * 8 + q;
            bb[0] = Bs[(kc * 8 + r)     * 68 + ocb];
            bb[1] = Bs[(kc * 8 + r + 4) * 68 + ocb];
            mma_bf16(acc[0][nt], a[0], bb);
            mma_bf16(acc[1][nt], a[1], bb);
        }
    }
    int b = (int)(p0 / HW);
    int hwbase = (int)(p0 % HW);
    #pragma unroll
    for (int m = 0; m < 2; m++) {
        #pragma unroll
        for (int nt = 0; nt < 4; nt++) {
            #pragma unroll
            for (int hh = 0; hh < 2; hh++) {
                int p  = pxg * 32 + m * 16 + q + hh * 8;
                int hw = hwbase + p;
                int oc = ocg * 32 + nt * 8 + 2 * r;
                size_t a0 = ((size_t)b * 64 + oc) * HW + hw;
                size_t a1 = a0 + HW;
                out[a0] = acc[m][nt][hh * 2 + 0] + b_out[oc]     + xin[a0];
                out[a1] = acc[m][nt][hh * 2 + 1] + b_out[oc + 1] + xin[a1];
            }
        }
    }
}

// ---------------- launch --------------------------------------------------
extern "C" void kernel_launch(void* const* d_in, const int* in_sizes, int n_in,
                              void* d_out, int out_size) {
    const float* x    = (const float*)d_in[0];
    const float* ln_w = (const float*)d_in[1];
    const float* ln_b = (const float*)d_in[2];
    const float* w_in = (const float*)d_in[3];
    const float* b_in = (const float*)d_in[4];
    const float* w_out= (const float*)d_in[5];
    const float* b_out= (const float*)d_in[6];
    const float* dw1  = (const float*)d_in[7];
    const float* db1  = (const float*)d_in[8];
    const float* dw2  = (const float*)d_in[9];
    const float* db2  = (const float*)d_in[10];
    const float* dw3  = (const float*)d_in[11];
    const float* db3  = (const float*)d_in[12];
    const float* ow1  = (const float*)d_in[13];
    const float* ob1  = (const float*)d_in[14];
    const float* ow2  = (const float*)d_in[15];
    const float* ob2  = (const float*)d_in[16];
    const float* ow3  = (const float*)d_in[17];
    const float* ob3  = (const float*)d_in[18];
    float* out = (float*)d_out;

    float *px1, *px2, *py, *poff;
    uint32_t *pwA, *pwB, *pwC;
    cudaGetSymbolAddress((void**)&px1,  g_x1);
    cudaGetSymbolAddress((void**)&px2,  g_x2);
    cudaGetSymbolAddress((void**)&py,   g_y);
    cudaGetSymbolAddress((void**)&poff, g_off);
    cudaGetSymbolAddress((void**)&pwA,  g_wA);
    cudaGetSymbolAddress((void**)&pwB,  g_wB);
    cudaGetSymbolAddress((void**)&pwC,  g_wC);

    const int SMC1 = (20 * 12 * 36 + 32 * 132) * 4;
    const int SMC2 = (20 * 12 * 36 + 32 * 68)  * 4;
    const int SMC3 = (18 * 10 * 36 + 32 * 36)  * 4;
    const int SMD7 = (24 * 16 * 32 + 128 * 36 + 32 * 68) * 4;
    const int SMD5 = (22 * 14 * 32 + 128 * 36 + 32 * 68) * 4;
    const int SMD3 = (20 * 12 * 32 + 128 * 36 + 32 * 68) * 4;

    cudaFuncSetAttribute(k_conv_tc<5,2,98,128,128>, cudaFuncAttributeMaxDynamicSharedMemorySize, SMC1);
    cudaFuncSetAttribute(k_conv_tc<5,2,50,64,64>,   cudaFuncAttributeMaxDynamicSharedMemorySize, SMC2);
    cudaFuncSetAttribute(k_conv_tc<3,1,18,32,32>,   cudaFuncAttributeMaxDynamicSharedMemorySize, SMC3);
    cudaFuncSetAttribute(k_deform_tc<7,3>, cudaFuncAttributeMaxDynamicSharedMemorySize, SMD7);
    cudaFuncSetAttribute(k_deform_tc<5,2>, cudaFuncAttributeMaxDynamicSharedMemorySize, SMD5);
    cudaFuncSetAttribute(k_deform_tc<3,1>, cudaFuncAttributeMaxDynamicSharedMemorySize, SMD3);

    dim3 tiles(WWID / 16, HH / 8, BATCH);   // 16x8 px tiles

    k_ln_win<<<BHW / 8, 256>>>(x, ln_w, ln_b, w_in, b_in, px1, px2);

    // stage 1: offset conv 5x5 -> 98, deform 7x7
    k_transpose_bf<<<256, 256>>>(ow1, pwA, 25, 98, 128);
    k_conv_tc<5,2,98,128,128><<<tiles, 256, SMC1>>>(px1, pwA, ob1, poff);
    k_transpose_bf<<<256, 256>>>(dw1, pwB, 49, 64, 64);
    k_deform_tc<7,3><<<tiles, 256, SMD7>>>(px1, poff, pwB, db1, py);

    // stage 2: offset conv 5x5 -> 50, deform 5x5
    k_transpose_bf<<<256, 256>>>(ow2, pwA, 25, 50, 64);
    k_conv_tc<5,2,50,64,64><<<tiles, 256, SMC2>>>(py, pwA, ob2, poff);
    k_transpose_bf<<<256, 256>>>(dw2, pwB, 25, 64, 64);
    k_deform_tc<5,2><<<tiles, 256, SMD5>>>(py, poff, pwB, db2, px1);

    // stage 3: offset conv 3x3 -> 18, deform 3x3
    k_transpose_bf<<<256, 256>>>(ow3, pwA, 9, 18, 32);
    k_conv_tc<3,1,18,32,32><<<tiles, 256, SMC3>>>(px1, pwA, ob3, poff);
    k_transpose_bf<<<256, 256>>>(dw3, pwB, 9, 64, 64);
    k_deform_tc<3,1><<<tiles, 256, SMD3>>>(px1, poff, pwB, db3, py);

    k_transpose_bf<<<8, 256>>>(w_out, pwC, 1, 64, 64);
    k_final_tc<<<BHW / 128, 256>>>(py, px2, x, pwC, b_out, out);
}

// round 6
// speedup vs baseline: 1.2906x; 1.2906x over previous
#include <cuda_runtime.h>
#include <cuda_bf16.h>
#include <math.h>
#include <stdint.h>

#define BATCH 4
#define CH    64
#define HH    192
#define WWID  192
#define HW    (HH*WWID)
#define BHW   (BATCH*HW)

// ---------------- device scratch (allocation-free) ----------------
__device__ float    g_x1 [BHW*CH];      // NHWC
__device__ float    g_x2 [BHW*CH];      // NHWC
__device__ float    g_y  [BHW*CH];      // NHWC ping-pong
__device__ float    g_off[98*BHW];      // PLANAR offsets [ch][pixel]
__device__ uint32_t g_wA [25*32*128];   // packed offset-conv weights [tap][kpair][ocPad]
__device__ uint32_t g_wB [49*32*64];    // packed deform weights      [tap][kpair][oc]
__device__ uint32_t g_wC [32*64];       // packed w_out               [kpair][oc]

// ---------------- bf16 helpers --------------------------------------------
static __device__ __forceinline__ uint32_t packbf2(float lo, float hi) {
    uint32_t r;
    asm("cvt.rn.bf16x2.f32 %0, %1, %2;" : "=r"(r) : "f"(hi), "f"(lo));
    return r;
}
static __device__ __forceinline__ void mma_bf16(float* d, const uint32_t* a,
                                                const uint32_t* b) {
    asm volatile(
        "mma.sync.aligned.m16n8k16.row.col.f32.bf16.bf16.f32 "
        "{%0,%1,%2,%3},{%4,%5,%6,%7},{%8,%9},{%0,%1,%2,%3};"
        : "+f"(d[0]), "+f"(d[1]), "+f"(d[2]), "+f"(d[3])
        : "r"(a[0]), "r"(a[1]), "r"(a[2]), "r"(a[3]), "r"(b[0]), "r"(b[1]));
}

// ---------------- weight transpose+pack: w[O][C][K2] -> out[tap][kp][ocPad] -
__global__ void k_transpose_bf(const float* __restrict__ w, uint32_t* __restrict__ out,
                               int K2, int KOUT, int KOUTP) {
    int n = K2 * 32 * KOUTP;
    for (int idx = blockIdx.x * blockDim.x + threadIdx.x; idx < n;
         idx += gridDim.x * blockDim.x) {
        int oc  = idx % KOUTP;
        int kp  = (idx / KOUTP) % 32;
        int tap = idx / (KOUTP * 32);
        float lo = 0.f, hi = 0.f;
        if (oc < KOUT) {
            lo = w[(oc * 64 + 2 * kp)     * K2 + tap];
            hi = w[(oc * 64 + 2 * kp + 1) * K2 + tap];
        }
        out[idx] = packbf2(lo, hi);
    }
}

// ---------------- fused LayerNorm + 1x1 conv (w_in: 64 -> 128) -------------
__global__ __launch_bounds__(256) void k_ln_win(
    const float* __restrict__ x, const float* __restrict__ ln_w,
    const float* __restrict__ ln_b, const float* __restrict__ w_in,
    const float* __restrict__ b_in, float* __restrict__ out1,
    float* __restrict__ out2)
{
    __shared__ float wT[64 * 128];   // [c][o]
    __shared__ float hb[8][64];
    int tid = threadIdx.x;
    for (int idx = tid; idx < 8192; idx += 256) {
        int o = idx >> 6, c = idx & 63;
        wT[c * 128 + o] = w_in[idx];
    }
    int wp = tid >> 5, lane = tid & 31;
    int pg = blockIdx.x * 8 + wp;
    int b = pg / HW, hw = pg % HW;
    const float* xb = x + (size_t)b * CH * HW + hw;
    float v0 = xb[(size_t)lane * HW];
    float v1 = xb[(size_t)(lane + 32) * HW];
    float s = v0 + v1, q = v0 * v0 + v1 * v1;
    #pragma unroll
    for (int o = 16; o; o >>= 1) {
        s += __shfl_xor_sync(0xffffffffu, s, o);
        q += __shfl_xor_sync(0xffffffffu, q, o);
    }
    float mu  = s * (1.f / 64.f);
    float var = q * (1.f / 64.f) - mu * mu;
    float rs  = rsqrtf(var + 1e-5f);
    hb[wp][lane]      = (v0 - mu) * rs * ln_w[lane]      + ln_b[lane];
    hb[wp][lane + 32] = (v1 - mu) * rs * ln_w[lane + 32] + ln_b[lane + 32];
    __syncthreads();
    float a0 = b_in[lane], a1 = b_in[lane + 32];
    float a2 = b_in[lane + 64], a3 = b_in[lane + 96];
    #pragma unroll 8
    for (int c = 0; c < 64; c++) {
        float hv = hb[wp][c];
        const float* wr = &wT[c * 128 + lane];
        a0 += hv * wr[0];  a1 += hv * wr[32];
        a2 += hv * wr[64]; a3 += hv * wr[96];
    }
    float* o1 = out1 + (size_t)pg * 64;
    float* o2 = out2 + (size_t)pg * 64;
    o1[lane] = a0; o1[lane + 32] = a1;
    o2[lane] = a2; o2[lane + 32] = a3;
}

// ---------------- dense KxK conv, bf16 MMA, HALO-tiled ----------------------
template<int K, int PAD, int KOUT, int KOUTP, int SPAN>
__global__ __launch_bounds__(256) void k_conv_tc(
    const float* __restrict__ in, const uint32_t* __restrict__ wT,
    const float* __restrict__ bias, float* __restrict__ out)
{
    constexpr int HX = 16 + K - 1, HY = 8 + K - 1, HPX = HX * HY;
    constexpr int NT = SPAN / 16;
    constexpr int SPANP = SPAN + 4;
    extern __shared__ uint32_t sm[];
    uint32_t* As = sm;                 // [HPX][36] bf16x2 words (c-pairs)
    uint32_t* Bs = sm + HPX * 36;      // [32 kpair][SPANP] bf16x2 words
    int tid = threadIdx.x, lane = tid & 31, w = tid >> 5;
    int q = lane >> 2, r = lane & 3;
    int pxg = w >> 1, ocg = w & 1;
    int b = blockIdx.z;
    int ty0 = blockIdx.y * 8, tx0 = blockIdx.x * 16;
    float acc[2][NT][4] = {};

    // halo fill (once)
    for (int idx = tid; idx < HPX * 32; idx += 256) {
        int hp = idx >> 5, c2 = idx & 31;
        int hy = hp / HX, hx = hp % HX;
        int yy = ty0 + hy - PAD, xx = tx0 + hx - PAD;
        float2 val = make_float2(0.f, 0.f);
        if (yy >= 0 && yy < HH && xx >= 0 && xx < WWID)
            val = *(const float2*)(in + ((size_t)((b * HH + yy) * WWID + xx)) * 64 + 2 * c2);
        As[hp * 36 + c2] = packbf2(val.x, val.y);
    }

    for (int tap = 0; tap < K * K; tap++) {
        int ki = tap / K, kj = tap % K;
        __syncthreads();
        for (int idx = tid; idx < 32 * SPAN; idx += 256) {
            int kp = idx / SPAN, oc = idx % SPAN;
            Bs[kp * SPANP + oc] = wT[((size_t)tap * 32 + kp) * KOUTP + oc];
        }
        __syncthreads();
        #pragma unroll
        for (int kc = 0; kc < 4; kc++) {
            uint32_t a[2][4];
            #pragma unroll
            for (int m = 0; m < 2; m++) {
                int hbase = (pxg * 2 + m + ki) * HX + kj;
                const uint32_t* Ap = As + (hbase + q) * 36 + kc * 8 + r;
                a[m][0] = Ap[0];
                a[m][1] = Ap[8 * 36];
                a[m][2] = Ap[4];
                a[m][3] = Ap[8 * 36 + 4];
            }
            #pragma unroll
            for (int nt = 0; nt < NT; nt++) {
                uint32_t bb[2];
                int ocb = ocg * (SPAN / 2) + nt * 8 + q;
                bb[0] = Bs[(kc * 8 + r)     * SPANP + ocb];
                bb[1] = Bs[(kc * 8 + r + 4) * SPANP + ocb];
                mma_bf16(acc[0][nt], a[0], bb);
                mma_bf16(acc[1][nt], a[1], bb);
            }
        }
    }
    // store PLANAR [oc][pixel] with bias
    #pragma unroll
    for (int m = 0; m < 2; m++) {
        #pragma unroll
        for (int nt = 0; nt < NT; nt++) {
            #pragma unroll
            for (int hh = 0; hh < 2; hh++) {
                int p  = pxg * 32 + m * 16 + q + hh * 8;
                int pg = (b * HH + ty0 + (p >> 4)) * WWID + tx0 + (p & 15);
                int oc = ocg * (SPAN / 2) + nt * 8 + 2 * r;
                float v0 = acc[m][nt][hh * 2 + 0];
                float v1 = acc[m][nt][hh * 2 + 1];
                if (oc     < KOUT) out[(size_t)oc       * BHW + pg] = v0 + bias[oc];
                if (oc + 1 < KOUT) out[(size_t)(oc + 1) * BHW + pg] = v1 + bias[oc + 1];
            }
        }
    }
}

// ---------------- deformable KxK conv (Cout=64), bf16 MMA (R4 structure) ----
template<int K, int PAD>
__global__ __launch_bounds__(256) void k_deform_tc(
    const float* __restrict__ in, const float* __restrict__ off,
    const uint32_t* __restrict__ wT, const float* __restrict__ bias,
    float* __restrict__ out)
{
    extern __shared__ uint32_t sm[];
    uint32_t* As = sm;                       // [128][36] bf16x2
    uint32_t* Bs = sm + 128 * 36;            // [32][68] bf16x2
    float* w00 = (float*)(Bs + 32 * 68);     // 4 x 128 bilinear weights
    float* w01 = w00 + 128;
    float* w10 = w01 + 128;
    float* w11 = w10 + 128;
    int*   s_y0 = (int*)(w11 + 128);
    int*   s_x0 = s_y0 + 128;

    int tid = threadIdx.x, lane = tid & 31, w = tid >> 5;
    int q = lane >> 2, r = lane & 3;
    int pxg = w >> 1, ocg = w & 1;
    int b = blockIdx.z;
    int ty0 = blockIdx.y * 8, tx0 = blockIdx.x * 16;
    const float* base = in + (size_t)b * HW * 64;
    float acc[2][4][4] = {};

    for (int tap = 0; tap < K * K; tap++) {
        int ki = tap / K, kj = tap % K;
        __syncthreads();
        for (int idx = tid; idx < 2048; idx += 256) {
            int kp = idx >> 6, oc = idx & 63;
            Bs[kp * 68 + oc] = wT[((size_t)tap * 32 + kp) * 64 + oc];
        }
        if (tid < 128) {
            int p  = tid;
            int yy = ty0 + (p >> 4), xx = tx0 + (p & 15);
            int pg = (b * HH + yy) * WWID + xx;
            float oy = off[(size_t)(2 * tap)     * BHW + pg];
            float ox = off[(size_t)(2 * tap + 1) * BHW + pg];
            float py = (float)(yy + ki - PAD) + oy;
            float px = (float)(xx + kj - PAD) + ox;
            float fy = floorf(py), fx = floorf(px);
            float wy = py - fy,    wx = px - fx;
            s_y0[p] = (int)fy; s_x0[p] = (int)fx;
            w00[p] = (1.f - wy) * (1.f - wx);
            w01[p] = (1.f - wy) * wx;
            w10[p] = wy * (1.f - wx);
            w11[p] = wy * wx;
        }
        __syncthreads();
        #pragma unroll 4
        for (int it = 0; it < 16; it++) {
            int v  = it * 256 + tid;
            int p  = v >> 5, c2 = v & 31;
            int y0 = s_y0[p], x0 = s_x0[p];
            float a00 = w00[p], a01 = w01[p], a10 = w10[p], a11 = w11[p];
            bool yv0 = (unsigned)y0       < HH;
            bool yv1 = (unsigned)(y0 + 1) < HH;
            bool xv0 = (unsigned)x0       < WWID;
            bool xv1 = (unsigned)(x0 + 1) < WWID;
            long long r0 = ((long long)y0 * WWID + x0) * 64 + 2 * c2;
            float2 v00 = make_float2(0.f, 0.f), v01 = v00, v10 = v00, v11 = v00;
            if (yv0 && xv0) v00 = *(const float2*)(base + r0);
            if (yv0 && xv1) v01 = *(const float2*)(base + r0 + 64);
            if (yv1 && xv0) v10 = *(const float2*)(base + r0 + 64 * WWID);
            if (yv1 && xv1) v11 = *(const float2*)(base + r0 + 64 * WWID + 64);
            float rx = a00 * v00.x + a01 * v01.x + a10 * v10.x + a11 * v11.x;
            float ry = a00 * v00.y + a01 * v01.y + a10 * v10.y + a11 * v11.y;
            As[p * 36 + c2] = packbf2(rx, ry);
        }
        __syncthreads();
        #pragma unroll
        for (int kc = 0; kc < 4; kc++) {
            uint32_t a[2][4];
            #pragma unroll
            for (int m = 0; m < 2; m++) {
                int pr = pxg * 32 + m * 16;
                const uint32_t* Ap = As + (pr + q) * 36 + kc * 8 + r;
                a[m][0] = Ap[0];
                a[m][1] = Ap[8 * 36];
                a[m][2] = Ap[4];
                a[m][3] = Ap[8 * 36 + 4];
            }
            #pragma unroll
            for (int nt = 0; nt < 4; nt++) {
                uint32_t bb[2];
                int ocb = ocg * 32 + nt * 8 + q;
                bb[0] = Bs[(kc * 8 + r)     * 68 + ocb];
                bb[1] = Bs[(kc * 8 + r + 4) * 68 + ocb];
                mma_bf16(acc[0][nt], a[0], bb);
                mma_bf16(acc[1][nt], a[1], bb);
            }
        }
    }
    #pragma unroll
    for (int m = 0; m < 2; m++) {
        #pragma unroll
        for (int nt = 0; nt < 4; nt++) {
            #pragma unroll
            for (int hh = 0; hh < 2; hh++) {
                int p  = pxg * 32 + m * 16 + q + hh * 8;
                int pg = (b * HH + ty0 + (p >> 4)) * WWID + tx0 + (p & 15);
                int oc = ocg * 32 + nt * 8 + 2 * r;
                float2 v;
                v.x = acc[m][nt][hh * 2 + 0] + bias[oc];
                v.y = acc[m][nt][hh * 2 + 1] + bias[oc + 1];
                *(float2*)(out + (size_t)pg * 64 + oc) = v;
            }
        }
    }
}

// ---------------- final: (x1+x2) @ w_out^T + b_out + residual, bf16 MMA ----
__global__ __launch_bounds__(256) void k_final_tc(
    const float* __restrict__ x1, const float* __restrict__ x2,
    const float* __restrict__ xin, const uint32_t* __restrict__ wC,
    const float* __restrict__ b_out, float* __restrict__ out)
{
    __shared__ uint32_t As[128 * 36];
    __shared__ uint32_t Bs[32 * 68];
    int tid = threadIdx.x, lane = tid & 31, w = tid >> 5;
    int q = lane >> 2, r = lane & 3;
    int pxg = w >> 1, ocg = w & 1;
    size_t p0 = (size_t)blockIdx.x * 128;
    for (int idx = tid; idx < 2048; idx += 256) {
        int kp = idx >> 6, oc = idx & 63;
        Bs[kp * 68 + oc] = wC[kp * 64 + oc];
    }
    for (int idx = tid; idx < 128 * 32; idx += 256) {
        int p = idx >> 5, c2 = idx & 31;
        float2 a = *(const float2*)(x1 + (p0 + p) * 64 + 2 * c2);
        float2 bb = *(const float2*)(x2 + (p0 + p) * 64 + 2 * c2);
        As[p * 36 + c2] = packbf2(a.x + bb.x, a.y + bb.y);
    }
    __syncthreads();
    float acc[2][4][4] = {};
    #pragma unroll
    for (int kc = 0; kc < 4; kc++) {
        uint32_t a[2][4];
        #pragma unroll
        for (int m = 0; m < 2; m++) {
            int pr = pxg * 32 + m * 16;
            const uint32_t* Ap = As + (pr + q) * 36 + kc * 8 + r;
            a[m][0] = Ap[0];
            a[m][1] = Ap[8 * 36];
            a[m][2] = Ap[4];
            a[m][3] = Ap[8 * 36 + 4];
        }
        #pragma unroll
        for (int nt = 0; nt < 4; nt++) {
            uint32_t bb[2];
            int ocb = ocg * 32 + nt * 8 + q;
            bb[0] = Bs[(kc * 8 + r)     * 68 + ocb];
            bb[1] = Bs[(kc * 8 + r + 4) * 68 + ocb];
            mma_bf16(acc[0][nt], a[0], bb);
            mma_bf16(acc[1][nt], a[1], bb);
        }
    }
    int b = (int)(p0 / HW);
    int hwbase = (int)(p0 % HW);
    #pragma unroll
    for (int m = 0; m < 2; m++) {
        #pragma unroll
        for (int nt = 0; nt < 4; nt++) {
            #pragma unroll
            for (int hh = 0; hh < 2; hh++) {
                int p  = pxg * 32 + m * 16 + q + hh * 8;
                int hw = hwbase + p;
                int oc = ocg * 32 + nt * 8 + 2 * r;
                size_t a0 = ((size_t)b * 64 + oc) * HW + hw;
                size_t a1 = a0 + HW;
                out[a0] = acc[m][nt][hh * 2 + 0] + b_out[oc]     + xin[a0];
                out[a1] = acc[m][nt][hh * 2 + 1] + b_out[oc + 1] + xin[a1];
            }
        }
    }
}

// ---------------- launch --------------------------------------------------
extern "C" void kernel_launch(void* const* d_in, const int* in_sizes, int n_in,
                              void* d_out, int out_size) {
    const float* x    = (const float*)d_in[0];
    const float* ln_w = (const float*)d_in[1];
    const float* ln_b = (const float*)d_in[2];
    const float* w_in = (const float*)d_in[3];
    const float* b_in = (const float*)d_in[4];
    const float* w_out= (const float*)d_in[5];
    const float* b_out= (const float*)d_in[6];
    const float* dw1  = (const float*)d_in[7];
    const float* db1  = (const float*)d_in[8];
    const float* dw2  = (const float*)d_in[9];
    const float* db2  = (const float*)d_in[10];
    const float* dw3  = (const float*)d_in[11];
    const float* db3  = (const float*)d_in[12];
    const float* ow1  = (const float*)d_in[13];
    const float* ob1  = (const float*)d_in[14];
    const float* ow2  = (const float*)d_in[15];
    const float* ob2  = (const float*)d_in[16];
    const float* ow3  = (const float*)d_in[17];
    const float* ob3  = (const float*)d_in[18];
    float* out = (float*)d_out;

    float *px1, *px2, *py, *poff;
    uint32_t *pwA, *pwB, *pwC;
    cudaGetSymbolAddress((void**)&px1,  g_x1);
    cudaGetSymbolAddress((void**)&px2,  g_x2);
    cudaGetSymbolAddress((void**)&py,   g_y);
    cudaGetSymbolAddress((void**)&poff, g_off);
    cudaGetSymbolAddress((void**)&pwA,  g_wA);
    cudaGetSymbolAddress((void**)&pwB,  g_wB);
    cudaGetSymbolAddress((void**)&pwC,  g_wC);

    const int SMC1 = (20 * 12 * 36 + 32 * 132) * 4;
    const int SMC2 = (20 * 12 * 36 + 32 * 68)  * 4;
    const int SMC3 = (18 * 10 * 36 + 32 * 36)  * 4;
    const int SMD  = (128 * 36 + 32 * 68) * 4 + 128 * 6 * 4;

    cudaFuncSetAttribute(k_conv_tc<5,2,98,128,128>, cudaFuncAttributeMaxDynamicSharedMemorySize, SMC1);
    cudaFuncSetAttribute(k_conv_tc<5,2,50,64,64>,   cudaFuncAttributeMaxDynamicSharedMemorySize, SMC2);
    cudaFuncSetAttribute(k_conv_tc<3,1,18,32,32>,   cudaFuncAttributeMaxDynamicSharedMemorySize, SMC3);
    cudaFuncSetAttribute(k_deform_tc<7,3>, cudaFuncAttributeMaxDynamicSharedMemorySize, SMD);
    cudaFuncSetAttribute(k_deform_tc<5,2>, cudaFuncAttributeMaxDynamicSharedMemorySize, SMD);
    cudaFuncSetAttribute(k_deform_tc<3,1>, cudaFuncAttributeMaxDynamicSharedMemorySize, SMD);

    dim3 tiles(WWID / 16, HH / 8, BATCH);   // 16x8 px tiles

    k_ln_win<<<BHW / 8, 256>>>(x, ln_w, ln_b, w_in, b_in, px1, px2);

    // stage 1: offset conv 5x5 -> 98, deform 7x7
    k_transpose_bf<<<256, 256>>>(ow1, pwA, 25, 98, 128);
    k_conv_tc<5,2,98,128,128><<<tiles, 256, SMC1>>>(px1, pwA, ob1, poff);
    k_transpose_bf<<<256, 256>>>(dw1, pwB, 49, 64, 64);
    k_deform_tc<7,3><<<tiles, 256, SMD>>>(px1, poff, pwB, db1, py);

    // stage 2: offset conv 5x5 -> 50, deform 5x5
    k_transpose_bf<<<256, 256>>>(ow2, pwA, 25, 50, 64);
    k_conv_tc<5,2,50,64,64><<<tiles, 256, SMC2>>>(py, pwA, ob2, poff);
    k_transpose_bf<<<256, 256>>>(dw2, pwB, 25, 64, 64);
    k_deform_tc<5,2><<<tiles, 256, SMD>>>(py, poff, pwB, db2, px1);

    // stage 3: offset conv 3x3 -> 18, deform 3x3
    k_transpose_bf<<<256, 256>>>(ow3, pwA, 9, 18, 32);
    k_conv_tc<3,1,18,32,32><<<tiles, 256, SMC3>>>(px1, pwA, ob3, poff);
    k_transpose_bf<<<256, 256>>>(dw3, pwB, 9, 64, 64);
    k_deform_tc<3,1><<<tiles, 256, SMD>>>(px1, poff, pwB, db3, py);

    k_transpose_bf<<<8, 256>>>(w_out, pwC, 1, 64, 64);
    k_final_tc<<<BHW / 128, 256>>>(py, px2, x, pwC, b_out, out);
}

// round 7
// speedup vs baseline: 2.0902x; 1.6195x over previous
#include <cuda_runtime.h>
#include <cuda_bf16.h>
#include <math.h>
#include <stdint.h>

#define BATCH 4
#define CH    64
#define HH    192
#define WWID  192
#define HW    (HH*WWID)
#define BHW   (BATCH*HW)

// ---------------- device scratch (allocation-free) ----------------
__device__ float    g_x1 [BHW*CH];      // NHWC
__device__ float    g_x2 [BHW*CH];      // NHWC
__device__ float    g_y  [BHW*CH];      // NHWC ping-pong
__device__ float    g_off[98*BHW];      // PLANAR offsets [ch][pixel]
__device__ uint32_t g_wA [25*32*128];   // packed offset-conv weights [tap][kpair][ocPad]
__device__ uint32_t g_wB [49*32*64];    // packed deform weights      [tap][kpair][oc]
__device__ uint32_t g_wC [32*64];       // packed w_out               [kpair][oc]
__device__ uint32_t g_wIn[32*128];      // packed w_in                [kpair][oc]

// ---------------- bf16 helpers --------------------------------------------
static __device__ __forceinline__ uint32_t packbf2(float lo, float hi) {
    uint32_t r;
    asm("cvt.rn.bf16x2.f32 %0, %1, %2;" : "=r"(r) : "f"(hi), "f"(lo));
    return r;
}
static __device__ __forceinline__ void mma_bf16(float* d, const uint32_t* a,
                                                const uint32_t* b) {
    asm volatile(
        "mma.sync.aligned.m16n8k16.row.col.f32.bf16.bf16.f32 "
        "{%0,%1,%2,%3},{%4,%5,%6,%7},{%8,%9},{%0,%1,%2,%3};"
        : "+f"(d[0]), "+f"(d[1]), "+f"(d[2]), "+f"(d[3])
        : "r"(a[0]), "r"(a[1]), "r"(a[2]), "r"(a[3]), "r"(b[0]), "r"(b[1]));
}

// ---------------- weight transpose+pack: w[O][C][K2] -> out[tap][kp][ocPad] -
__global__ void k_transpose_bf(const float* __restrict__ w, uint32_t* __restrict__ out,
                               int K2, int KOUT, int KOUTP) {
    int n = K2 * 32 * KOUTP;
    for (int idx = blockIdx.x * blockDim.x + threadIdx.x; idx < n;
         idx += gridDim.x * blockDim.x) {
        int oc  = idx % KOUTP;
        int kp  = (idx / KOUTP) % 32;
        int tap = idx / (KOUTP * 32);
        float lo = 0.f, hi = 0.f;
        if (oc < KOUT) {
            lo = w[(oc * 64 + 2 * kp)     * K2 + tap];
            hi = w[(oc * 64 + 2 * kp + 1) * K2 + tap];
        }
        out[idx] = packbf2(lo, hi);
    }
}

// ---------------- fused LayerNorm + 1x1 conv (64->128), bf16 MMA ------------
// 128 px per block; coalesced NCHW loads; LN stats in registers.
__global__ __launch_bounds__(256) void k_ln_win_tc(
    const float* __restrict__ x, const float* __restrict__ ln_w,
    const float* __restrict__ ln_b, const uint32_t* __restrict__ wIn,
    const float* __restrict__ b_in, float* __restrict__ out1,
    float* __restrict__ out2)
{
    __shared__ uint32_t As[128 * 36];
    __shared__ uint32_t Bs[32 * 132];
    __shared__ float s_sum[2][128], s_sq[2][128];
    __shared__ float s_lw[64], s_lb[64], s_bin[128];
    int tid = threadIdx.x, lane = tid & 31, w = tid >> 5;
    int q = lane >> 2, r = lane & 3;
    int pxg = w >> 1, ocg = w & 1;
    size_t p0 = (size_t)blockIdx.x * 128;
    int b = (int)(p0 / HW);
    int hw0 = (int)(p0 % HW);
    const float* xb = x + (size_t)b * 64 * HW + hw0;

    for (int idx = tid; idx < 1024; idx += 256)
        *(uint4*)(Bs + (idx >> 5) * 132 + 4 * (idx & 31)) =
            ((const uint4*)wIn)[idx];
    if (tid < 64) { s_lw[tid] = ln_w[tid]; s_lb[tid] = ln_b[tid]; }
    if (tid < 128) s_bin[tid] = b_in[tid];

    // load 32 channels per thread (coalesced: lane = pixel), partial stats
    int px = tid & 127, hi2 = tid >> 7;
    float v[32], s = 0.f, sq = 0.f;
    #pragma unroll
    for (int it = 0; it < 32; it++) {
        int c = 2 * it + hi2;
        float val = xb[(size_t)c * HW + px];
        v[it] = val; s += val; sq += val * val;
    }
    s_sum[hi2][px] = s; s_sq[hi2][px] = sq;
    __syncthreads();
    float S = s_sum[0][px] + s_sum[1][px];
    float Q = s_sq[0][px]  + s_sq[1][px];
    float mu = S * (1.f / 64.f);
    float var = Q * (1.f / 64.f) - mu * mu;
    float rs = rsqrtf(var + 1e-5f);
    __nv_bfloat16* Ah = (__nv_bfloat16*)As;
    #pragma unroll
    for (int it = 0; it < 32; it++) {
        int c = 2 * it + hi2;
        float nv = (v[it] - mu) * rs * s_lw[c] + s_lb[c];
        Ah[px * 72 + c] = __float2bfloat16(nv);
    }
    __syncthreads();

    float acc[2][8][4] = {};
    #pragma unroll
    for (int kc = 0; kc < 4; kc++) {
        uint32_t a[2][4];
        #pragma unroll
        for (int m = 0; m < 2; m++) {
            int pr = pxg * 32 + m * 16;
            const uint32_t* Ap = As + (pr + q) * 36 + kc * 8 + r;
            a[m][0] = Ap[0];
            a[m][1] = Ap[8 * 36];
            a[m][2] = Ap[4];
            a[m][3] = Ap[8 * 36 + 4];
        }
        #pragma unroll
        for (int nt = 0; nt < 8; nt++) {
            uint32_t bb[2];
            int ocb = ocg * 64 + nt * 8 + q;
            bb[0] = Bs[(kc * 8 + r)     * 132 + ocb];
            bb[1] = Bs[(kc * 8 + r + 4) * 132 + ocb];
            mma_bf16(acc[0][nt], a[0], bb);
            mma_bf16(acc[1][nt], a[1], bb);
        }
    }
    float* outp = ocg ? out2 : out1;
    #pragma unroll
    for (int m = 0; m < 2; m++) {
        #pragma unroll
        for (int nt = 0; nt < 8; nt++) {
            #pragma unroll
            for (int hh = 0; hh < 2; hh++) {
                int p = pxg * 32 + m * 16 + q + hh * 8;
                int ocl = nt * 8 + 2 * r;
                int ocG = ocg * 64 + ocl;
                float2 vv;
                vv.x = acc[m][nt][hh * 2 + 0] + s_bin[ocG];
                vv.y = acc[m][nt][hh * 2 + 1] + s_bin[ocG + 1];
                *(float2*)(outp + (p0 + p) * 64 + ocl) = vv;
            }
        }
    }
}

// ---------------- dense KxK conv, bf16 MMA, HALO-tiled ----------------------
template<int K, int PAD, int KOUT, int KOUTP, int SPAN>
__global__ __launch_bounds__(256) void k_conv_tc(
    const float* __restrict__ in, const uint32_t* __restrict__ wT,
    const float* __restrict__ bias, float* __restrict__ out)
{
    constexpr int HX = 16 + K - 1, HY = 8 + K - 1, HPX = HX * HY;
    constexpr int NT = SPAN / 16;
    constexpr int SPANP = SPAN + 4;
    extern __shared__ uint32_t sm[];
    uint32_t* As = sm;                 // [HPX][36] bf16x2 words (c-pairs)
    uint32_t* Bs = sm + HPX * 36;      // [32 kpair][SPANP] bf16x2 words
    int tid = threadIdx.x, lane = tid & 31, w = tid >> 5;
    int q = lane >> 2, r = lane & 3;
    int pxg = w >> 1, ocg = w & 1;
    int b = blockIdx.z;
    int ty0 = blockIdx.y * 8, tx0 = blockIdx.x * 16;
    float acc[2][NT][4] = {};

    // halo fill (once), float4 granularity
    for (int idx = tid; idx < HPX * 16; idx += 256) {
        int hp = idx >> 4, c4 = idx & 15;
        int hy = hp / HX, hx = hp % HX;
        int yy = ty0 + hy - PAD, xx = tx0 + hx - PAD;
        float4 val = make_float4(0.f, 0.f, 0.f, 0.f);
        if (yy >= 0 && yy < HH && xx >= 0 && xx < WWID)
            val = *(const float4*)(in + ((size_t)((b * HH + yy) * WWID + xx)) * 64 + 4 * c4);
        uint2 pk;
        pk.x = packbf2(val.x, val.y);
        pk.y = packbf2(val.z, val.w);
        *(uint2*)(As + hp * 36 + 2 * c4) = pk;
    }

    for (int tap = 0; tap < K * K; tap++) {
        int ki = tap / K, kj = tap % K;
        __syncthreads();
        for (int idx = tid; idx < 8 * SPAN; idx += 256) {
            int kp = idx / (SPAN / 4), oc4 = idx % (SPAN / 4);
            *(uint4*)(Bs + kp * SPANP + 4 * oc4) =
                ((const uint4*)(wT + ((size_t)tap * 32 + kp) * KOUTP))[oc4];
        }
        __syncthreads();
        #pragma unroll
        for (int kc = 0; kc < 4; kc++) {
            uint32_t a[2][4];
            #pragma unroll
            for (int m = 0; m < 2; m++) {
                int hbase = (pxg * 2 + m + ki) * HX + kj;
                const uint32_t* Ap = As + (hbase + q) * 36 + kc * 8 + r;
                a[m][0] = Ap[0];
                a[m][1] = Ap[8 * 36];
                a[m][2] = Ap[4];
                a[m][3] = Ap[8 * 36 + 4];
            }
            #pragma unroll
            for (int nt = 0; nt < NT; nt++) {
                uint32_t bb[2];
                int ocb = ocg * (SPAN / 2) + nt * 8 + q;
                bb[0] = Bs[(kc * 8 + r)     * SPANP + ocb];
                bb[1] = Bs[(kc * 8 + r + 4) * SPANP + ocb];
                mma_bf16(acc[0][nt], a[0], bb);
                mma_bf16(acc[1][nt], a[1], bb);
            }
        }
    }
    // store PLANAR [oc][pixel] with bias
    #pragma unroll
    for (int m = 0; m < 2; m++) {
        #pragma unroll
        for (int nt = 0; nt < NT; nt++) {
            #pragma unroll
            for (int hh = 0; hh < 2; hh++) {
                int p  = pxg * 32 + m * 16 + q + hh * 8;
                int pg = (b * HH + ty0 + (p >> 4)) * WWID + tx0 + (p & 15);
                int oc = ocg * (SPAN / 2) + nt * 8 + 2 * r;
                float v0 = acc[m][nt][hh * 2 + 0];
                float v1 = acc[m][nt][hh * 2 + 1];
                if (oc     < KOUT) out[(size_t)oc       * BHW + pg] = v0 + bias[oc];
                if (oc + 1 < KOUT) out[(size_t)(oc + 1) * BHW + pg] = v1 + bias[oc + 1];
            }
        }
    }
}

// ---------------- deformable KxK conv (Cout=64), bf16 MMA -------------------
template<int K, int PAD>
__global__ __launch_bounds__(256) void k_deform_tc(
    const float* __restrict__ in, const float* __restrict__ off,
    const uint32_t* __restrict__ wT, const float* __restrict__ bias,
    float* __restrict__ out)
{
    extern __shared__ uint32_t sm[];
    uint32_t* As = sm;                       // [128][36] bf16x2
    uint32_t* Bs = sm + 128 * 36;            // [32][68] bf16x2
    float* w00 = (float*)(Bs + 32 * 68);     // 4 x 128 bilinear weights
    float* w01 = w00 + 128;
    float* w10 = w01 + 128;
    float* w11 = w10 + 128;
    int*   s_y0 = (int*)(w11 + 128);
    int*   s_x0 = s_y0 + 128;

    int tid = threadIdx.x, lane = tid & 31, w = tid >> 5;
    int q = lane >> 2, r = lane & 3;
    int pxg = w >> 1, ocg = w & 1;
    int b = blockIdx.z;
    int ty0 = blockIdx.y * 8, tx0 = blockIdx.x * 16;
    const float* base = in + (size_t)b * HW * 64;
    float acc[2][4][4] = {};

    for (int tap = 0; tap < K * K; tap++) {
        int ki = tap / K, kj = tap % K;
        __syncthreads();
        for (int idx = tid; idx < 512; idx += 256) {
            int kp = idx >> 4, oc4 = idx & 15;
            *(uint4*)(Bs + kp * 68 + 4 * oc4) =
                ((const uint4*)(wT + ((size_t)tap * 32 + kp) * 64))[oc4];
        }
        if (tid < 128) {
            int p  = tid;
            int yy = ty0 + (p >> 4), xx = tx0 + (p & 15);
            int pg = (b * HH + yy) * WWID + xx;
            float oy = off[(size_t)(2 * tap)     * BHW + pg];
            float ox = off[(size_t)(2 * tap + 1) * BHW + pg];
            float py = (float)(yy + ki - PAD) + oy;
            float px = (float)(xx + kj - PAD) + ox;
            float fy = floorf(py), fx = floorf(px);
            float wy = py - fy,    wx = px - fx;
            s_y0[p] = (int)fy; s_x0[p] = (int)fx;
            w00[p] = (1.f - wy) * (1.f - wx);
            w01[p] = (1.f - wy) * wx;
            w10[p] = wy * (1.f - wx);
            w11[p] = wy * wx;
        }
        __syncthreads();
        // bilinear sampling, float4 granularity (16 lanes span 64 channels)
        #pragma unroll 4
        for (int it = 0; it < 8; it++) {
            int v  = it * 256 + tid;
            int p  = v >> 4, c4 = v & 15;
            int y0 = s_y0[p], x0 = s_x0[p];
            float a00 = w00[p], a01 = w01[p], a10 = w10[p], a11 = w11[p];
            bool yv0 = (unsigned)y0       < HH;
            bool yv1 = (unsigned)(y0 + 1) < HH;
            bool xv0 = (unsigned)x0       < WWID;
            bool xv1 = (unsigned)(x0 + 1) < WWID;
            long long r0 = ((long long)y0 * WWID + x0) * 64 + 4 * c4;
            float4 z = make_float4(0.f, 0.f, 0.f, 0.f);
            float4 v00 = z, v01 = z, v10 = z, v11 = z;
            if (yv0 && xv0) v00 = *(const float4*)(base + r0);
            if (yv0 && xv1) v01 = *(const float4*)(base + r0 + 64);
            if (yv1 && xv0) v10 = *(const float4*)(base + r0 + 64 * WWID);
            if (yv1 && xv1) v11 = *(const float4*)(base + r0 + 64 * WWID + 64);
            float rx = a00 * v00.x + a01 * v01.x + a10 * v10.x + a11 * v11.x;
            float ry = a00 * v00.y + a01 * v01.y + a10 * v10.y + a11 * v11.y;
            float rz = a00 * v00.z + a01 * v01.z + a10 * v10.z + a11 * v11.z;
            float rw = a00 * v00.w + a01 * v01.w + a10 * v10.w + a11 * v11.w;
            uint2 pk;
            pk.x = packbf2(rx, ry);
            pk.y = packbf2(rz, rw);
            *(uint2*)(As + p * 36 + 2 * c4) = pk;
        }
        __syncthreads();
        #pragma unroll
        for (int kc = 0; kc < 4; kc++) {
            uint32_t a[2][4];
            #pragma unroll
            for (int m = 0; m < 2; m++) {
                int pr = pxg * 32 + m * 16;
                const uint32_t* Ap = As + (pr + q) * 36 + kc * 8 + r;
                a[m][0] = Ap[0];
                a[m][1] = Ap[8 * 36];
                a[m][2] = Ap[4];
                a[m][3] = Ap[8 * 36 + 4];
            }
            #pragma unroll
            for (int nt = 0; nt < 4; nt++) {
                uint32_t bb[2];
                int ocb = ocg * 32 + nt * 8 + q;
                bb[0] = Bs[(kc * 8 + r)     * 68 + ocb];
                bb[1] = Bs[(kc * 8 + r + 4) * 68 + ocb];
                mma_bf16(acc[0][nt], a[0], bb);
                mma_bf16(acc[1][nt], a[1], bb);
            }
        }
    }
    #pragma unroll
    for (int m = 0; m < 2; m++) {
        #pragma unroll
        for (int nt = 0; nt < 4; nt++) {
            #pragma unroll
            for (int hh = 0; hh < 2; hh++) {
                int p  = pxg * 32 + m * 16 + q + hh * 8;
                int pg = (b * HH + ty0 + (p >> 4)) * WWID + tx0 + (p & 15);
                int oc = ocg * 32 + nt * 8 + 2 * r;
                float2 v;
                v.x = acc[m][nt][hh * 2 + 0] + bias[oc];
                v.y = acc[m][nt][hh * 2 + 1] + bias[oc + 1];
                *(float2*)(out + (size_t)pg * 64 + oc) = v;
            }
        }
    }
}

// ---------------- final: (x1+x2) @ w_out^T + b_out + residual, bf16 MMA ----
__global__ __launch_bounds__(256) void k_final_tc(
    const float* __restrict__ x1, const float* __restrict__ x2,
    const float* __restrict__ xin, const uint32_t* __restrict__ wC,
    const float* __restrict__ b_out, float* __restrict__ out)
{
    __shared__ uint32_t As[128 * 36];
    __shared__ uint32_t Bs[32 * 68];
    int tid = threadIdx.x, lane = tid & 31, w = tid >> 5;
    int q = lane >> 2, r = lane & 3;
    int pxg = w >> 1, ocg = w & 1;
    size_t p0 = (size_t)blockIdx.x * 128;
    for (int idx = tid; idx < 512; idx += 256) {
        int kp = idx >> 4, oc4 = idx & 15;
        *(uint4*)(Bs + kp * 68 + 4 * oc4) = ((const uint4*)wC)[idx];
    }
    for (int idx = tid; idx < 128 * 16; idx += 256) {
        int p = idx >> 4, c4 = idx & 15;
        float4 a = *(const float4*)(x1 + (p0 + p) * 64 + 4 * c4);
        float4 bb = *(const float4*)(x2 + (p0 + p) * 64 + 4 * c4);
        uint2 pk;
        pk.x = packbf2(a.x + bb.x, a.y + bb.y);
        pk.y = packbf2(a.z + bb.z, a.w + bb.w);
        *(uint2*)(As + p * 36 + 2 * c4) = pk;
    }
    __syncthreads();
    float acc[2][4][4] = {};
    #pragma unroll
    for (int kc = 0; kc < 4; kc++) {
        uint32_t a[2][4];
        #pragma unroll
        for (int m = 0; m < 2; m++) {
            int pr = pxg * 32 + m * 16;
            const uint32_t* Ap = As + (pr + q) * 36 + kc * 8 + r;
            a[m][0] = Ap[0];
            a[m][1] = Ap[8 * 36];
            a[m][2] = Ap[4];
            a[m][3] = Ap[8 * 36 + 4];
        }
        #pragma unroll
        for (int nt = 0; nt < 4; nt++) {
            uint32_t bb[2];
            int ocb = ocg * 32 + nt * 8 + q;
            bb[0] = Bs[(kc * 8 + r)     * 68 + ocb];
            bb[1] = Bs[(kc * 8 + r + 4) * 68 + ocb];
            mma_bf16(acc[0][nt], a[0], bb);
            mma_bf16(acc[1][nt], a[1], bb);
        }
    }
    int b = (int)(p0 / HW);
    int hwbase = (int)(p0 % HW);
    #pragma unroll
    for (int m = 0; m < 2; m++) {
        #pragma unroll
        for (int nt = 0; nt < 4; nt++) {
            #pragma unroll
            for (int hh = 0; hh < 2; hh++) {
                int p  = pxg * 32 + m * 16 + q + hh * 8;
                int hw = hwbase + p;
                int oc = ocg * 32 + nt * 8 + 2 * r;
                size_t a0 = ((size_t)b * 64 + oc) * HW + hw;
                size_t a1 = a0 + HW;
                out[a0] = acc[m][nt][hh * 2 + 0] + b_out[oc]     + xin[a0];
                out[a1] = acc[m][nt][hh * 2 + 1] + b_out[oc + 1] + xin[a1];
            }
        }
    }
}

// ---------------- launch --------------------------------------------------
extern "C" void kernel_launch(void* const* d_in, const int* in_sizes, int n_in,
                              void* d_out, int out_size) {
    const float* x    = (const float*)d_in[0];
    const float* ln_w = (const float*)d_in[1];
    const float* ln_b = (const float*)d_in[2];
    const float* w_in = (const float*)d_in[3];
    const float* b_in = (const float*)d_in[4];
    const float* w_out= (const float*)d_in[5];
    const float* b_out= (const float*)d_in[6];
    const float* dw1  = (const float*)d_in[7];
    const float* db1  = (const float*)d_in[8];
    const float* dw2  = (const float*)d_in[9];
    const float* db2  = (const float*)d_in[10];
    const float* dw3  = (const float*)d_in[11];
    const float* db3  = (const float*)d_in[12];
    const float* ow1  = (const float*)d_in[13];
    const float* ob1  = (const float*)d_in[14];
    const float* ow2  = (const float*)d_in[15];
    const float* ob2  = (const float*)d_in[16];
    const float* ow3  = (const float*)d_in[17];
    const float* ob3  = (const float*)d_in[18];
    float* out = (float*)d_out;

    float *px1, *px2, *py, *poff;
    uint32_t *pwA, *pwB, *pwC, *pwIn;
    cudaGetSymbolAddress((void**)&px1,  g_x1);
    cudaGetSymbolAddress((void**)&px2,  g_x2);
    cudaGetSymbolAddress((void**)&py,   g_y);
    cudaGetSymbolAddress((void**)&poff, g_off);
    cudaGetSymbolAddress((void**)&pwA,  g_wA);
    cudaGetSymbolAddress((void**)&pwB,  g_wB);
    cudaGetSymbolAddress((void**)&pwC,  g_wC);
    cudaGetSymbolAddress((void**)&pwIn, g_wIn);

    const int SMC1 = (20 * 12 * 36 + 32 * 132) * 4;
    const int SMC2 = (20 * 12 * 36 + 32 * 68)  * 4;
    const int SMC3 = (18 * 10 * 36 + 32 * 36)  * 4;
    const int SMD  = (128 * 36 + 32 * 68) * 4 + 128 * 6 * 4;

    cudaFuncSetAttribute(k_conv_tc<5,2,98,128,128>, cudaFuncAttributeMaxDynamicSharedMemorySize, SMC1);
    cudaFuncSetAttribute(k_conv_tc<5,2,50,64,64>,   cudaFuncAttributeMaxDynamicSharedMemorySize, SMC2);
    cudaFuncSetAttribute(k_conv_tc<3,1,18,32,32>,   cudaFuncAttributeMaxDynamicSharedMemorySize, SMC3);
    cudaFuncSetAttribute(k_deform_tc<7,3>, cudaFuncAttributeMaxDynamicSharedMemorySize, SMD);
    cudaFuncSetAttribute(k_deform_tc<5,2>, cudaFuncAttributeMaxDynamicSharedMemorySize, SMD);
    cudaFuncSetAttribute(k_deform_tc<3,1>, cudaFuncAttributeMaxDynamicSharedMemorySize, SMD);

    dim3 tiles(WWID / 16, HH / 8, BATCH);   // 16x8 px tiles

    // fused LN + w_in projection (bf16 MMA)
    k_transpose_bf<<<32, 256>>>(w_in, pwIn, 1, 128, 128);
    k_ln_win_tc<<<BHW / 128, 256>>>(x, ln_w, ln_b, pwIn, b_in, px1, px2);

    // stage 1: offset conv 5x5 -> 98, deform 7x7
    k_transpose_bf<<<256, 256>>>(ow1, pwA, 25, 98, 128);
    k_conv_tc<5,2,98,128,128><<<tiles, 256, SMC1>>>(px1, pwA, ob1, poff);
    k_transpose_bf<<<256, 256>>>(dw1, pwB, 49, 64, 64);
    k_deform_tc<7,3><<<tiles, 256, SMD>>>(px1, poff, pwB, db1, py);

    // stage 2: offset conv 5x5 -> 50, deform 5x5
    k_transpose_bf<<<256, 256>>>(ow2, pwA, 25, 50, 64);
    k_conv_tc<5,2,50,64,64><<<tiles, 256, SMC2>>>(py, pwA, ob2, poff);
    k_transpose_bf<<<256, 256>>>(dw2, pwB, 25, 64, 64);
    k_deform_tc<5,2><<<tiles, 256, SMD>>>(py, poff, pwB, db2, px1);

    // stage 3: offset conv 3x3 -> 18, deform 3x3
    k_transpose_bf<<<256, 256>>>(ow3, pwA, 9, 18, 32);
    k_conv_tc<3,1,18,32,32><<<tiles, 256, SMC3>>>(px1, pwA, ob3, poff);
    k_transpose_bf<<<256, 256>>>(dw3, pwB, 9, 64, 64);
    k_deform_tc<3,1><<<tiles, 256, SMD>>>(px1, poff, pwB, db3, py);

    k_transpose_bf<<<8, 256>>>(w_out, pwC, 1, 64, 64);
    k_final_tc<<<BHW / 128, 256>>>(py, px2, x, pwC, b_out, out);
}

// round 8
// speedup vs baseline: 2.1049x; 1.0070x over previous
#include <cuda_runtime.h>
#include <cuda_bf16.h>
#include <math.h>
#include <stdint.h>

#define BATCH 4
#define CH    64
#define HH    192
#define WWID  192
#define HW    (HH*WWID)
#define BHW   (BATCH*HW)

// ---------------- device scratch (allocation-free) ----------------
__device__ uint32_t g_x1 [BHW*32];      // bf16x2 NHWC (32 words/px)
__device__ uint32_t g_x2 [BHW*32];      // bf16x2 NHWC
__device__ uint32_t g_y  [BHW*32];      // bf16x2 NHWC ping-pong
__device__ float    g_off[98*BHW];      // PLANAR offsets [ch][pixel], fp32
__device__ uint32_t g_wA [25*32*128];   // packed offset-conv weights [tap][kpair][ocPad]
__device__ uint32_t g_wB [49*32*64];    // packed deform weights      [tap][kpair][oc]
__device__ uint32_t g_wC [32*64];       // packed w_out               [kpair][oc]
__device__ uint32_t g_wIn[32*128];      // packed w_in                [kpair][oc]

// ---------------- bf16 helpers --------------------------------------------
static __device__ __forceinline__ uint32_t packbf2(float lo, float hi) {
    uint32_t r;
    asm("cvt.rn.bf16x2.f32 %0, %1, %2;" : "=r"(r) : "f"(hi), "f"(lo));
    return r;
}
static __device__ __forceinline__ float2 unpbf2(uint32_t u) {
    return __bfloat1622float2(*(__nv_bfloat162*)&u);
}
static __device__ __forceinline__ void mma_bf16(float* d, const uint32_t* a,
                                                const uint32_t* b) {
    asm volatile(
        "mma.sync.aligned.m16n8k16.row.col.f32.bf16.bf16.f32 "
        "{%0,%1,%2,%3},{%4,%5,%6,%7},{%8,%9},{%0,%1,%2,%3};"
        : "+f"(d[0]), "+f"(d[1]), "+f"(d[2]), "+f"(d[3])
        : "r"(a[0]), "r"(a[1]), "r"(a[2]), "r"(a[3]), "r"(b[0]), "r"(b[1]));
}

// ---------------- weight transpose+pack: w[O][C][K2] -> out[tap][kp][ocPad] -
__global__ void k_transpose_bf(const float* __restrict__ w, uint32_t* __restrict__ out,
                               int K2, int KOUT, int KOUTP) {
    int n = K2 * 32 * KOUTP;
    for (int idx = blockIdx.x * blockDim.x + threadIdx.x; idx < n;
         idx += gridDim.x * blockDim.x) {
        int oc  = idx % KOUTP;
        int kp  = (idx / KOUTP) % 32;
        int tap = idx / (KOUTP * 32);
        float lo = 0.f, hi = 0.f;
        if (oc < KOUT) {
            lo = w[(oc * 64 + 2 * kp)     * K2 + tap];
            hi = w[(oc * 64 + 2 * kp + 1) * K2 + tap];
        }
        out[idx] = packbf2(lo, hi);
    }
}

// ---------------- fused LayerNorm + 1x1 conv (64->128), bf16 MMA ------------
__global__ __launch_bounds__(256) void k_ln_win_tc(
    const float* __restrict__ x, const float* __restrict__ ln_w,
    const float* __restrict__ ln_b, const uint32_t* __restrict__ wIn,
    const float* __restrict__ b_in, uint32_t* __restrict__ out1,
    uint32_t* __restrict__ out2)
{
    __shared__ uint32_t As[128 * 36];
    __shared__ uint32_t Bs[32 * 132];
    __shared__ float s_sum[2][128], s_sq[2][128];
    __shared__ float s_lw[64], s_lb[64], s_bin[128];
    int tid = threadIdx.x, lane = tid & 31, w = tid >> 5;
    int q = lane >> 2, r = lane & 3;
    int pxg = w >> 1, ocg = w & 1;
    size_t p0 = (size_t)blockIdx.x * 128;
    int b = (int)(p0 / HW);
    int hw0 = (int)(p0 % HW);
    const float* xb = x + (size_t)b * 64 * HW + hw0;

    for (int idx = tid; idx < 1024; idx += 256)
        *(uint4*)(Bs + (idx >> 5) * 132 + 4 * (idx & 31)) =
            ((const uint4*)wIn)[idx];
    if (tid < 64) { s_lw[tid] = ln_w[tid]; s_lb[tid] = ln_b[tid]; }
    if (tid < 128) s_bin[tid] = b_in[tid];

    int px = tid & 127, hi2 = tid >> 7;
    float v[32], s = 0.f, sq = 0.f;
    #pragma unroll
    for (int it = 0; it < 32; it++) {
        int c = 2 * it + hi2;
        float val = xb[(size_t)c * HW + px];
        v[it] = val; s += val; sq += val * val;
    }
    s_sum[hi2][px] = s; s_sq[hi2][px] = sq;
    __syncthreads();
    float S = s_sum[0][px] + s_sum[1][px];
    float Q = s_sq[0][px]  + s_sq[1][px];
    float mu = S * (1.f / 64.f);
    float var = Q * (1.f / 64.f) - mu * mu;
    float rs = rsqrtf(var + 1e-5f);
    __nv_bfloat16* Ah = (__nv_bfloat16*)As;
    #pragma unroll
    for (int it = 0; it < 32; it++) {
        int c = 2 * it + hi2;
        float nv = (v[it] - mu) * rs * s_lw[c] + s_lb[c];
        Ah[px * 72 + c] = __float2bfloat16(nv);
    }
    __syncthreads();

    float acc[2][8][4] = {};
    #pragma unroll
    for (int kc = 0; kc < 4; kc++) {
        uint32_t a[2][4];
        #pragma unroll
        for (int m = 0; m < 2; m++) {
            int pr = pxg * 32 + m * 16;
            const uint32_t* Ap = As + (pr + q) * 36 + kc * 8 + r;
            a[m][0] = Ap[0];
            a[m][1] = Ap[8 * 36];
            a[m][2] = Ap[4];
            a[m][3] = Ap[8 * 36 + 4];
        }
        #pragma unroll
        for (int nt = 0; nt < 8; nt++) {
            uint32_t bb[2];
            int ocb = ocg * 64 + nt * 8 + q;
            bb[0] = Bs[(kc * 8 + r)     * 132 + ocb];
            bb[1] = Bs[(kc * 8 + r + 4) * 132 + ocb];
            mma_bf16(acc[0][nt], a[0], bb);
            mma_bf16(acc[1][nt], a[1], bb);
        }
    }
    uint32_t* outw = ocg ? out2 : out1;
    #pragma unroll
    for (int m = 0; m < 2; m++) {
        #pragma unroll
        for (int nt = 0; nt < 8; nt++) {
            #pragma unroll
            for (int hh = 0; hh < 2; hh++) {
                int p = pxg * 32 + m * 16 + q + hh * 8;
                int ocl = nt * 8 + 2 * r;
                int ocG = ocg * 64 + ocl;
                float vx = acc[m][nt][hh * 2 + 0] + s_bin[ocG];
                float vy = acc[m][nt][hh * 2 + 1] + s_bin[ocG + 1];
                outw[(p0 + p) * 32 + (ocl >> 1)] = packbf2(vx, vy);
            }
        }
    }
}

// ---------------- dense KxK conv, bf16 MMA, HALO-tiled ----------------------
template<int K, int PAD, int KOUT, int KOUTP, int SPAN>
__global__ __launch_bounds__(256) void k_conv_tc(
    const uint32_t* __restrict__ in, const uint32_t* __restrict__ wT,
    const float* __restrict__ bias, float* __restrict__ out)
{
    constexpr int HX = 16 + K - 1, HY = 8 + K - 1, HPX = HX * HY;
    constexpr int NT = SPAN / 16;
    constexpr int SPANP = SPAN + 4;
    extern __shared__ uint32_t sm[];
    uint32_t* As = sm;                 // [HPX][36] bf16x2 words
    uint32_t* Bs = sm + HPX * 36;      // [32 kpair][SPANP]
    int tid = threadIdx.x, lane = tid & 31, w = tid >> 5;
    int q = lane >> 2, r = lane & 3;
    int pxg = w >> 1, ocg = w & 1;
    int b = blockIdx.z;
    int ty0 = blockIdx.y * 8, tx0 = blockIdx.x * 16;
    float acc[2][NT][4] = {};

    // halo fill (once), uint4 = 8 channels, already bf16x2
    for (int idx = tid; idx < HPX * 8; idx += 256) {
        int hp = idx >> 3, c8 = idx & 7;
        int hy = hp / HX, hx = hp % HX;
        int yy = ty0 + hy - PAD, xx = tx0 + hx - PAD;
        uint4 val = make_uint4(0u, 0u, 0u, 0u);
        if (yy >= 0 && yy < HH && xx >= 0 && xx < WWID)
            val = *(const uint4*)(in + ((size_t)((b * HH + yy) * WWID + xx)) * 32 + 4 * c8);
        *(uint4*)(As + hp * 36 + 4 * c8) = val;
    }

    for (int tap = 0; tap < K * K; tap++) {
        int ki = tap / K, kj = tap % K;
        __syncthreads();
        for (int idx = tid; idx < 8 * SPAN; idx += 256) {
            int kp = idx / (SPAN / 4), oc4 = idx % (SPAN / 4);
            *(uint4*)(Bs + kp * SPANP + 4 * oc4) =
                ((const uint4*)(wT + ((size_t)tap * 32 + kp) * KOUTP))[oc4];
        }
        __syncthreads();
        #pragma unroll
        for (int kc = 0; kc < 4; kc++) {
            uint32_t a[2][4];
            #pragma unroll
            for (int m = 0; m < 2; m++) {
                int hbase = (pxg * 2 + m + ki) * HX + kj;
                const uint32_t* Ap = As + (hbase + q) * 36 + kc * 8 + r;
                a[m][0] = Ap[0];
                a[m][1] = Ap[8 * 36];
                a[m][2] = Ap[4];
                a[m][3] = Ap[8 * 36 + 4];
            }
            #pragma unroll
            for (int nt = 0; nt < NT; nt++) {
                uint32_t bb[2];
                int ocb = ocg * (SPAN / 2) + nt * 8 + q;
                bb[0] = Bs[(kc * 8 + r)     * SPANP + ocb];
                bb[1] = Bs[(kc * 8 + r + 4) * SPANP + ocb];
                mma_bf16(acc[0][nt], a[0], bb);
                mma_bf16(acc[1][nt], a[1], bb);
            }
        }
    }
    // store PLANAR [oc][pixel] fp32 with bias
    #pragma unroll
    for (int m = 0; m < 2; m++) {
        #pragma unroll
        for (int nt = 0; nt < NT; nt++) {
            #pragma unroll
            for (int hh = 0; hh < 2; hh++) {
                int p  = pxg * 32 + m * 16 + q + hh * 8;
                int pg = (b * HH + ty0 + (p >> 4)) * WWID + tx0 + (p & 15);
                int oc = ocg * (SPAN / 2) + nt * 8 + 2 * r;
                float v0 = acc[m][nt][hh * 2 + 0];
                float v1 = acc[m][nt][hh * 2 + 1];
                if (oc     < KOUT) out[(size_t)oc       * BHW + pg] = v0 + bias[oc];
                if (oc + 1 < KOUT) out[(size_t)(oc + 1) * BHW + pg] = v1 + bias[oc + 1];
            }
        }
    }
}

// ---------------- deformable KxK conv (Cout=64), bf16 MMA -------------------
template<int K, int PAD>
__global__ __launch_bounds__(256) void k_deform_tc(
    const uint32_t* __restrict__ in, const float* __restrict__ off,
    const uint32_t* __restrict__ wT, const float* __restrict__ bias,
    uint32_t* __restrict__ out)
{
    extern __shared__ uint32_t sm[];
    uint32_t* As = sm;                       // [128][36] bf16x2
    uint32_t* Bs = sm + 128 * 36;            // [32][68] bf16x2
    float* w00 = (float*)(Bs + 32 * 68);     // 4 x 128 bilinear weights
    float* w01 = w00 + 128;
    float* w10 = w01 + 128;
    float* w11 = w10 + 128;
    int*   s_y0 = (int*)(w11 + 128);
    int*   s_x0 = s_y0 + 128;

    int tid = threadIdx.x, lane = tid & 31, w = tid >> 5;
    int q = lane >> 2, r = lane & 3;
    int pxg = w >> 1, ocg = w & 1;
    int b = blockIdx.z;
    int ty0 = blockIdx.y * 8, tx0 = blockIdx.x * 16;
    const uint32_t* base = in + (size_t)b * HW * 32;
    float acc[2][4][4] = {};

    for (int tap = 0; tap < K * K; tap++) {
        int ki = tap / K, kj = tap % K;
        __syncthreads();
        for (int idx = tid; idx < 512; idx += 256) {
            int kp = idx >> 4, oc4 = idx & 15;
            *(uint4*)(Bs + kp * 68 + 4 * oc4) =
                ((const uint4*)(wT + ((size_t)tap * 32 + kp) * 64))[oc4];
        }
        if (tid < 128) {
            int p  = tid;
            int yy = ty0 + (p >> 4), xx = tx0 + (p & 15);
            int pg = (b * HH + yy) * WWID + xx;
            float oy = off[(size_t)(2 * tap)     * BHW + pg];
            float ox = off[(size_t)(2 * tap + 1) * BHW + pg];
            float py = (float)(yy + ki - PAD) + oy;
            float px = (float)(xx + kj - PAD) + ox;
            float fy = floorf(py), fx = floorf(px);
            float wy = py - fy,    wx = px - fx;
            s_y0[p] = (int)fy; s_x0[p] = (int)fx;
            w00[p] = (1.f - wy) * (1.f - wx);
            w01[p] = (1.f - wy) * wx;
            w10[p] = wy * (1.f - wx);
            w11[p] = wy * wx;
        }
        __syncthreads();
        // bilinear sampling from bf16 gmem, uint2 = 4 channels per lane
        #pragma unroll 4
        for (int it = 0; it < 8; it++) {
            int v  = it * 256 + tid;
            int p  = v >> 4, c4 = v & 15;
            int y0 = s_y0[p], x0 = s_x0[p];
            float a00 = w00[p], a01 = w01[p], a10 = w10[p], a11 = w11[p];
            bool yv0 = (unsigned)y0       < HH;
            bool yv1 = (unsigned)(y0 + 1) < HH;
            bool xv0 = (unsigned)x0       < WWID;
            bool xv1 = (unsigned)(x0 + 1) < WWID;
            long long r0 = ((long long)y0 * WWID + x0) * 32 + 2 * c4;
            uint2 z = make_uint2(0u, 0u);
            uint2 u00 = z, u01 = z, u10 = z, u11 = z;
            if (yv0 && xv0) u00 = *(const uint2*)(base + r0);
            if (yv0 && xv1) u01 = *(const uint2*)(base + r0 + 32);
            if (yv1 && xv0) u10 = *(const uint2*)(base + r0 + 32 * WWID);
            if (yv1 && xv1) u11 = *(const uint2*)(base + r0 + 32 * WWID + 32);
            float2 a0 = unpbf2(u00.x), a1 = unpbf2(u01.x);
            float2 a2 = unpbf2(u10.x), a3 = unpbf2(u11.x);
            float rx = a00 * a0.x + a01 * a1.x + a10 * a2.x + a11 * a3.x;
            float ry = a00 * a0.y + a01 * a1.y + a10 * a2.y + a11 * a3.y;
            float2 b0 = unpbf2(u00.y), b1 = unpbf2(u01.y);
            float2 b2 = unpbf2(u10.y), b3 = unpbf2(u11.y);
            float rz = a00 * b0.x + a01 * b1.x + a10 * b2.x + a11 * b3.x;
            float rw = a00 * b0.y + a01 * b1.y + a10 * b2.y + a11 * b3.y;
            uint2 pk;
            pk.x = packbf2(rx, ry);
            pk.y = packbf2(rz, rw);
            *(uint2*)(As + p * 36 + 2 * c4) = pk;
        }
        __syncthreads();
        #pragma unroll
        for (int kc = 0; kc < 4; kc++) {
            uint32_t a[2][4];
            #pragma unroll
            for (int m = 0; m < 2; m++) {
                int pr = pxg * 32 + m * 16;
                const uint32_t* Ap = As + (pr + q) * 36 + kc * 8 + r;
                a[m][0] = Ap[0];
                a[m][1] = Ap[8 * 36];
                a[m][2] = Ap[4];
                a[m][3] = Ap[8 * 36 + 4];
            }
            #pragma unroll
            for (int nt = 0; nt < 4; nt++) {
                uint32_t bb[2];
                int ocb = ocg * 32 + nt * 8 + q;
                bb[0] = Bs[(kc * 8 + r)     * 68 + ocb];
                bb[1] = Bs[(kc * 8 + r + 4) * 68 + ocb];
                mma_bf16(acc[0][nt], a[0], bb);
                mma_bf16(acc[1][nt], a[1], bb);
            }
        }
    }
    #pragma unroll
    for (int m = 0; m < 2; m++) {
        #pragma unroll
        for (int nt = 0; nt < 4; nt++) {
            #pragma unroll
            for (int hh = 0; hh < 2; hh++) {
                int p  = pxg * 32 + m * 16 + q + hh * 8;
                int pg = (b * HH + ty0 + (p >> 4)) * WWID + tx0 + (p & 15);
                int oc = ocg * 32 + nt * 8 + 2 * r;
                float vx = acc[m][nt][hh * 2 + 0] + bias[oc];
                float vy = acc[m][nt][hh * 2 + 1] + bias[oc + 1];
                out[(size_t)pg * 32 + (oc >> 1)] = packbf2(vx, vy);
            }
        }
    }
}

// ---------------- final: (x1+x2) @ w_out^T + b_out + residual, bf16 MMA ----
__global__ __launch_bounds__(256) void k_final_tc(
    const uint32_t* __restrict__ x1, const uint32_t* __restrict__ x2,
    const float* __restrict__ xin, const uint32_t* __restrict__ wC,
    const float* __restrict__ b_out, float* __restrict__ out)
{
    __shared__ uint32_t As[128 * 36];
    __shared__ uint32_t Bs[32 * 68];
    int tid = threadIdx.x, lane = tid & 31, w = tid >> 5;
    int q = lane >> 2, r = lane & 3;
    int pxg = w >> 1, ocg = w & 1;
    size_t p0 = (size_t)blockIdx.x * 128;
    for (int idx = tid; idx < 512; idx += 256) {
        int kp = idx >> 4, oc4 = idx & 15;
        *(uint4*)(Bs + kp * 68 + 4 * oc4) = ((const uint4*)wC)[idx];
    }
    for (int idx = tid; idx < 128 * 16; idx += 256) {
        int p = idx >> 4, c4 = idx & 15;
        uint2 a = *(const uint2*)(x1 + (p0 + p) * 32 + 2 * c4);
        uint2 bb = *(const uint2*)(x2 + (p0 + p) * 32 + 2 * c4);
        uint2 pk;
        __nv_bfloat162 sa = __hadd2(*(__nv_bfloat162*)&a.x, *(__nv_bfloat162*)&bb.x);
        __nv_bfloat162 sb = __hadd2(*(__nv_bfloat162*)&a.y, *(__nv_bfloat162*)&bb.y);
        pk.x = *(uint32_t*)&sa;
        pk.y = *(uint32_t*)&sb;
        *(uint2*)(As + p * 36 + 2 * c4) = pk;
    }
    __syncthreads();
    float acc[2][4][4] = {};
    #pragma unroll
    for (int kc = 0; kc < 4; kc++) {
        uint32_t a[2][4];
        #pragma unroll
        for (int m = 0; m < 2; m++) {
            int pr = pxg * 32 + m * 16;
            const uint32_t* Ap = As + (pr + q) * 36 + kc * 8 + r;
            a[m][0] = Ap[0];
            a[m][1] = Ap[8 * 36];
            a[m][2] = Ap[4];
            a[m][3] = Ap[8 * 36 + 4];
        }
        #pragma unroll
        for (int nt = 0; nt < 4; nt++) {
            uint32_t bb[2];
            int ocb = ocg * 32 + nt * 8 + q;
            bb[0] = Bs[(kc * 8 + r)     * 68 + ocb];
            bb[1] = Bs[(kc * 8 + r + 4) * 68 + ocb];
            mma_bf16(acc[0][nt], a[0], bb);
            mma_bf16(acc[1][nt], a[1], bb);
        }
    }
    int b = (int)(p0 / HW);
    int hwbase = (int)(p0 % HW);
    #pragma unroll
    for (int m = 0; m < 2; m++) {
        #pragma unroll
        for (int nt = 0; nt < 4; nt++) {
            #pragma unroll
            for (int hh = 0; hh < 2; hh++) {
                int p  = pxg * 32 + m * 16 + q + hh * 8;
                int hw = hwbase + p;
                int oc = ocg * 32 + nt * 8 + 2 * r;
                size_t a0 = ((size_t)b * 64 + oc) * HW + hw;
                size_t a1 = a0 + HW;
                out[a0] = acc[m][nt][hh * 2 + 0] + b_out[oc]     + xin[a0];
                out[a1] = acc[m][nt][hh * 2 + 1] + b_out[oc + 1] + xin[a1];
            }
        }
    }
}

// ---------------- launch --------------------------------------------------
extern "C" void kernel_launch(void* const* d_in, const int* in_sizes, int n_in,
                              void* d_out, int out_size) {
    const float* x    = (const float*)d_in[0];
    const float* ln_w = (const float*)d_in[1];
    const float* ln_b = (const float*)d_in[2];
    const float* w_in = (const float*)d_in[3];
    const float* b_in = (const float*)d_in[4];
    const float* w_out= (const float*)d_in[5];
    const float* b_out= (const float*)d_in[6];
    const float* dw1  = (const float*)d_in[7];
    const float* db1  = (const float*)d_in[8];
    const float* dw2  = (const float*)d_in[9];
    const float* db2  = (const float*)d_in[10];
    const float* dw3  = (const float*)d_in[11];
    const float* db3  = (const float*)d_in[12];
    const float* ow1  = (const float*)d_in[13];
    const float* ob1  = (const float*)d_in[14];
    const float* ow2  = (const float*)d_in[15];
    const float* ob2  = (const float*)d_in[16];
    const float* ow3  = (const float*)d_in[17];
    const float* ob3  = (const float*)d_in[18];
    float* out = (float*)d_out;

    float *poff;
    uint32_t *px1, *px2, *py, *pwA, *pwB, *pwC, *pwIn;
    cudaGetSymbolAddress((void**)&px1,  g_x1);
    cudaGetSymbolAddress((void**)&px2,  g_x2);
    cudaGetSymbolAddress((void**)&py,   g_y);
    cudaGetSymbolAddress((void**)&poff, g_off);
    cudaGetSymbolAddress((void**)&pwA,  g_wA);
    cudaGetSymbolAddress((void**)&pwB,  g_wB);
    cudaGetSymbolAddress((void**)&pwC,  g_wC);
    cudaGetSymbolAddress((void**)&pwIn, g_wIn);

    const int SMC1 = (20 * 12 * 36 + 32 * 132) * 4;
    const int SMC2 = (20 * 12 * 36 + 32 * 68)  * 4;
    const int SMC3 = (18 * 10 * 36 + 32 * 36)  * 4;
    const int SMD  = (128 * 36 + 32 * 68) * 4 + 128 * 6 * 4;

    cudaFuncSetAttribute(k_conv_tc<5,2,98,128,128>, cudaFuncAttributeMaxDynamicSharedMemorySize, SMC1);
    cudaFuncSetAttribute(k_conv_tc<5,2,50,64,64>,   cudaFuncAttributeMaxDynamicSharedMemorySize, SMC2);
    cudaFuncSetAttribute(k_conv_tc<3,1,18,32,32>,   cudaFuncAttributeMaxDynamicSharedMemorySize, SMC3);
    cudaFuncSetAttribute(k_deform_tc<7,3>, cudaFuncAttributeMaxDynamicSharedMemorySize, SMD);
    cudaFuncSetAttribute(k_deform_tc<5,2>, cudaFuncAttributeMaxDynamicSharedMemorySize, SMD);
    cudaFuncSetAttribute(k_deform_tc<3,1>, cudaFuncAttributeMaxDynamicSharedMemorySize, SMD);

    dim3 tiles(WWID / 16, HH / 8, BATCH);   // 16x8 px tiles

    // fused LN + w_in projection (bf16 MMA), outputs packed bf16 NHWC
    k_transpose_bf<<<32, 256>>>(w_in, pwIn, 1, 128, 128);
    k_ln_win_tc<<<BHW / 128, 256>>>(x, ln_w, ln_b, pwIn, b_in, px1, px2);

    // stage 1: offset conv 5x5 -> 98, deform 7x7
    k_transpose_bf<<<256, 256>>>(ow1, pwA, 25, 98, 128);
    k_conv_tc<5,2,98,128,128><<<tiles, 256, SMC1>>>(px1, pwA, ob1, poff);
    k_transpose_bf<<<256, 256>>>(dw1, pwB, 49, 64, 64);
    k_deform_tc<7,3><<<tiles, 256, SMD>>>(px1, poff, pwB, db1, py);

    // stage 2: offset conv 5x5 -> 50, deform 5x5
    k_transpose_bf<<<256, 256>>>(ow2, pwA, 25, 50, 64);
    k_conv_tc<5,2,50,64,64><<<tiles, 256, SMC2>>>(py, pwA, ob2, poff);
    k_transpose_bf<<<256, 256>>>(dw2, pwB, 25, 64, 64);
    k_deform_tc<5,2><<<tiles, 256, SMD>>>(py, poff, pwB, db2, px1);

    // stage 3: offset conv 3x3 -> 18, deform 3x3
    k_transpose_bf<<<256, 256>>>(ow3, pwA, 9, 18, 32);
    k_conv_tc<3,1,18,32,32><<<tiles, 256, SMC3>>>(px1, pwA, ob3, poff);
    k_transpose_bf<<<256, 256>>>(dw3, pwB, 9, 64, 64);
    k_deform_tc<3,1><<<tiles, 256, SMD>>>(px1, poff, pwB, db3, py);

    k_transpose_bf<<<8, 256>>>(w_out, pwC, 1, 64, 64);
    k_final_tc<<<BHW / 128, 256>>>(py, px2, x, pwC, b_out, out);
}

// round 10
// speedup vs baseline: 2.1121x; 1.0034x over previous
#include <cuda_runtime.h>
#include <cuda_bf16.h>
#include <math.h>
#include <stdint.h>

#define BATCH 4
#define CH    64
#define HH    192
#define WWID  192
#define HW    (HH*WWID)
#define BHW   (BATCH*HW)

// ---------------- device scratch (allocation-free) ----------------
__device__ uint32_t g_x1 [BHW*32];      // bf16x2 NHWC (32 words/px)
__device__ uint32_t g_x2 [BHW*32];      // bf16x2 NHWC
__device__ uint32_t g_y  [BHW*32];      // bf16x2 NHWC ping-pong
__device__ float    g_off[98*BHW];      // PLANAR offsets [ch][pixel], fp32
__device__ uint32_t g_wA [25*32*128];   // packed offset-conv weights [tap][kpair][ocPad]
__device__ uint32_t g_wB [49*32*64];    // packed deform weights      [tap][kpair][oc]
__device__ uint32_t g_wC [32*64];       // packed w_out               [kpair][oc]
__device__ uint32_t g_wIn[32*128];      // packed w_in                [kpair][oc]

// ---------------- helpers ---------------------------------------------------
static __device__ __forceinline__ uint32_t packbf2(float lo, float hi) {
    uint32_t r;
    asm("cvt.rn.bf16x2.f32 %0, %1, %2;" : "=r"(r) : "f"(hi), "f"(lo));
    return r;
}
static __device__ __forceinline__ float2 unpbf2(uint32_t u) {
    return __bfloat1622float2(*(__nv_bfloat162*)&u);
}
static __device__ __forceinline__ void mma_bf16(float* d, const uint32_t* a,
                                                const uint32_t* b) {
    asm volatile(
        "mma.sync.aligned.m16n8k16.row.col.f32.bf16.bf16.f32 "
        "{%0,%1,%2,%3},{%4,%5,%6,%7},{%8,%9},{%0,%1,%2,%3};"
        : "+f"(d[0]), "+f"(d[1]), "+f"(d[2]), "+f"(d[3])
        : "r"(a[0]), "r"(a[1]), "r"(a[2]), "r"(a[3]), "r"(b[0]), "r"(b[1]));
}
static __device__ __forceinline__ uint32_t smem_u32(const void* p) {
    uint32_t a;
    asm("{ .reg .u64 t; cvta.to.shared.u64 t, %1; cvt.u32.u64 %0, t; }"
        : "=r"(a) : "l"(p));
    return a;
}
static __device__ __forceinline__ void cpa16(uint32_t dst, const void* src) {
    asm volatile("cp.async.ca.shared.global [%0], [%1], 16;"
                 :: "r"(dst), "l"(src) : "memory");
}
static __device__ __forceinline__ void cpa_commit() {
    asm volatile("cp.async.commit_group;" ::: "memory");
}
static __device__ __forceinline__ void cpa_wait0() {
    asm volatile("cp.async.wait_group 0;" ::: "memory");
}

// ---------------- weight transpose+pack: w[O][C][K2] -> out[tap][kp][ocPad] -
__global__ void k_transpose_bf(const float* __restrict__ w, uint32_t* __restrict__ out,
                               int K2, int KOUT, int KOUTP) {
    int n = K2 * 32 * KOUTP;
    for (int idx = blockIdx.x * blockDim.x + threadIdx.x; idx < n;
         idx += gridDim.x * blockDim.x) {
        int oc  = idx % KOUTP;
        int kp  = (idx / KOUTP) % 32;
        int tap = idx / (KOUTP * 32);
        float lo = 0.f, hi = 0.f;
        if (oc < KOUT) {
            lo = w[(oc * 64 + 2 * kp)     * K2 + tap];
            hi = w[(oc * 64 + 2 * kp + 1) * K2 + tap];
        }
        out[idx] = packbf2(lo, hi);
    }
}

// ---------------- fused LayerNorm + 1x1 conv (64->128), bf16 MMA ------------
__global__ __launch_bounds__(256) void k_ln_win_tc(
    const float* __restrict__ x, const float* __restrict__ ln_w,
    const float* __restrict__ ln_b, const uint32_t* __restrict__ wIn,
    const float* __restrict__ b_in, uint32_t* __restrict__ out1,
    uint32_t* __restrict__ out2)
{
    __shared__ uint32_t As[128 * 36];
    __shared__ uint32_t Bs[32 * 132];
    __shared__ float s_sum[2][128], s_sq[2][128];
    __shared__ float s_lw[64], s_lb[64], s_bin[128];
    int tid = threadIdx.x, lane = tid & 31, w = tid >> 5;
    int q = lane >> 2, r = lane & 3;
    int pxg = w >> 1, ocg = w & 1;
    size_t p0 = (size_t)blockIdx.x * 128;
    int b = (int)(p0 / HW);
    int hw0 = (int)(p0 % HW);
    const float* xb = x + (size_t)b * 64 * HW + hw0;

    for (int idx = tid; idx < 1024; idx += 256)
        *(uint4*)(Bs + (idx >> 5) * 132 + 4 * (idx & 31)) =
            ((const uint4*)wIn)[idx];
    if (tid < 64) { s_lw[tid] = ln_w[tid]; s_lb[tid] = ln_b[tid]; }
    if (tid < 128) s_bin[tid] = b_in[tid];

    int px = tid & 127, hi2 = tid >> 7;
    float v[32], s = 0.f, sq = 0.f;
    #pragma unroll
    for (int it = 0; it < 32; it++) {
        int c = 2 * it + hi2;
        float val = xb[(size_t)c * HW + px];
        v[it] = val; s += val; sq += val * val;
    }
    s_sum[hi2][px] = s; s_sq[hi2][px] = sq;
    __syncthreads();
    float S = s_sum[0][px] + s_sum[1][px];
    float Q = s_sq[0][px]  + s_sq[1][px];
    float mu = S * (1.f / 64.f);
    float var = Q * (1.f / 64.f) - mu * mu;
    float rs = rsqrtf(var + 1e-5f);
    __nv_bfloat16* Ah = (__nv_bfloat16*)As;
    #pragma unroll
    for (int it = 0; it < 32; it++) {
        int c = 2 * it + hi2;
        float nv = (v[it] - mu) * rs * s_lw[c] + s_lb[c];
        Ah[px * 72 + c] = __float2bfloat16(nv);
    }
    __syncthreads();

    float acc[2][8][4] = {};
    #pragma unroll
    for (int kc = 0; kc < 4; kc++) {
        uint32_t a[2][4];
        #pragma unroll
        for (int m = 0; m < 2; m++) {
            int pr = pxg * 32 + m * 16;
            const uint32_t* Ap = As + (pr + q) * 36 + kc * 8 + r;
            a[m][0] = Ap[0];
            a[m][1] = Ap[8 * 36];
            a[m][2] = Ap[4];
            a[m][3] = Ap[8 * 36 + 4];
        }
        #pragma unroll
        for (int nt = 0; nt < 8; nt++) {
            uint32_t bb[2];
            int ocb = ocg * 64 + nt * 8 + q;
            bb[0] = Bs[(kc * 8 + r)     * 132 + ocb];
            bb[1] = Bs[(kc * 8 + r + 4) * 132 + ocb];
            mma_bf16(acc[0][nt], a[0], bb);
            mma_bf16(acc[1][nt], a[1], bb);
        }
    }
    uint32_t* outw = ocg ? out2 : out1;
    #pragma unroll
    for (int m = 0; m < 2; m++) {
        #pragma unroll
        for (int nt = 0; nt < 8; nt++) {
            #pragma unroll
            for (int hh = 0; hh < 2; hh++) {
                int p = pxg * 32 + m * 16 + q + hh * 8;
                int ocl = nt * 8 + 2 * r;
                int ocG = ocg * 64 + ocl;
                float vx = acc[m][nt][hh * 2 + 0] + s_bin[ocG];
                float vy = acc[m][nt][hh * 2 + 1] + s_bin[ocG + 1];
                outw[(p0 + p) * 32 + (ocl >> 1)] = packbf2(vx, vy);
            }
        }
    }
}

// ---------------- dense KxK conv, bf16 MMA, 16x16 tile, MT=4, async B -------
template<int K, int PAD, int KOUT, int KOUTP, int SPAN>
__global__ __launch_bounds__(256) void k_conv_tc(
    const uint32_t* __restrict__ in, const uint32_t* __restrict__ wT,
    const float* __restrict__ bias, float* __restrict__ out)
{
    constexpr int HX = 16 + K - 1, HY = 16 + K - 1, HPX = HX * HY;
    constexpr int NT = SPAN / 16;          // n8 tiles per warp (SPAN/2 oc)
    constexpr int SPANP = SPAN + 4;
    constexpr int BW = 32 * SPANP;         // words per B buffer
    extern __shared__ uint32_t sm[];
    uint32_t* As = sm;                     // [HPX][36]
    uint32_t* B0 = sm + HPX * 36;
    uint32_t* B1 = B0 + BW;
    int tid = threadIdx.x, lane = tid & 31, w = tid >> 5;
    int q = lane >> 2, r = lane & 3;
    int pxg = w >> 1, ocg = w & 1;         // 4 pxg x 2 ocg
    int b = blockIdx.z;
    int ty0 = blockIdx.y * 16, tx0 = blockIdx.x * 16;
    uint32_t b0a = smem_u32(B0), b1a = smem_u32(B1);
    float acc[4][NT][4] = {};

    // halo fill (once)
    for (int idx = tid; idx < HPX * 8; idx += 256) {
        int hp = idx >> 3, c8 = idx & 7;
        int hy = hp / HX, hx = hp % HX;
        int yy = ty0 + hy - PAD, xx = tx0 + hx - PAD;
        uint4 val = make_uint4(0u, 0u, 0u, 0u);
        if (yy >= 0 && yy < HH && xx >= 0 && xx < WWID)
            val = *(const uint4*)(in + ((size_t)((b * HH + yy) * WWID + xx)) * 32 + 4 * c8);
        *(uint4*)(As + hp * 36 + 4 * c8) = val;
    }
    // preload B[0] via cp.async
    for (int idx = tid; idx < 8 * SPAN; idx += 256) {
        int kp = idx / (SPAN / 4), oc4 = idx % (SPAN / 4);
        cpa16(b0a + (uint32_t)(kp * SPANP + 4 * oc4) * 4,
              wT + (size_t)kp * KOUTP + 4 * oc4);
    }
    cpa_commit();
    cpa_wait0();
    __syncthreads();

    for (int tap = 0; tap < K * K; tap++) {
        int ki = tap / K, kj = tap % K;
        // stream next tap's B into the other buffer (overlaps compute)
        if (tap + 1 < K * K) {
            uint32_t dsta = ((tap + 1) & 1) ? b1a : b0a;
            const uint32_t* src = wT + (size_t)(tap + 1) * 32 * KOUTP;
            for (int idx = tid; idx < 8 * SPAN; idx += 256) {
                int kp = idx / (SPAN / 4), oc4 = idx % (SPAN / 4);
                cpa16(dsta + (uint32_t)(kp * SPANP + 4 * oc4) * 4,
                      src + kp * KOUTP + 4 * oc4);
            }
            cpa_commit();
        }
        const uint32_t* Bc = (tap & 1) ? B1 : B0;
        #pragma unroll
        for (int kc = 0; kc < 4; kc++) {
            uint32_t a[4][4];
            #pragma unroll
            for (int m = 0; m < 4; m++) {
                int hbase = (pxg * 4 + m + ki) * HX + kj;
                const uint32_t* Ap = As + (hbase + q) * 36 + kc * 8 + r;
                a[m][0] = Ap[0];
                a[m][1] = Ap[8 * 36];
                a[m][2] = Ap[4];
                a[m][3] = Ap[8 * 36 + 4];
            }
            #pragma unroll
            for (int nt = 0; nt < NT; nt++) {
                uint32_t bb[2];
                int ocb = ocg * (SPAN / 2) + nt * 8 + q;
                bb[0] = Bc[(kc * 8 + r)     * SPANP + ocb];
                bb[1] = Bc[(kc * 8 + r + 4) * SPANP + ocb];
                #pragma unroll
                for (int m = 0; m < 4; m++) mma_bf16(acc[m][nt], a[m], bb);
            }
        }
        cpa_wait0();
        __syncthreads();
    }
    // store PLANAR [oc][pixel] fp32 with bias
    #pragma unroll
    for (int m = 0; m < 4; m++) {
        #pragma unroll
        for (int nt = 0; nt < NT; nt++) {
            #pragma unroll
            for (int hh = 0; hh < 2; hh++) {
                int p  = (pxg * 4 + m) * 16 + q + hh * 8;
                int pg = (b * HH + ty0 + (p >> 4)) * WWID + tx0 + (p & 15);
                int oc = ocg * (SPAN / 2) + nt * 8 + 2 * r;
                float v0 = acc[m][nt][hh * 2 + 0];
                float v1 = acc[m][nt][hh * 2 + 1];
                if (oc     < KOUT) out[(size_t)oc       * BHW + pg] = v0 + bias[oc];
                if (oc + 1 < KOUT) out[(size_t)(oc + 1) * BHW + pg] = v1 + bias[oc + 1];
            }
        }
    }
}

// ---------------- deformable KxK conv (Cout=64), 16x16 tile, MT=4 -----------
template<int K, int PAD>
__global__ __launch_bounds__(256) void k_deform_tc(
    const uint32_t* __restrict__ in, const float* __restrict__ off,
    const uint32_t* __restrict__ wT, const float* __restrict__ bias,
    uint32_t* __restrict__ out)
{
    extern __shared__ uint32_t sm[];
    uint32_t* As = sm;                       // [256][36] bf16x2
    uint32_t* Bs = sm + 256 * 36;            // [32][68] bf16x2
    float* w00 = (float*)(Bs + 32 * 68);     // 4 x 256 bilinear weights
    float* w01 = w00 + 256;
    float* w10 = w01 + 256;
    float* w11 = w10 + 256;
    int*   s_y0 = (int*)(w11 + 256);
    int*   s_x0 = s_y0 + 256;

    int tid = threadIdx.x, lane = tid & 31, w = tid >> 5;
    int q = lane >> 2, r = lane & 3;
    int pxg = w >> 1, ocg = w & 1;           // 4 pxg x 2 ocg
    int b = blockIdx.z;
    int ty0 = blockIdx.y * 16, tx0 = blockIdx.x * 16;
    const uint32_t* base = in + (size_t)b * HW * 32;
    float acc[4][4][4] = {};

    for (int tap = 0; tap < K * K; tap++) {
        int ki = tap / K, kj = tap % K;
        __syncthreads();
        for (int idx = tid; idx < 512; idx += 256) {
            int kp = idx >> 4, oc4 = idx & 15;
            *(uint4*)(Bs + kp * 68 + 4 * oc4) =
                ((const uint4*)(wT + ((size_t)tap * 32 + kp) * 64))[oc4];
        }
        {
            int p  = tid;
            int yy = ty0 + (p >> 4), xx = tx0 + (p & 15);
            int pg = (b * HH + yy) * WWID + xx;
            float oy = off[(size_t)(2 * tap)     * BHW + pg];
            float ox = off[(size_t)(2 * tap + 1) * BHW + pg];
            float py = (float)(yy + ki - PAD) + oy;
            float px = (float)(xx + kj - PAD) + ox;
            float fy = floorf(py), fx = floorf(px);
            float wy = py - fy,    wx = px - fx;
            s_y0[p] = (int)fy; s_x0[p] = (int)fx;
            w00[p] = (1.f - wy) * (1.f - wx);
            w01[p] = (1.f - wy) * wx;
            w10[p] = wy * (1.f - wx);
            w11[p] = wy * wx;
        }
        __syncthreads();
        // bilinear sampling from bf16 gmem, uint2 = 4 channels per lane
        #pragma unroll 4
        for (int it = 0; it < 16; it++) {
            int v  = it * 256 + tid;
            int p  = v >> 4, c4 = v & 15;
            int y0 = s_y0[p], x0 = s_x0[p];
            float a00 = w00[p], a01 = w01[p], a10 = w10[p], a11 = w11[p];
            bool yv0 = (unsigned)y0       < HH;
            bool yv1 = (unsigned)(y0 + 1) < HH;
            bool xv0 = (unsigned)x0       < WWID;
            bool xv1 = (unsigned)(x0 + 1) < WWID;
            long long r0 = ((long long)y0 * WWID + x0) * 32 + 2 * c4;
            uint2 z = make_uint2(0u, 0u);
            uint2 u00 = z, u01 = z, u10 = z, u11 = z;
            if (yv0 && xv0) u00 = *(const uint2*)(base + r0);
            if (yv0 && xv1) u01 = *(const uint2*)(base + r0 + 32);
            if (yv1 && xv0) u10 = *(const uint2*)(base + r0 + 32 * WWID);
            if (yv1 && xv1) u11 = *(const uint2*)(base + r0 + 32 * WWID + 32);
            float2 a0 = unpbf2(u00.x), a1 = unpbf2(u01.x);
            float2 a2 = unpbf2(u10.x), a3 = unpbf2(u11.x);
            float rx = a00 * a0.x + a01 * a1.x + a10 * a2.x + a11 * a3.x;
            float ry = a00 * a0.y + a01 * a1.y + a10 * a2.y + a11 * a3.y;
            float2 b0 = unpbf2(u00.y), b1 = unpbf2(u01.y);
            float2 b2 = unpbf2(u10.y), b3 = unpbf2(u11.y);
            float rz = a00 * b0.x + a01 * b1.x + a10 * b2.x + a11 * b3.x;
            float rw = a00 * b0.y + a01 * b1.y + a10 * b2.y + a11 * b3.y;
            uint2 pk;
            pk.x = packbf2(rx, ry);
            pk.y = packbf2(rz, rw);
            *(uint2*)(As + p * 36 + 2 * c4) = pk;
        }
        __syncthreads();
        #pragma unroll
        for (int kc = 0; kc < 4; kc++) {
            uint32_t a[4][4];
            #pragma unroll
            for (int m = 0; m < 4; m++) {
                int pr = (pxg * 4 + m) * 16;
                const uint32_t* Ap = As + (pr + q) * 36 + kc * 8 + r;
                a[m][0] = Ap[0];
                a[m][1] = Ap[8 * 36];
                a[m][2] = Ap[4];
                a[m][3] = Ap[8 * 36 + 4];
            }
            #pragma unroll
            for (int nt = 0; nt < 4; nt++) {
                uint32_t bb[2];
                int ocb = ocg * 32 + nt * 8 + q;
                bb[0] = Bs[(kc * 8 + r)     * 68 + ocb];
                bb[1] = Bs[(kc * 8 + r + 4) * 68 + ocb];
                #pragma unroll
                for (int m = 0; m < 4; m++) mma_bf16(acc[m][nt], a[m], bb);
            }
        }
    }
    #pragma unroll
    for (int m = 0; m < 4; m++) {
        #pragma unroll
        for (int nt = 0; nt < 4; nt++) {
            #pragma unroll
            for (int hh = 0; hh < 2; hh++) {
                int p  = (pxg * 4 + m) * 16 + q + hh * 8;
                int pg = (b * HH + ty0 + (p >> 4)) * WWID + tx0 + (p & 15);
                int oc = ocg * 32 + nt * 8 + 2 * r;
                float vx = acc[m][nt][hh * 2 + 0] + bias[oc];
                float vy = acc[m][nt][hh * 2 + 1] + bias[oc + 1];
                out[(size_t)pg * 32 + (oc >> 1)] = packbf2(vx, vy);
            }
        }
    }
}

// ---------------- final: (x1+x2) @ w_out^T + b_out + residual, bf16 MMA ----
__global__ __launch_bounds__(256) void k_final_tc(
    const uint32_t* __restrict__ x1, const uint32_t* __restrict__ x2,
    const float* __restrict__ xin, const uint32_t* __restrict__ wC,
    const float* __restrict__ b_out, float* __restrict__ out)
{
    __shared__ uint32_t As[128 * 36];
    __shared__ uint32_t Bs[32 * 68];
    int tid = threadIdx.x, lane = tid & 31, w = tid >> 5;
    int q = lane >> 2, r = lane & 3;
    int pxg = w >> 1, ocg = w & 1;
    size_t p0 = (size_t)blockIdx.x * 128;
    for (int idx = tid; idx < 512; idx += 256) {
        int kp = idx >> 4, oc4 = idx & 15;
        *(uint4*)(Bs + kp * 68 + 4 * oc4) = ((const uint4*)wC)[idx];
    }
    for (int idx = tid; idx < 128 * 16; idx += 256) {
        int p = idx >> 4, c4 = idx & 15;
        uint2 a = *(const uint2*)(x1 + (p0 + p) * 32 + 2 * c4);
        uint2 bb = *(const uint2*)(x2 + (p0 + p) * 32 + 2 * c4);
        uint2 pk;
        __nv_bfloat162 sa = __hadd2(*(__nv_bfloat162*)&a.x, *(__nv_bfloat162*)&bb.x);
        __nv_bfloat162 sb = __hadd2(*(__nv_bfloat162*)&a.y, *(__nv_bfloat162*)&bb.y);
        pk.x = *(uint32_t*)&sa;
        pk.y = *(uint32_t*)&sb;
        *(uint2*)(As + p * 36 + 2 * c4) = pk;
    }
    __syncthreads();
    float acc[2][4][4] = {};
    #pragma unroll
    for (int kc = 0; kc < 4; kc++) {
        uint32_t a[2][4];
        #pragma unroll
        for (int m = 0; m < 2; m++) {
            int pr = pxg * 32 + m * 16;
            const uint32_t* Ap = As + (pr + q) * 36 + kc * 8 + r;
            a[m][0] = Ap[0];
            a[m][1] = Ap[8 * 36];
            a[m][2] = Ap[4];
            a[m][3] = Ap[8 * 36 + 4];
        }
        #pragma unroll
        for (int nt = 0; nt < 4; nt++) {
            uint32_t bb[2];
            int ocb = ocg * 32 + nt * 8 + q;
            bb[0] = Bs[(kc * 8 + r)     * 68 + ocb];
            bb[1] = Bs[(kc * 8 + r + 4) * 68 + ocb];
            mma_bf16(acc[0][nt], a[0], bb);
            mma_bf16(acc[1][nt], a[1], bb);
        }
    }
    int b = (int)(p0 / HW);
    int hwbase = (int)(p0 % HW);
    #pragma unroll
    for (int m = 0; m < 2; m++) {
        #pragma unroll
        for (int nt = 0; nt < 4; nt++) {
            #pragma unroll
            for (int hh = 0; hh < 2; hh++) {
                int p  = pxg * 32 + m * 16 + q + hh * 8;
                int hw = hwbase + p;
                int oc = ocg * 32 + nt * 8 + 2 * r;
                size_t a0 = ((size_t)b * 64 + oc) * HW + hw;
                size_t a1 = a0 + HW;
                out[a0] = acc[m][nt][hh * 2 + 0] + b_out[oc]     + xin[a0];
                out[a1] = acc[m][nt][hh * 2 + 1] + b_out[oc + 1] + xin[a1];
            }
        }
    }
}

// ---------------- launch --------------------------------------------------
extern "C" void kernel_launch(void* const* d_in, const int* in_sizes, int n_in,
                              void* d_out, int out_size) {
    const float* x    = (const float*)d_in[0];
    const float* ln_w = (const float*)d_in[1];
    const float* ln_b = (const float*)d_in[2];
    const float* w_in = (const float*)d_in[3];
    const float* b_in = (const float*)d_in[4];
    const float* w_out= (const float*)d_in[5];
    const float* b_out= (const float*)d_in[6];
    const float* dw1  = (const float*)d_in[7];
    const float* db1  = (const float*)d_in[8];
    const float* dw2  = (const float*)d_in[9];
    const float* db2  = (const float*)d_in[10];
    const float* dw3  = (const float*)d_in[11];
    const float* db3  = (const float*)d_in[12];
    const float* ow1  = (const float*)d_in[13];
    const float* ob1  = (const float*)d_in[14];
    const float* ow2  = (const float*)d_in[15];
    const float* ob2  = (const float*)d_in[16];
    const float* ow3  = (const float*)d_in[17];
    const float* ob3  = (const float*)d_in[18];
    float* out = (float*)d_out;

    float *poff;
    uint32_t *px1, *px2, *py, *pwA, *pwB, *pwC, *pwIn;
    cudaGetSymbolAddress((void**)&px1,  g_x1);
    cudaGetSymbolAddress((void**)&px2,  g_x2);
    cudaGetSymbolAddress((void**)&py,   g_y);
    cudaGetSymbolAddress((void**)&poff, g_off);
    cudaGetSymbolAddress((void**)&pwA,  g_wA);
    cudaGetSymbolAddress((void**)&pwB,  g_wB);
    cudaGetSymbolAddress((void**)&pwC,  g_wC);
    cudaGetSymbolAddress((void**)&pwIn, g_wIn);

    const int SMC1 = (20 * 20 * 36 + 2 * 32 * 132) * 4;   // 91.4 KB
    const int SMC2 = (20 * 20 * 36 + 2 * 32 * 68)  * 4;   // 75.0 KB
    const int SMC3 = (18 * 18 * 36 + 2 * 32 * 36)  * 4;   // 55.9 KB
    const int SMD  = (256 * 36 + 32 * 68) * 4 + 256 * 6 * 4;  // 51.7 KB

    cudaFuncSetAttribute(k_conv_tc<5,2,98,128,128>, cudaFuncAttributeMaxDynamicSharedMemorySize, SMC1);
    cudaFuncSetAttribute(k_conv_tc<5,2,50,64,64>,   cudaFuncAttributeMaxDynamicSharedMemorySize, SMC2);
    cudaFuncSetAttribute(k_conv_tc<3,1,18,32,32>,   cudaFuncAttributeMaxDynamicSharedMemorySize, SMC3);
    cudaFuncSetAttribute(k_deform_tc<7,3>, cudaFuncAttributeMaxDynamicSharedMemorySize, SMD);
    cudaFuncSetAttribute(k_deform_tc<5,2>, cudaFuncAttributeMaxDynamicSharedMemorySize, SMD);
    cudaFuncSetAttribute(k_deform_tc<3,1>, cudaFuncAttributeMaxDynamicSharedMemorySize, SMD);

    dim3 tiles(WWID / 16, HH / 16, BATCH);   // 16x16 px tiles

    // fused LN + w_in projection (bf16 MMA), outputs packed bf16 NHWC
    k_transpose_bf<<<32, 256>>>(w_in, pwIn, 1, 128, 128);
    k_ln_win_tc<<<BHW / 128, 256>>>(x, ln_w, ln_b, pwIn, b_in, px1, px2);

    // stage 1: offset conv 5x5 -> 98, deform 7x7
    k_transpose_bf<<<256, 256>>>(ow1, pwA, 25, 98, 128);
    k_conv_tc<5,2,98,128,128><<<tiles, 256, SMC1>>>(px1, pwA, ob1, poff);
    k_transpose_bf<<<256, 256>>>(dw1, pwB, 49, 64, 64);
    k_deform_tc<7,3><<<tiles, 256, SMD>>>(px1, poff, pwB, db1, py);

    // stage 2: offset conv 5x5 -> 50, deform 5x5
    k_transpose_bf<<<256, 256>>>(ow2, pwA, 25, 50, 64);
    k_conv_tc<5,2,50,64,64><<<tiles, 256, SMC2>>>(py, pwA, ob2, poff);
    k_transpose_bf<<<256, 256>>>(dw2, pwB, 25, 64, 64);
    k_deform_tc<5,2><<<tiles, 256, SMD>>>(py, poff, pwB, db2, px1);

    // stage 3: offset conv 3x3 -> 18, deform 3x3
    k_transpose_bf<<<256, 256>>>(ow3, pwA, 9, 18, 32);
    k_conv_tc<3,1,18,32,32><<<tiles, 256, SMC3>>>(px1, pwA, ob3, poff);
    k_transpose_bf<<<256, 256>>>(dw3, pwB, 9, 64, 64);
    k_deform_tc<3,1><<<tiles, 256, SMD>>>(px1, poff, pwB, db3, py);

    k_transpose_bf<<<8, 256>>>(w_out, pwC, 1, 64, 64);
    k_final_tc<<<BHW / 128, 256>>>(py, px2, x, pwC, b_out, out);
}

// round 11
// speedup vs baseline: 2.1847x; 1.0344x over previous
#include <cuda_runtime.h>
#include <cuda_bf16.h>
#include <math.h>
#include <stdint.h>

#define BATCH 4
#define CH    64
#define HH    192
#define WWID  192
#define HW    (HH*WWID)
#define BHW   (BATCH*HW)

// ---------------- device scratch (allocation-free) ----------------
__device__ uint32_t g_x1 [BHW*32];      // bf16x2 NHWC (32 words/px)
__device__ uint32_t g_x2 [BHW*32];      // bf16x2 NHWC
__device__ uint32_t g_y  [BHW*32];      // bf16x2 NHWC ping-pong
__device__ float    g_off[98*BHW];      // PLANAR offsets [ch][pixel], fp32
__device__ uint32_t g_wA [25*32*128];   // packed offset-conv weights [tap][kpair][ocPad]
__device__ uint32_t g_wB [49*32*64];    // packed deform weights      [tap][kpair][oc]
__device__ uint32_t g_wC [32*64];       // packed w_out               [kpair][oc]
__device__ uint32_t g_wIn[32*128];      // packed w_in                [kpair][oc]

// ---------------- helpers ---------------------------------------------------
static __device__ __forceinline__ uint32_t packbf2(float lo, float hi) {
    uint32_t r;
    asm("cvt.rn.bf16x2.f32 %0, %1, %2;" : "=r"(r) : "f"(hi), "f"(lo));
    return r;
}
static __device__ __forceinline__ float2 unpbf2(uint32_t u) {
    return __bfloat1622float2(*(__nv_bfloat162*)&u);
}
static __device__ __forceinline__ void mma_bf16(float* d, const uint32_t* a,
                                                const uint32_t* b) {
    asm volatile(
        "mma.sync.aligned.m16n8k16.row.col.f32.bf16.bf16.f32 "
        "{%0,%1,%2,%3},{%4,%5,%6,%7},{%8,%9},{%0,%1,%2,%3};"
        : "+f"(d[0]), "+f"(d[1]), "+f"(d[2]), "+f"(d[3])
        : "r"(a[0]), "r"(a[1]), "r"(a[2]), "r"(a[3]), "r"(b[0]), "r"(b[1]));
}
static __device__ __forceinline__ uint32_t smem_u32(const void* p) {
    uint32_t a;
    asm("{ .reg .u64 t; cvta.to.shared.u64 t, %1; cvt.u32.u64 %0, t; }"
        : "=r"(a) : "l"(p));
    return a;
}
static __device__ __forceinline__ void cpa16(uint32_t dst, const void* src) {
    asm volatile("cp.async.ca.shared.global [%0], [%1], 16;"
                 :: "r"(dst), "l"(src) : "memory");
}
static __device__ __forceinline__ void cpa_commit() {
    asm volatile("cp.async.commit_group;" ::: "memory");
}
static __device__ __forceinline__ void cpa_wait0() {
    asm volatile("cp.async.wait_group 0;" ::: "memory");
}

// ---------------- weight transpose+pack: w[O][C][K2] -> out[tap][kp][ocPad] -
__global__ void k_transpose_bf(const float* __restrict__ w, uint32_t* __restrict__ out,
                               int K2, int KOUT, int KOUTP) {
    int n = K2 * 32 * KOUTP;
    for (int idx = blockIdx.x * blockDim.x + threadIdx.x; idx < n;
         idx += gridDim.x * blockDim.x) {
        int oc  = idx % KOUTP;
        int kp  = (idx / KOUTP) % 32;
        int tap = idx / (KOUTP * 32);
        float lo = 0.f, hi = 0.f;
        if (oc < KOUT) {
            lo = w[(oc * 64 + 2 * kp)     * K2 + tap];
            hi = w[(oc * 64 + 2 * kp + 1) * K2 + tap];
        }
        out[idx] = packbf2(lo, hi);
    }
}

// ---------------- fused LayerNorm + 1x1 conv (64->128), bf16 MMA ------------
__global__ __launch_bounds__(256) void k_ln_win_tc(
    const float* __restrict__ x, const float* __restrict__ ln_w,
    const float* __restrict__ ln_b, const uint32_t* __restrict__ wIn,
    const float* __restrict__ b_in, uint32_t* __restrict__ out1,
    uint32_t* __restrict__ out2)
{
    __shared__ uint32_t As[128 * 36];
    __shared__ uint32_t Bs[32 * 132];
    __shared__ float s_sum[2][128], s_sq[2][128];
    __shared__ float s_lw[64], s_lb[64], s_bin[128];
    int tid = threadIdx.x, lane = tid & 31, w = tid >> 5;
    int q = lane >> 2, r = lane & 3;
    int pxg = w >> 1, ocg = w & 1;
    size_t p0 = (size_t)blockIdx.x * 128;
    int b = (int)(p0 / HW);
    int hw0 = (int)(p0 % HW);
    const float* xb = x + (size_t)b * 64 * HW + hw0;

    for (int idx = tid; idx < 1024; idx += 256)
        *(uint4*)(Bs + (idx >> 5) * 132 + 4 * (idx & 31)) =
            ((const uint4*)wIn)[idx];
    if (tid < 64) { s_lw[tid] = ln_w[tid]; s_lb[tid] = ln_b[tid]; }
    if (tid < 128) s_bin[tid] = b_in[tid];

    int px = tid & 127, hi2 = tid >> 7;
    float v[32], s = 0.f, sq = 0.f;
    #pragma unroll
    for (int it = 0; it < 32; it++) {
        int c = 2 * it + hi2;
        float val = xb[(size_t)c * HW + px];
        v[it] = val; s += val; sq += val * val;
    }
    s_sum[hi2][px] = s; s_sq[hi2][px] = sq;
    __syncthreads();
    float S = s_sum[0][px] + s_sum[1][px];
    float Q = s_sq[0][px]  + s_sq[1][px];
    float mu = S * (1.f / 64.f);
    float var = Q * (1.f / 64.f) - mu * mu;
    float rs = rsqrtf(var + 1e-5f);
    __nv_bfloat16* Ah = (__nv_bfloat16*)As;
    #pragma unroll
    for (int it = 0; it < 32; it++) {
        int c = 2 * it + hi2;
        float nv = (v[it] - mu) * rs * s_lw[c] + s_lb[c];
        Ah[px * 72 + c] = __float2bfloat16(nv);
    }
    __syncthreads();

    float acc[2][8][4] = {};
    #pragma unroll
    for (int kc = 0; kc < 4; kc++) {
        uint32_t a[2][4];
        #pragma unroll
        for (int m = 0; m < 2; m++) {
            int pr = pxg * 32 + m * 16;
            const uint32_t* Ap = As + (pr + q) * 36 + kc * 8 + r;
            a[m][0] = Ap[0];
            a[m][1] = Ap[8 * 36];
            a[m][2] = Ap[4];
            a[m][3] = Ap[8 * 36 + 4];
        }
        #pragma unroll
        for (int nt = 0; nt < 8; nt++) {
            uint32_t bb[2];
            int ocb = ocg * 64 + nt * 8 + q;
            bb[0] = Bs[(kc * 8 + r)     * 132 + ocb];
            bb[1] = Bs[(kc * 8 + r + 4) * 132 + ocb];
            mma_bf16(acc[0][nt], a[0], bb);
            mma_bf16(acc[1][nt], a[1], bb);
        }
    }
    uint32_t* outw = ocg ? out2 : out1;
    #pragma unroll
    for (int m = 0; m < 2; m++) {
        #pragma unroll
        for (int nt = 0; nt < 8; nt++) {
            #pragma unroll
            for (int hh = 0; hh < 2; hh++) {
                int p = pxg * 32 + m * 16 + q + hh * 8;
                int ocl = nt * 8 + 2 * r;
                int ocG = ocg * 64 + ocl;
                float vx = acc[m][nt][hh * 2 + 0] + s_bin[ocG];
                float vy = acc[m][nt][hh * 2 + 1] + s_bin[ocG + 1];
                outw[(p0 + p) * 32 + (ocl >> 1)] = packbf2(vx, vy);
            }
        }
    }
}

// ---------------- dense KxK conv, bf16 MMA, 16x16 tile, MT=4, async B -------
template<int K, int PAD, int KOUT, int KOUTP, int SPAN>
__global__ __launch_bounds__(256) void k_conv_tc(
    const uint32_t* __restrict__ in, const uint32_t* __restrict__ wT,
    const float* __restrict__ bias, float* __restrict__ out)
{
    constexpr int HX = 16 + K - 1, HY = 16 + K - 1, HPX = HX * HY;
    constexpr int NT = SPAN / 16;
    constexpr int SPANP = SPAN + 4;
    constexpr int BW = 32 * SPANP;
    extern __shared__ uint32_t sm[];
    uint32_t* As = sm;                     // [HPX][36]
    uint32_t* B0 = sm + HPX * 36;
    uint32_t* B1 = B0 + BW;
    int tid = threadIdx.x, lane = tid & 31, w = tid >> 5;
    int q = lane >> 2, r = lane & 3;
    int pxg = w >> 1, ocg = w & 1;
    int b = blockIdx.z;
    int ty0 = blockIdx.y * 16, tx0 = blockIdx.x * 16;
    uint32_t b0a = smem_u32(B0), b1a = smem_u32(B1);
    float acc[4][NT][4] = {};

    for (int idx = tid; idx < HPX * 8; idx += 256) {
        int hp = idx >> 3, c8 = idx & 7;
        int hy = hp / HX, hx = hp % HX;
        int yy = ty0 + hy - PAD, xx = tx0 + hx - PAD;
        uint4 val = make_uint4(0u, 0u, 0u, 0u);
        if (yy >= 0 && yy < HH && xx >= 0 && xx < WWID)
            val = *(const uint4*)(in + ((size_t)((b * HH + yy) * WWID + xx)) * 32 + 4 * c8);
        *(uint4*)(As + hp * 36 + 4 * c8) = val;
    }
    for (int idx = tid; idx < 8 * SPAN; idx += 256) {
        int kp = idx / (SPAN / 4), oc4 = idx % (SPAN / 4);
        cpa16(b0a + (uint32_t)(kp * SPANP + 4 * oc4) * 4,
              wT + (size_t)kp * KOUTP + 4 * oc4);
    }
    cpa_commit();
    cpa_wait0();
    __syncthreads();

    for (int tap = 0; tap < K * K; tap++) {
        int ki = tap / K, kj = tap % K;
        if (tap + 1 < K * K) {
            uint32_t dsta = ((tap + 1) & 1) ? b1a : b0a;
            const uint32_t* src = wT + (size_t)(tap + 1) * 32 * KOUTP;
            for (int idx = tid; idx < 8 * SPAN; idx += 256) {
                int kp = idx / (SPAN / 4), oc4 = idx % (SPAN / 4);
                cpa16(dsta + (uint32_t)(kp * SPANP + 4 * oc4) * 4,
                      src + kp * KOUTP + 4 * oc4);
            }
            cpa_commit();
        }
        const uint32_t* Bc = (tap & 1) ? B1 : B0;
        #pragma unroll
        for (int kc = 0; kc < 4; kc++) {
            uint32_t a[4][4];
            #pragma unroll
            for (int m = 0; m < 4; m++) {
                int hbase = (pxg * 4 + m + ki) * HX + kj;
                const uint32_t* Ap = As + (hbase + q) * 36 + kc * 8 + r;
                a[m][0] = Ap[0];
                a[m][1] = Ap[8 * 36];
                a[m][2] = Ap[4];
                a[m][3] = Ap[8 * 36 + 4];
            }
            #pragma unroll
            for (int nt = 0; nt < NT; nt++) {
                uint32_t bb[2];
                int ocb = ocg * (SPAN / 2) + nt * 8 + q;
                bb[0] = Bc[(kc * 8 + r)     * SPANP + ocb];
                bb[1] = Bc[(kc * 8 + r + 4) * SPANP + ocb];
                #pragma unroll
                for (int m = 0; m < 4; m++) mma_bf16(acc[m][nt], a[m], bb);
            }
        }
        cpa_wait0();
        __syncthreads();
    }
    #pragma unroll
    for (int m = 0; m < 4; m++) {
        #pragma unroll
        for (int nt = 0; nt < NT; nt++) {
            #pragma unroll
            for (int hh = 0; hh < 2; hh++) {
                int p  = (pxg * 4 + m) * 16 + q + hh * 8;
                int pg = (b * HH + ty0 + (p >> 4)) * WWID + tx0 + (p & 15);
                int oc = ocg * (SPAN / 2) + nt * 8 + 2 * r;
                float v0 = acc[m][nt][hh * 2 + 0];
                float v1 = acc[m][nt][hh * 2 + 1];
                if (oc     < KOUT) out[(size_t)oc       * BHW + pg] = v0 + bias[oc];
                if (oc + 1 < KOUT) out[(size_t)(oc + 1) * BHW + pg] = v1 + bias[oc + 1];
            }
        }
    }
}

// ---------------- deformable KxK conv (Cout=64), R8 structure (MT=2) --------
template<int K, int PAD>
__global__ __launch_bounds__(256) void k_deform_tc(
    const uint32_t* __restrict__ in, const float* __restrict__ off,
    const uint32_t* __restrict__ wT, const float* __restrict__ bias,
    uint32_t* __restrict__ out)
{
    extern __shared__ uint32_t sm[];
    uint32_t* As = sm;                       // [128][36] bf16x2
    uint32_t* Bs = sm + 128 * 36;            // [32][68] bf16x2
    float* w00 = (float*)(Bs + 32 * 68);     // 4 x 128 bilinear weights
    float* w01 = w00 + 128;
    float* w10 = w01 + 128;
    float* w11 = w10 + 128;
    int*   s_y0 = (int*)(w11 + 128);
    int*   s_x0 = s_y0 + 128;

    int tid = threadIdx.x, lane = tid & 31, w = tid >> 5;
    int q = lane >> 2, r = lane & 3;
    int pxg = w >> 1, ocg = w & 1;
    int b = blockIdx.z;
    int ty0 = blockIdx.y * 8, tx0 = blockIdx.x * 16;
    const uint32_t* base = in + (size_t)b * HW * 32;
    float acc[2][4][4] = {};

    for (int tap = 0; tap < K * K; tap++) {
        int ki = tap / K, kj = tap % K;
        __syncthreads();
        for (int idx = tid; idx < 512; idx += 256) {
            int kp = idx >> 4, oc4 = idx & 15;
            *(uint4*)(Bs + kp * 68 + 4 * oc4) =
                ((const uint4*)(wT + ((size_t)tap * 32 + kp) * 64))[oc4];
        }
        if (tid < 128) {
            int p  = tid;
            int yy = ty0 + (p >> 4), xx = tx0 + (p & 15);
            int pg = (b * HH + yy) * WWID + xx;
            float oy = off[(size_t)(2 * tap)     * BHW + pg];
            float ox = off[(size_t)(2 * tap + 1) * BHW + pg];
            float py = (float)(yy + ki - PAD) + oy;
            float px = (float)(xx + kj - PAD) + ox;
            float fy = floorf(py), fx = floorf(px);
            float wy = py - fy,    wx = px - fx;
            s_y0[p] = (int)fy; s_x0[p] = (int)fx;
            w00[p] = (1.f - wy) * (1.f - wx);
            w01[p] = (1.f - wy) * wx;
            w10[p] = wy * (1.f - wx);
            w11[p] = wy * wx;
        }
        __syncthreads();
        #pragma unroll 4
        for (int it = 0; it < 8; it++) {
            int v  = it * 256 + tid;
            int p  = v >> 4, c4 = v & 15;
            int y0 = s_y0[p], x0 = s_x0[p];
            float a00 = w00[p], a01 = w01[p], a10 = w10[p], a11 = w11[p];
            bool yv0 = (unsigned)y0       < HH;
            bool yv1 = (unsigned)(y0 + 1) < HH;
            bool xv0 = (unsigned)x0       < WWID;
            bool xv1 = (unsigned)(x0 + 1) < WWID;
            long long r0 = ((long long)y0 * WWID + x0) * 32 + 2 * c4;
            uint2 z = make_uint2(0u, 0u);
            uint2 u00 = z, u01 = z, u10 = z, u11 = z;
            if (yv0 && xv0) u00 = *(const uint2*)(base + r0);
            if (yv0 && xv1) u01 = *(const uint2*)(base + r0 + 32);
            if (yv1 && xv0) u10 = *(const uint2*)(base + r0 + 32 * WWID);
            if (yv1 && xv1) u11 = *(const uint2*)(base + r0 + 32 * WWID + 32);
            float2 a0 = unpbf2(u00.x), a1 = unpbf2(u01.x);
            float2 a2 = unpbf2(u10.x), a3 = unpbf2(u11.x);
            float rx = a00 * a0.x + a01 * a1.x + a10 * a2.x + a11 * a3.x;
            float ry = a00 * a0.y + a01 * a1.y + a10 * a2.y + a11 * a3.y;
            float2 b0 = unpbf2(u00.y), b1 = unpbf2(u01.y);
            float2 b2 = unpbf2(u10.y), b3 = unpbf2(u11.y);
            float rz = a00 * b0.x + a01 * b1.x + a10 * b2.x + a11 * b3.x;
            float rw = a00 * b0.y + a01 * b1.y + a10 * b2.y + a11 * b3.y;
            uint2 pk;
            pk.x = packbf2(rx, ry);
            pk.y = packbf2(rz, rw);
            *(uint2*)(As + p * 36 + 2 * c4) = pk;
        }
        __syncthreads();
        #pragma unroll
        for (int kc = 0; kc < 4; kc++) {
            uint32_t a[2][4];
            #pragma unroll
            for (int m = 0; m < 2; m++) {
                int pr = pxg * 32 + m * 16;
                const uint32_t* Ap = As + (pr + q) * 36 + kc * 8 + r;
                a[m][0] = Ap[0];
                a[m][1] = Ap[8 * 36];
                a[m][2] = Ap[4];
                a[m][3] = Ap[8 * 36 + 4];
            }
            #pragma unroll
            for (int nt = 0; nt < 4; nt++) {
                uint32_t bb[2];
                int ocb = ocg * 32 + nt * 8 + q;
                bb[0] = Bs[(kc * 8 + r)     * 68 + ocb];
                bb[1] = Bs[(kc * 8 + r + 4) * 68 + ocb];
                mma_bf16(acc[0][nt], a[0], bb);
                mma_bf16(acc[1][nt], a[1], bb);
            }
        }
    }
    #pragma unroll
    for (int m = 0; m < 2; m++) {
        #pragma unroll
        for (int nt = 0; nt < 4; nt++) {
            #pragma unroll
            for (int hh = 0; hh < 2; hh++) {
                int p  = pxg * 32 + m * 16 + q + hh * 8;
                int pg = (b * HH + ty0 + (p >> 4)) * WWID + tx0 + (p & 15);
                int oc = ocg * 32 + nt * 8 + 2 * r;
                float vx = acc[m][nt][hh * 2 + 0] + bias[oc];
                float vy = acc[m][nt][hh * 2 + 1] + bias[oc + 1];
                out[(size_t)pg * 32 + (oc >> 1)] = packbf2(vx, vy);
            }
        }
    }
}

// ---------------- final: (x1+x2) @ w_out^T + b_out + residual, bf16 MMA ----
__global__ __launch_bounds__(256) void k_final_tc(
    const uint32_t* __restrict__ x1, const uint32_t* __restrict__ x2,
    const float* __restrict__ xin, const uint32_t* __restrict__ wC,
    const float* __restrict__ b_out, float* __restrict__ out)
{
    __shared__ uint32_t As[128 * 36];
    __shared__ uint32_t Bs[32 * 68];
    int tid = threadIdx.x, lane = tid & 31, w = tid >> 5;
    int q = lane >> 2, r = lane & 3;
    int pxg = w >> 1, ocg = w & 1;
    size_t p0 = (size_t)blockIdx.x * 128;
    for (int idx = tid; idx < 512; idx += 256) {
        int kp = idx >> 4, oc4 = idx & 15;
        *(uint4*)(Bs + kp * 68 + 4 * oc4) = ((const uint4*)wC)[idx];
    }
    for (int idx = tid; idx < 128 * 16; idx += 256) {
        int p = idx >> 4, c4 = idx & 15;
        uint2 a = *(const uint2*)(x1 + (p0 + p) * 32 + 2 * c4);
        uint2 bb = *(const uint2*)(x2 + (p0 + p) * 32 + 2 * c4);
        uint2 pk;
        __nv_bfloat162 sa = __hadd2(*(__nv_bfloat162*)&a.x, *(__nv_bfloat162*)&bb.x);
        __nv_bfloat162 sb = __hadd2(*(__nv_bfloat162*)&a.y, *(__nv_bfloat162*)&bb.y);
        pk.x = *(uint32_t*)&sa;
        pk.y = *(uint32_t*)&sb;
        *(uint2*)(As + p * 36 + 2 * c4) = pk;
    }
    __syncthreads();
    float acc[2][4][4] = {};
    #pragma unroll
    for (int kc = 0; kc < 4; kc++) {
        uint32_t a[2][4];
        #pragma unroll
        for (int m = 0; m < 2; m++) {
            int pr = pxg * 32 + m * 16;
            const uint32_t* Ap = As + (pr + q) * 36 + kc * 8 + r;
            a[m][0] = Ap[0];
            a[m][1] = Ap[8 * 36];
            a[m][2] = Ap[4];
            a[m][3] = Ap[8 * 36 + 4];
        }
        #pragma unroll
        for (int nt = 0; nt < 4; nt++) {
            uint32_t bb[2];
            int ocb = ocg * 32 + nt * 8 + q;
            bb[0] = Bs[(kc * 8 + r)     * 68 + ocb];
            bb[1] = Bs[(kc * 8 + r + 4) * 68 + ocb];
            mma_bf16(acc[0][nt], a[0], bb);
            mma_bf16(acc[1][nt], a[1], bb);
        }
    }
    int b = (int)(p0 / HW);
    int hwbase = (int)(p0 % HW);
    #pragma unroll
    for (int m = 0; m < 2; m++) {
        #pragma unroll
        for (int nt = 0; nt < 4; nt++) {
            #pragma unroll
            for (int hh = 0; hh < 2; hh++) {
                int p  = pxg * 32 + m * 16 + q + hh * 8;
                int hw = hwbase + p;
                int oc = ocg * 32 + nt * 8 + 2 * r;
                size_t a0 = ((size_t)b * 64 + oc) * HW + hw;
                size_t a1 = a0 + HW;
                out[a0] = acc[m][nt][hh * 2 + 0] + b_out[oc]     + xin[a0];
                out[a1] = acc[m][nt][hh * 2 + 1] + b_out[oc + 1] + xin[a1];
            }
        }
    }
}

// ---------------- launch --------------------------------------------------
extern "C" void kernel_launch(void* const* d_in, const int* in_sizes, int n_in,
                              void* d_out, int out_size) {
    const float* x    = (const float*)d_in[0];
    const float* ln_w = (const float*)d_in[1];
    const float* ln_b = (const float*)d_in[2];
    const float* w_in = (const float*)d_in[3];
    const float* b_in = (const float*)d_in[4];
    const float* w_out= (const float*)d_in[5];
    const float* b_out= (const float*)d_in[6];
    const float* dw1  = (const float*)d_in[7];
    const float* db1  = (const float*)d_in[8];
    const float* dw2  = (const float*)d_in[9];
    const float* db2  = (const float*)d_in[10];
    const float* dw3  = (const float*)d_in[11];
    const float* db3  = (const float*)d_in[12];
    const float* ow1  = (const float*)d_in[13];
    const float* ob1  = (const float*)d_in[14];
    const float* ow2  = (const float*)d_in[15];
    const float* ob2  = (const float*)d_in[16];
    const float* ow3  = (const float*)d_in[17];
    const float* ob3  = (const float*)d_in[18];
    float* out = (float*)d_out;

    float *poff;
    uint32_t *px1, *px2, *py, *pwA, *pwB, *pwC, *pwIn;
    cudaGetSymbolAddress((void**)&px1,  g_x1);
    cudaGetSymbolAddress((void**)&px2,  g_x2);
    cudaGetSymbolAddress((void**)&py,   g_y);
    cudaGetSymbolAddress((void**)&poff, g_off);
    cudaGetSymbolAddress((void**)&pwA,  g_wA);
    cudaGetSymbolAddress((void**)&pwB,  g_wB);
    cudaGetSymbolAddress((void**)&pwC,  g_wC);
    cudaGetSymbolAddress((void**)&pwIn, g_wIn);

    const int SMC1 = (20 * 20 * 36 + 2 * 32 * 132) * 4;   // 91.4 KB
    const int SMC2 = (20 * 20 * 36 + 2 * 32 * 68)  * 4;   // 75.0 KB
    const int SMC3 = (18 * 18 * 36 + 2 * 32 * 36)  * 4;   // 55.9 KB
    const int SMD  = (128 * 36 + 32 * 68) * 4 + 128 * 6 * 4;  // 27 KB

    cudaFuncSetAttribute(k_conv_tc<5,2,98,128,128>, cudaFuncAttributeMaxDynamicSharedMemorySize, SMC1);
    cudaFuncSetAttribute(k_conv_tc<5,2,50,64,64>,   cudaFuncAttributeMaxDynamicSharedMemorySize, SMC2);
    cudaFuncSetAttribute(k_conv_tc<3,1,18,32,32>,   cudaFuncAttributeMaxDynamicSharedMemorySize, SMC3);
    cudaFuncSetAttribute(k_deform_tc<7,3>, cudaFuncAttributeMaxDynamicSharedMemorySize, SMD);
    cudaFuncSetAttribute(k_deform_tc<5,2>, cudaFuncAttributeMaxDynamicSharedMemorySize, SMD);
    cudaFuncSetAttribute(k_deform_tc<3,1>, cudaFuncAttributeMaxDynamicSharedMemorySize, SMD);

    dim3 ctiles(WWID / 16, HH / 16, BATCH);  // convs: 16x16 px tiles
    dim3 dtiles(WWID / 16, HH / 8,  BATCH);  // deforms: 16x8 px tiles

    // fused LN + w_in projection (bf16 MMA), outputs packed bf16 NHWC
    k_transpose_bf<<<32, 256>>>(w_in, pwIn, 1, 128, 128);
    k_ln_win_tc<<<BHW / 128, 256>>>(x, ln_w, ln_b, pwIn, b_in, px1, px2);

    // stage 1: offset conv 5x5 -> 98, deform 7x7
    k_transpose_bf<<<256, 256>>>(ow1, pwA, 25, 98, 128);
    k_conv_tc<5,2,98,128,128><<<ctiles, 256, SMC1>>>(px1, pwA, ob1, poff);
    k_transpose_bf<<<256, 256>>>(dw1, pwB, 49, 64, 64);
    k_deform_tc<7,3><<<dtiles, 256, SMD>>>(px1, poff, pwB, db1, py);

    // stage 2: offset conv 5x5 -> 50, deform 5x5
    k_transpose_bf<<<256, 256>>>(ow2, pwA, 25, 50, 64);
    k_conv_tc<5,2,50,64,64><<<ctiles, 256, SMC2>>>(py, pwA, ob2, poff);
    k_transpose_bf<<<256, 256>>>(dw2, pwB, 25, 64, 64);
    k_deform_tc<5,2><<<dtiles, 256, SMD>>>(py, poff, pwB, db2, px1);

    // stage 3: offset conv 3x3 -> 18, deform 3x3
    k_transpose_bf<<<256, 256>>>(ow3, pwA, 9, 18, 32);
    k_conv_tc<3,1,18,32,32><<<ctiles, 256, SMC3>>>(px1, pwA, ob3, poff);
    k_transpose_bf<<<256, 256>>>(dw3, pwB, 9, 64, 64);
    k_deform_tc<3,1><<<dtiles, 256, SMD>>>(px1, poff, pwB, db3, py);

    k_transpose_bf<<<8, 256>>>(w_out, pwC, 1, 64, 64);
    k_final_tc<<<BHW / 128, 256>>>(py, px2, x, pwC, b_out, out);
}

// round 12
// speedup vs baseline: 2.4738x; 1.1324x over previous
#include <cuda_runtime.h>
#include <cuda_bf16.h>
#include <math.h>
#include <stdint.h>

#define BATCH 4
#define CH    64
#define HH    192
#define WWID  192
#define HW    (HH*WWID)
#define BHW   (BATCH*HW)

// ---------------- device scratch (allocation-free) ----------------
__device__ uint32_t g_x1 [BHW*32];      // bf16x2 NHWC (32 words/px)
__device__ uint32_t g_x2 [BHW*32];      // bf16x2 NHWC
__device__ uint32_t g_y  [BHW*32];      // bf16x2 NHWC ping-pong
__device__ float    g_off[98*BHW];      // PLANAR offsets [ch][pixel], fp32
__device__ uint32_t g_wA [25*32*128];   // packed offset-conv weights [tap][kpair][ocPad]
__device__ uint32_t g_wB [49*32*64];    // packed deform weights      [tap][kpair][oc]
__device__ uint32_t g_wC [32*64];       // packed w_out               [kpair][oc]
__device__ uint32_t g_wIn[32*128];      // packed w_in                [kpair][oc]

// ---------------- helpers ---------------------------------------------------
static __device__ __forceinline__ uint32_t packbf2(float lo, float hi) {
    uint32_t r;
    asm("cvt.rn.bf16x2.f32 %0, %1, %2;" : "=r"(r) : "f"(hi), "f"(lo));
    return r;
}
static __device__ __forceinline__ float2 unpbf2(uint32_t u) {
    return __bfloat1622float2(*(__nv_bfloat162*)&u);
}
static __device__ __forceinline__ uint32_t bil1(uint32_t u00, uint32_t u01,
                                                uint32_t u10, uint32_t u11,
                                                float f00, float f01,
                                                float f10, float f11) {
    float2 a = unpbf2(u00), b = unpbf2(u01), c = unpbf2(u10), d = unpbf2(u11);
    return packbf2(f00 * a.x + f01 * b.x + f10 * c.x + f11 * d.x,
                   f00 * a.y + f01 * b.y + f10 * c.y + f11 * d.y);
}
static __device__ __forceinline__ void mma_bf16(float* d, const uint32_t* a,
                                                const uint32_t* b) {
    asm volatile(
        "mma.sync.aligned.m16n8k16.row.col.f32.bf16.bf16.f32 "
        "{%0,%1,%2,%3},{%4,%5,%6,%7},{%8,%9},{%0,%1,%2,%3};"
        : "+f"(d[0]), "+f"(d[1]), "+f"(d[2]), "+f"(d[3])
        : "r"(a[0]), "r"(a[1]), "r"(a[2]), "r"(a[3]), "r"(b[0]), "r"(b[1]));
}
static __device__ __forceinline__ uint32_t smem_u32(const void* p) {
    uint32_t a;
    asm("{ .reg .u64 t; cvta.to.shared.u64 t, %1; cvt.u32.u64 %0, t; }"
        : "=r"(a) : "l"(p));
    return a;
}
static __device__ __forceinline__ void cpa16(uint32_t dst, const void* src) {
    asm volatile("cp.async.ca.shared.global [%0], [%1], 16;"
                 :: "r"(dst), "l"(src) : "memory");
}
static __device__ __forceinline__ void cpa_commit() {
    asm volatile("cp.async.commit_group;" ::: "memory");
}
static __device__ __forceinline__ void cpa_wait0() {
    asm volatile("cp.async.wait_group 0;" ::: "memory");
}

// ---------------- weight transpose+pack: w[O][C][K2] -> out[tap][kp][ocPad] -
__global__ void k_transpose_bf(const float* __restrict__ w, uint32_t* __restrict__ out,
                               int K2, int KOUT, int KOUTP) {
    int n = K2 * 32 * KOUTP;
    for (int idx = blockIdx.x * blockDim.x + threadIdx.x; idx < n;
         idx += gridDim.x * blockDim.x) {
        int oc  = idx % KOUTP;
        int kp  = (idx / KOUTP) % 32;
        int tap = idx / (KOUTP * 32);
        float lo = 0.f, hi = 0.f;
        if (oc < KOUT) {
            lo = w[(oc * 64 + 2 * kp)     * K2 + tap];
            hi = w[(oc * 64 + 2 * kp + 1) * K2 + tap];
        }
        out[idx] = packbf2(lo, hi);
    }
}

// ---------------- fused LayerNorm + 1x1 conv (64->128), bf16 MMA ------------
__global__ __launch_bounds__(256) void k_ln_win_tc(
    const float* __restrict__ x, const float* __restrict__ ln_w,
    const float* __restrict__ ln_b, const uint32_t* __restrict__ wIn,
    const float* __restrict__ b_in, uint32_t* __restrict__ out1,
    uint32_t* __restrict__ out2)
{
    __shared__ uint32_t As[128 * 36];
    __shared__ uint32_t Bs[32 * 132];
    __shared__ float s_sum[2][128], s_sq[2][128];
    __shared__ float s_lw[64], s_lb[64], s_bin[128];
    int tid = threadIdx.x, lane = tid & 31, w = tid >> 5;
    int q = lane >> 2, r = lane & 3;
    int pxg = w >> 1, ocg = w & 1;
    size_t p0 = (size_t)blockIdx.x * 128;
    int b = (int)(p0 / HW);
    int hw0 = (int)(p0 % HW);
    const float* xb = x + (size_t)b * 64 * HW + hw0;

    for (int idx = tid; idx < 1024; idx += 256)
        *(uint4*)(Bs + (idx >> 5) * 132 + 4 * (idx & 31)) =
            ((const uint4*)wIn)[idx];
    if (tid < 64) { s_lw[tid] = ln_w[tid]; s_lb[tid] = ln_b[tid]; }
    if (tid < 128) s_bin[tid] = b_in[tid];

    int px = tid & 127, hi2 = tid >> 7;
    float v[32], s = 0.f, sq = 0.f;
    #pragma unroll
    for (int it = 0; it < 32; it++) {
        int c = 2 * it + hi2;
        float val = xb[(size_t)c * HW + px];
        v[it] = val; s += val; sq += val * val;
    }
    s_sum[hi2][px] = s; s_sq[hi2][px] = sq;
    __syncthreads();
    float S = s_sum[0][px] + s_sum[1][px];
    float Q = s_sq[0][px]  + s_sq[1][px];
    float mu = S * (1.f / 64.f);
    float var = Q * (1.f / 64.f) - mu * mu;
    float rs = rsqrtf(var + 1e-5f);
    __nv_bfloat16* Ah = (__nv_bfloat16*)As;
    #pragma unroll
    for (int it = 0; it < 32; it++) {
        int c = 2 * it + hi2;
        float nv = (v[it] - mu) * rs * s_lw[c] + s_lb[c];
        Ah[px * 72 + c] = __float2bfloat16(nv);
    }
    __syncthreads();

    float acc[2][8][4] = {};
    #pragma unroll
    for (int kc = 0; kc < 4; kc++) {
        uint32_t a[2][4];
        #pragma unroll
        for (int m = 0; m < 2; m++) {
            int pr = pxg * 32 + m * 16;
            const uint32_t* Ap = As + (pr + q) * 36 + kc * 8 + r;
            a[m][0] = Ap[0];
            a[m][1] = Ap[8 * 36];
            a[m][2] = Ap[4];
            a[m][3] = Ap[8 * 36 + 4];
        }
        #pragma unroll
        for (int nt = 0; nt < 8; nt++) {
            uint32_t bb[2];
            int ocb = ocg * 64 + nt * 8 + q;
            bb[0] = Bs[(kc * 8 + r)     * 132 + ocb];
            bb[1] = Bs[(kc * 8 + r + 4) * 132 + ocb];
            mma_bf16(acc[0][nt], a[0], bb);
            mma_bf16(acc[1][nt], a[1], bb);
        }
    }
    uint32_t* outw = ocg ? out2 : out1;
    #pragma unroll
    for (int m = 0; m < 2; m++) {
        #pragma unroll
        for (int nt = 0; nt < 8; nt++) {
            #pragma unroll
            for (int hh = 0; hh < 2; hh++) {
                int p = pxg * 32 + m * 16 + q + hh * 8;
                int ocl = nt * 8 + 2 * r;
                int ocG = ocg * 64 + ocl;
                float vx = acc[m][nt][hh * 2 + 0] + s_bin[ocG];
                float vy = acc[m][nt][hh * 2 + 1] + s_bin[ocG + 1];
                outw[(p0 + p) * 32 + (ocl >> 1)] = packbf2(vx, vy);
            }
        }
    }
}

// ---------------- dense KxK conv, bf16 MMA, 16x16 tile, MT=4, async B -------
template<int K, int PAD, int KOUT, int KOUTP, int SPAN>
__global__ __launch_bounds__(256) void k_conv_tc(
    const uint32_t* __restrict__ in, const uint32_t* __restrict__ wT,
    const float* __restrict__ bias, float* __restrict__ out)
{
    constexpr int HX = 16 + K - 1, HY = 16 + K - 1, HPX = HX * HY;
    constexpr int NT = SPAN / 16;
    constexpr int SPANP = SPAN + 4;
    constexpr int BW = 32 * SPANP;
    extern __shared__ uint32_t sm[];
    uint32_t* As = sm;                     // [HPX][36]
    uint32_t* B0 = sm + HPX * 36;
    uint32_t* B1 = B0 + BW;
    int tid = threadIdx.x, lane = tid & 31, w = tid >> 5;
    int q = lane >> 2, r = lane & 3;
    int pxg = w >> 1, ocg = w & 1;
    int b = blockIdx.z;
    int ty0 = blockIdx.y * 16, tx0 = blockIdx.x * 16;
    uint32_t b0a = smem_u32(B0), b1a = smem_u32(B1);
    float acc[4][NT][4] = {};

    for (int idx = tid; idx < HPX * 8; idx += 256) {
        int hp = idx >> 3, c8 = idx & 7;
        int hy = hp / HX, hx = hp % HX;
        int yy = ty0 + hy - PAD, xx = tx0 + hx - PAD;
        uint4 val = make_uint4(0u, 0u, 0u, 0u);
        if (yy >= 0 && yy < HH && xx >= 0 && xx < WWID)
            val = *(const uint4*)(in + ((size_t)((b * HH + yy) * WWID + xx)) * 32 + 4 * c8);
        *(uint4*)(As + hp * 36 + 4 * c8) = val;
    }
    for (int idx = tid; idx < 8 * SPAN; idx += 256) {
        int kp = idx / (SPAN / 4), oc4 = idx % (SPAN / 4);
        cpa16(b0a + (uint32_t)(kp * SPANP + 4 * oc4) * 4,
              wT + (size_t)kp * KOUTP + 4 * oc4);
    }
    cpa_commit();
    cpa_wait0();
    __syncthreads();

    for (int tap = 0; tap < K * K; tap++) {
        int ki = tap / K, kj = tap % K;
        if (tap + 1 < K * K) {
            uint32_t dsta = ((tap + 1) & 1) ? b1a : b0a;
            const uint32_t* src = wT + (size_t)(tap + 1) * 32 * KOUTP;
            for (int idx = tid; idx < 8 * SPAN; idx += 256) {
                int kp = idx / (SPAN / 4), oc4 = idx % (SPAN / 4);
                cpa16(dsta + (uint32_t)(kp * SPANP + 4 * oc4) * 4,
                      src + kp * KOUTP + 4 * oc4);
            }
            cpa_commit();
        }
        const uint32_t* Bc = (tap & 1) ? B1 : B0;
        #pragma unroll
        for (int kc = 0; kc < 4; kc++) {
            uint32_t a[4][4];
            #pragma unroll
            for (int m = 0; m < 4; m++) {
                int hbase = (pxg * 4 + m + ki) * HX + kj;
                const uint32_t* Ap = As + (hbase + q) * 36 + kc * 8 + r;
                a[m][0] = Ap[0];
                a[m][1] = Ap[8 * 36];
                a[m][2] = Ap[4];
                a[m][3] = Ap[8 * 36 + 4];
            }
            #pragma unroll
            for (int nt = 0; nt < NT; nt++) {
                uint32_t bb[2];
                int ocb = ocg * (SPAN / 2) + nt * 8 + q;
                bb[0] = Bc[(kc * 8 + r)     * SPANP + ocb];
                bb[1] = Bc[(kc * 8 + r + 4) * SPANP + ocb];
                #pragma unroll
                for (int m = 0; m < 4; m++) mma_bf16(acc[m][nt], a[m], bb);
            }
        }
        cpa_wait0();
        __syncthreads();
    }
    #pragma unroll
    for (int m = 0; m < 4; m++) {
        #pragma unroll
        for (int nt = 0; nt < NT; nt++) {
            #pragma unroll
            for (int hh = 0; hh < 2; hh++) {
                int p  = (pxg * 4 + m) * 16 + q + hh * 8;
                int pg = (b * HH + ty0 + (p >> 4)) * WWID + tx0 + (p & 15);
                int oc = ocg * (SPAN / 2) + nt * 8 + 2 * r;
                float v0 = acc[m][nt][hh * 2 + 0];
                float v1 = acc[m][nt][hh * 2 + 1];
                if (oc     < KOUT) out[(size_t)oc       * BHW + pg] = v0 + bias[oc];
                if (oc + 1 < KOUT) out[(size_t)(oc + 1) * BHW + pg] = v1 + bias[oc + 1];
            }
        }
    }
}

// ---------------- deformable KxK conv (Cout=64), MT=2, fused sampling -------
// 8 lanes per pixel (uint4); per-lane redundant offset math; 2 syncs/tap.
template<int K, int PAD>
__global__ __launch_bounds__(256) void k_deform_tc(
    const uint32_t* __restrict__ in, const float* __restrict__ off,
    const uint32_t* __restrict__ wT, const float* __restrict__ bias,
    uint32_t* __restrict__ out)
{
    extern __shared__ uint32_t sm[];
    uint32_t* As = sm;                       // [128][36] bf16x2
    uint32_t* B0 = sm + 128 * 36;            // [32][68] x2 buffers
    uint32_t* B1 = B0 + 32 * 68;
    int tid = threadIdx.x, lane = tid & 31, w = tid >> 5;
    int q = lane >> 2, r = lane & 3;
    int pxg = w >> 1, ocg = w & 1;
    int b = blockIdx.z;
    int ty0 = blockIdx.y * 8, tx0 = blockIdx.x * 16;
    const uint32_t* base = in + (size_t)b * HW * 32;
    uint32_t b0a = smem_u32(B0), b1a = smem_u32(B1);
    float acc[2][4][4] = {};

    // preload B[0]
    for (int idx = tid; idx < 512; idx += 256) {
        int kp = idx >> 4, oc4 = idx & 15;
        cpa16(b0a + (uint32_t)(kp * 68 + 4 * oc4) * 4,
              wT + (size_t)kp * 64 + 4 * oc4);
    }
    cpa_commit();
    cpa_wait0();
    __syncthreads();

    for (int tap = 0; tap < K * K; tap++) {
        int ki = tap / K, kj = tap % K;
        // prefetch next tap's B
        if (tap + 1 < K * K) {
            uint32_t dsta = ((tap + 1) & 1) ? b1a : b0a;
            const uint32_t* src = wT + (size_t)(tap + 1) * 32 * 64;
            for (int idx = tid; idx < 512; idx += 256) {
                int kp = idx >> 4, oc4 = idx & 15;
                cpa16(dsta + (uint32_t)(kp * 68 + 4 * oc4) * 4,
                      src + kp * 64 + 4 * oc4);
            }
            cpa_commit();
        }
        // sampling: 8 lanes per pixel, per-lane params (broadcast offset loads)
        #pragma unroll
        for (int it = 0; it < 4; it++) {
            int v  = it * 256 + tid;
            int p  = v >> 3, c8 = v & 7;
            int yy = ty0 + (p >> 4), xx = tx0 + (p & 15);
            int pg = (b * HH + yy) * WWID + xx;
            float oy = __ldg(off + (size_t)(2 * tap)     * BHW + pg);
            float ox = __ldg(off + (size_t)(2 * tap + 1) * BHW + pg);
            float py = (float)(yy + ki - PAD) + oy;
            float px = (float)(xx + kj - PAD) + ox;
            float fy = floorf(py), fx = floorf(px);
            int y0 = (int)fy, x0 = (int)fx;
            float wy = py - fy, wx = px - fx;
            float f00 = (1.f - wy) * (1.f - wx);
            float f01 = (1.f - wy) * wx;
            float f10 = wy * (1.f - wx);
            float f11 = wy * wx;
            bool yv0 = (unsigned)y0       < HH;
            bool yv1 = (unsigned)(y0 + 1) < HH;
            bool xv0 = (unsigned)x0       < WWID;
            bool xv1 = (unsigned)(x0 + 1) < WWID;
            long long r0 = ((long long)y0 * WWID + x0) * 32 + 4 * c8;
            uint4 z = make_uint4(0u, 0u, 0u, 0u);
            uint4 u00 = z, u01 = z, u10 = z, u11 = z;
            if (yv0 && xv0) u00 = *(const uint4*)(base + r0);
            if (yv0 && xv1) u01 = *(const uint4*)(base + r0 + 32);
            if (yv1 && xv0) u10 = *(const uint4*)(base + r0 + 32 * WWID);
            if (yv1 && xv1) u11 = *(const uint4*)(base + r0 + 32 * WWID + 32);
            uint4 res;
            res.x = bil1(u00.x, u01.x, u10.x, u11.x, f00, f01, f10, f11);
            res.y = bil1(u00.y, u01.y, u10.y, u11.y, f00, f01, f10, f11);
            res.z = bil1(u00.z, u01.z, u10.z, u11.z, f00, f01, f10, f11);
            res.w = bil1(u00.w, u01.w, u10.w, u11.w, f00, f01, f10, f11);
            *(uint4*)(As + p * 36 + 4 * c8) = res;
        }
        __syncthreads();
        const uint32_t* Bc = (tap & 1) ? B1 : B0;
        #pragma unroll
        for (int kc = 0; kc < 4; kc++) {
            uint32_t a[2][4];
            #pragma unroll
            for (int m = 0; m < 2; m++) {
                int pr = pxg * 32 + m * 16;
                const uint32_t* Ap = As + (pr + q) * 36 + kc * 8 + r;
                a[m][0] = Ap[0];
                a[m][1] = Ap[8 * 36];
                a[m][2] = Ap[4];
                a[m][3] = Ap[8 * 36 + 4];
            }
            #pragma unroll
            for (int nt = 0; nt < 4; nt++) {
                uint32_t bb[2];
                int ocb = ocg * 32 + nt * 8 + q;
                bb[0] = Bc[(kc * 8 + r)     * 68 + ocb];
                bb[1] = Bc[(kc * 8 + r + 4) * 68 + ocb];
                mma_bf16(acc[0][nt], a[0], bb);
                mma_bf16(acc[1][nt], a[1], bb);
            }
        }
        cpa_wait0();
        __syncthreads();
    }
    #pragma unroll
    for (int m = 0; m < 2; m++) {
        #pragma unroll
        for (int nt = 0; nt < 4; nt++) {
            #pragma unroll
            for (int hh = 0; hh < 2; hh++) {
                int p  = pxg * 32 + m * 16 + q + hh * 8;
                int pg = (b * HH + ty0 + (p >> 4)) * WWID + tx0 + (p & 15);
                int oc = ocg * 32 + nt * 8 + 2 * r;
                float vx = acc[m][nt][hh * 2 + 0] + bias[oc];
                float vy = acc[m][nt][hh * 2 + 1] + bias[oc + 1];
                out[(size_t)pg * 32 + (oc >> 1)] = packbf2(vx, vy);
            }
        }
    }
}

// ---------------- final: (x1+x2) @ w_out^T + b_out + residual, bf16 MMA ----
__global__ __launch_bounds__(256) void k_final_tc(
    const uint32_t* __restrict__ x1, const uint32_t* __restrict__ x2,
    const float* __restrict__ xin, const uint32_t* __restrict__ wC,
    const float* __restrict__ b_out, float* __restrict__ out)
{
    __shared__ uint32_t As[128 * 36];
    __shared__ uint32_t Bs[32 * 68];
    int tid = threadIdx.x, lane = tid & 31, w = tid >> 5;
    int q = lane >> 2, r = lane & 3;
    int pxg = w >> 1, ocg = w & 1;
    size_t p0 = (size_t)blockIdx.x * 128;
    for (int idx = tid; idx < 512; idx += 256) {
        int kp = idx >> 4, oc4 = idx & 15;
        *(uint4*)(Bs + kp * 68 + 4 * oc4) = ((const uint4*)wC)[idx];
    }
    for (int idx = tid; idx < 128 * 16; idx += 256) {
        int p = idx >> 4, c4 = idx & 15;
        uint2 a = *(const uint2*)(x1 + (p0 + p) * 32 + 2 * c4);
        uint2 bb = *(const uint2*)(x2 + (p0 + p) * 32 + 2 * c4);
        uint2 pk;
        __nv_bfloat162 sa = __hadd2(*(__nv_bfloat162*)&a.x, *(__nv_bfloat162*)&bb.x);
        __nv_bfloat162 sb = __hadd2(*(__nv_bfloat162*)&a.y, *(__nv_bfloat162*)&bb.y);
        pk.x = *(uint32_t*)&sa;
        pk.y = *(uint32_t*)&sb;
        *(uint2*)(As + p * 36 + 2 * c4) = pk;
    }
    __syncthreads();
    float acc[2][4][4] = {};
    #pragma unroll
    for (int kc = 0; kc < 4; kc++) {
        uint32_t a[2][4];
        #pragma unroll
        for (int m = 0; m < 2; m++) {
            int pr = pxg * 32 + m * 16;
            const uint32_t* Ap = As + (pr + q) * 36 + kc * 8 + r;
            a[m][0] = Ap[0];
            a[m][1] = Ap[8 * 36];
            a[m][2] = Ap[4];
            a[m][3] = Ap[8 * 36 + 4];
        }
        #pragma unroll
        for (int nt = 0; nt < 4; nt++) {
            uint32_t bb[2];
            int ocb = ocg * 32 + nt * 8 + q;
            bb[0] = Bs[(kc * 8 + r)     * 68 + ocb];
            bb[1] = Bs[(kc * 8 + r + 4) * 68 + ocb];
            mma_bf16(acc[0][nt], a[0], bb);
            mma_bf16(acc[1][nt], a[1], bb);
        }
    }
    int b = (int)(p0 / HW);
    int hwbase = (int)(p0 % HW);
    #pragma unroll
    for (int m = 0; m < 2; m++) {
        #pragma unroll
        for (int nt = 0; nt < 4; nt++) {
            #pragma unroll
            for (int hh = 0; hh < 2; hh++) {
                int p  = pxg * 32 + m * 16 + q + hh * 8;
                int hw = hwbase + p;
                int oc = ocg * 32 + nt * 8 + 2 * r;
                size_t a0 = ((size_t)b * 64 + oc) * HW + hw;
                size_t a1 = a0 + HW;
                out[a0] = acc[m][nt][hh * 2 + 0] + b_out[oc]     + xin[a0];
                out[a1] = acc[m][nt][hh * 2 + 1] + b_out[oc + 1] + xin[a1];
            }
        }
    }
}

// ---------------- launch --------------------------------------------------
extern "C" void kernel_launch(void* const* d_in, const int* in_sizes, int n_in,
                              void* d_out, int out_size) {
    const float* x    = (const float*)d_in[0];
    const float* ln_w = (const float*)d_in[1];
    const float* ln_b = (const float*)d_in[2];
    const float* w_in = (const float*)d_in[3];
    const float* b_in = (const float*)d_in[4];
    const float* w_out= (const float*)d_in[5];
    const float* b_out= (const float*)d_in[6];
    const float* dw1  = (const float*)d_in[7];
    const float* db1  = (const float*)d_in[8];
    const float* dw2  = (const float*)d_in[9];
    const float* db2  = (const float*)d_in[10];
    const float* dw3  = (const float*)d_in[11];
    const float* db3  = (const float*)d_in[12];
    const float* ow1  = (const float*)d_in[13];
    const float* ob1  = (const float*)d_in[14];
    const float* ow2  = (const float*)d_in[15];
    const float* ob2  = (const float*)d_in[16];
    const float* ow3  = (const float*)d_in[17];
    const float* ob3  = (const float*)d_in[18];
    float* out = (float*)d_out;

    float *poff;
    uint32_t *px1, *px2, *py, *pwA, *pwB, *pwC, *pwIn;
    cudaGetSymbolAddress((void**)&px1,  g_x1);
    cudaGetSymbolAddress((void**)&px2,  g_x2);
    cudaGetSymbolAddress((void**)&py,   g_y);
    cudaGetSymbolAddress((void**)&poff, g_off);
    cudaGetSymbolAddress((void**)&pwA,  g_wA);
    cudaGetSymbolAddress((void**)&pwB,  g_wB);
    cudaGetSymbolAddress((void**)&pwC,  g_wC);
    cudaGetSymbolAddress((void**)&pwIn, g_wIn);

    const int SMC1 = (20 * 20 * 36 + 2 * 32 * 132) * 4;   // 91.4 KB
    const int SMC2 = (20 * 20 * 36 + 2 * 32 * 68)  * 4;   // 75.0 KB
    const int SMC3 = (18 * 18 * 36 + 2 * 32 * 36)  * 4;   // 55.9 KB
    const int SMD  = (128 * 36 + 2 * 32 * 68) * 4;        // 35.4 KB

    cudaFuncSetAttribute(k_conv_tc<5,2,98,128,128>, cudaFuncAttributeMaxDynamicSharedMemorySize, SMC1);
    cudaFuncSetAttribute(k_conv_tc<5,2,50,64,64>,   cudaFuncAttributeMaxDynamicSharedMemorySize, SMC2);
    cudaFuncSetAttribute(k_conv_tc<3,1,18,32,32>,   cudaFuncAttributeMaxDynamicSharedMemorySize, SMC3);
    cudaFuncSetAttribute(k_deform_tc<7,3>, cudaFuncAttributeMaxDynamicSharedMemorySize, SMD);
    cudaFuncSetAttribute(k_deform_tc<5,2>, cudaFuncAttributeMaxDynamicSharedMemorySize, SMD);
    cudaFuncSetAttribute(k_deform_tc<3,1>, cudaFuncAttributeMaxDynamicSharedMemorySize, SMD);

    dim3 ctiles(WWID / 16, HH / 16, BATCH);  // convs: 16x16 px tiles
    dim3 dtiles(WWID / 16, HH / 8,  BATCH);  // deforms: 16x8 px tiles

    // weight prep for stage 1 first (puts deform7x7 at launch #6 for ncu -s 5)
    k_transpose_bf<<<32, 256>>>(w_in, pwIn, 1, 128, 128);
    k_transpose_bf<<<256, 256>>>(ow1, pwA, 25, 98, 128);
    k_transpose_bf<<<256, 256>>>(dw1, pwB, 49, 64, 64);

    k_ln_win_tc<<<BHW / 128, 256>>>(x, ln_w, ln_b, pwIn, b_in, px1, px2);

    // stage 1: offset conv 5x5 -> 98, deform 7x7
    k_conv_tc<5,2,98,128,128><<<ctiles, 256, SMC1>>>(px1, pwA, ob1, poff);
    k_deform_tc<7,3><<<dtiles, 256, SMD>>>(px1, poff, pwB, db1, py);

    // stage 2: offset conv 5x5 -> 50, deform 5x5
    k_transpose_bf<<<256, 256>>>(ow2, pwA, 25, 50, 64);
    k_conv_tc<5,2,50,64,64><<<ctiles, 256, SMC2>>>(py, pwA, ob2, poff);
    k_transpose_bf<<<256, 256>>>(dw2, pwB, 25, 64, 64);
    k_deform_tc<5,2><<<dtiles, 256, SMD>>>(py, poff, pwB, db2, px1);

    // stage 3: offset conv 3x3 -> 18, deform 3x3
    k_transpose_bf<<<256, 256>>>(ow3, pwA, 9, 18, 32);
    k_conv_tc<3,1,18,32,32><<<ctiles, 256, SMC3>>>(px1, pwA, ob3, poff);
    k_transpose_bf<<<256, 256>>>(dw3, pwB, 9, 64, 64);
    k_deform_tc<3,1><<<dtiles, 256, SMD>>>(px1, poff, pwB, db3, py);

    k_transpose_bf<<<8, 256>>>(w_out, pwC, 1, 64, 64);
    k_final_tc<<<BHW / 128, 256>>>(py, px2, x, pwC, b_out, out);
}

// round 13
// speedup vs baseline: 2.4985x; 1.0100x over previous
#include <cuda_runtime.h>
#include <cuda_bf16.h>
#include <math.h>
#include <stdint.h>

#define BATCH 4
#define CH    64
#define HH    192
#define WWID  192
#define HW    (HH*WWID)
#define BHW   (BATCH*HW)

// ---------------- device scratch (allocation-free) ----------------
__device__ uint32_t g_x1 [BHW*32];      // bf16x2 NHWC (32 words/px)
__device__ uint32_t g_x2 [BHW*32];      // bf16x2 NHWC
__device__ uint32_t g_y  [BHW*32];      // bf16x2 NHWC ping-pong
__device__ float    g_off[98*BHW];      // PLANAR offsets [ch][pixel], fp32
__device__ uint32_t g_wIn[32*128];      // packed weights (dedicated buffers)
__device__ uint32_t g_wA1[25*32*128];
__device__ uint32_t g_wB1[49*32*64];
__device__ uint32_t g_wA2[25*32*64];
__device__ uint32_t g_wB2[25*32*64];
__device__ uint32_t g_wA3[9*32*32];
__device__ uint32_t g_wB3[9*32*64];
__device__ uint32_t g_wC [32*64];

// ---------------- helpers ---------------------------------------------------
static __device__ __forceinline__ uint32_t packbf2(float lo, float hi) {
    uint32_t r;
    asm("cvt.rn.bf16x2.f32 %0, %1, %2;" : "=r"(r) : "f"(hi), "f"(lo));
    return r;
}
static __device__ __forceinline__ float2 unpbf2(uint32_t u) {
    return __bfloat1622float2(*(__nv_bfloat162*)&u);
}
static __device__ __forceinline__ uint32_t bil1(uint32_t u00, uint32_t u01,
                                                uint32_t u10, uint32_t u11,
                                                float f00, float f01,
                                                float f10, float f11) {
    float2 a = unpbf2(u00), b = unpbf2(u01), c = unpbf2(u10), d = unpbf2(u11);
    return packbf2(f00 * a.x + f01 * b.x + f10 * c.x + f11 * d.x,
                   f00 * a.y + f01 * b.y + f10 * c.y + f11 * d.y);
}
static __device__ __forceinline__ void mma_bf16(float* d, const uint32_t* a,
                                                const uint32_t* b) {
    asm volatile(
        "mma.sync.aligned.m16n8k16.row.col.f32.bf16.bf16.f32 "
        "{%0,%1,%2,%3},{%4,%5,%6,%7},{%8,%9},{%0,%1,%2,%3};"
        : "+f"(d[0]), "+f"(d[1]), "+f"(d[2]), "+f"(d[3])
        : "r"(a[0]), "r"(a[1]), "r"(a[2]), "r"(a[3]), "r"(b[0]), "r"(b[1]));
}
static __device__ __forceinline__ uint32_t smem_u32(const void* p) {
    uint32_t a;
    asm("{ .reg .u64 t; cvta.to.shared.u64 t, %1; cvt.u32.u64 %0, t; }"
        : "=r"(a) : "l"(p));
    return a;
}
static __device__ __forceinline__ void cpa16(uint32_t dst, const void* src) {
    asm volatile("cp.async.ca.shared.global [%0], [%1], 16;"
                 :: "r"(dst), "l"(src) : "memory");
}
static __device__ __forceinline__ void cpa_commit() {
    asm volatile("cp.async.commit_group;" ::: "memory");
}
static __device__ __forceinline__ void cpa_wait0() {
    asm volatile("cp.async.wait_group 0;" ::: "memory");
}

// ---------------- single weight-pack kernel (all 8 tensors) ----------------
static __device__ __forceinline__ void pack_one(
    const float* __restrict__ w, uint32_t* __restrict__ out,
    int K2, int KOUT, int KOUTP, int gtid, int gs)
{
    int n = K2 * 32 * KOUTP;
    for (int idx = gtid; idx < n; idx += gs) {
        int oc  = idx % KOUTP;
        int kp  = (idx / KOUTP) % 32;
        int tap = idx / (KOUTP * 32);
        float lo = 0.f, hi = 0.f;
        if (oc < KOUT) {
            lo = w[(oc * 64 + 2 * kp)     * K2 + tap];
            hi = w[(oc * 64 + 2 * kp + 1) * K2 + tap];
        }
        out[idx] = packbf2(lo, hi);
    }
}
__global__ void k_pack_all(
    const float* wIn, const float* ow1, const float* dw1,
    const float* ow2, const float* dw2, const float* ow3, const float* dw3,
    const float* wout,
    uint32_t* oIn, uint32_t* oA1, uint32_t* oB1, uint32_t* oA2,
    uint32_t* oB2, uint32_t* oA3, uint32_t* oB3, uint32_t* oC)
{
    int gtid = blockIdx.x * blockDim.x + threadIdx.x;
    int gs   = gridDim.x * blockDim.x;
    pack_one(wIn,  oIn, 1, 128, 128, gtid, gs);
    pack_one(ow1,  oA1, 25, 98, 128, gtid, gs);
    pack_one(dw1,  oB1, 49, 64, 64,  gtid, gs);
    pack_one(ow2,  oA2, 25, 50, 64,  gtid, gs);
    pack_one(dw2,  oB2, 25, 64, 64,  gtid, gs);
    pack_one(ow3,  oA3, 9,  18, 32,  gtid, gs);
    pack_one(dw3,  oB3, 9,  64, 64,  gtid, gs);
    pack_one(wout, oC,  1,  64, 64,  gtid, gs);
}

// ---------------- fused LayerNorm + 1x1 conv (64->128), bf16 MMA ------------
__global__ __launch_bounds__(256) void k_ln_win_tc(
    const float* __restrict__ x, const float* __restrict__ ln_w,
    const float* __restrict__ ln_b, const uint32_t* __restrict__ wIn,
    const float* __restrict__ b_in, uint32_t* __restrict__ out1,
    uint32_t* __restrict__ out2)
{
    __shared__ uint32_t As[128 * 36];
    __shared__ uint32_t Bs[32 * 132];
    __shared__ float s_sum[2][128], s_sq[2][128];
    __shared__ float s_lw[64], s_lb[64], s_bin[128];
    int tid = threadIdx.x, lane = tid & 31, w = tid >> 5;
    int q = lane >> 2, r = lane & 3;
    int pxg = w >> 1, ocg = w & 1;
    size_t p0 = (size_t)blockIdx.x * 128;
    int b = (int)(p0 / HW);
    int hw0 = (int)(p0 % HW);
    const float* xb = x + (size_t)b * 64 * HW + hw0;

    for (int idx = tid; idx < 1024; idx += 256)
        *(uint4*)(Bs + (idx >> 5) * 132 + 4 * (idx & 31)) =
            ((const uint4*)wIn)[idx];
    if (tid < 64) { s_lw[tid] = ln_w[tid]; s_lb[tid] = ln_b[tid]; }
    if (tid < 128) s_bin[tid] = b_in[tid];

    int px = tid & 127, hi2 = tid >> 7;
    float v[32], s = 0.f, sq = 0.f;
    #pragma unroll
    for (int it = 0; it < 32; it++) {
        int c = 2 * it + hi2;
        float val = xb[(size_t)c * HW + px];
        v[it] = val; s += val; sq += val * val;
    }
    s_sum[hi2][px] = s; s_sq[hi2][px] = sq;
    __syncthreads();
    float S = s_sum[0][px] + s_sum[1][px];
    float Q = s_sq[0][px]  + s_sq[1][px];
    float mu = S * (1.f / 64.f);
    float var = Q * (1.f / 64.f) - mu * mu;
    float rs = rsqrtf(var + 1e-5f);
    __nv_bfloat16* Ah = (__nv_bfloat16*)As;
    #pragma unroll
    for (int it = 0; it < 32; it++) {
        int c = 2 * it + hi2;
        float nv = (v[it] - mu) * rs * s_lw[c] + s_lb[c];
        Ah[px * 72 + c] = __float2bfloat16(nv);
    }
    __syncthreads();

    float acc[2][8][4] = {};
    #pragma unroll
    for (int kc = 0; kc < 4; kc++) {
        uint32_t a[2][4];
        #pragma unroll
        for (int m = 0; m < 2; m++) {
            int pr = pxg * 32 + m * 16;
            const uint32_t* Ap = As + (pr + q) * 36 + kc * 8 + r;
            a[m][0] = Ap[0];
            a[m][1] = Ap[8 * 36];
            a[m][2] = Ap[4];
            a[m][3] = Ap[8 * 36 + 4];
        }
        #pragma unroll
        for (int nt = 0; nt < 8; nt++) {
            uint32_t bb[2];
            int ocb = ocg * 64 + nt * 8 + q;
            bb[0] = Bs[(kc * 8 + r)     * 132 + ocb];
            bb[1] = Bs[(kc * 8 + r + 4) * 132 + ocb];
            mma_bf16(acc[0][nt], a[0], bb);
            mma_bf16(acc[1][nt], a[1], bb);
        }
    }
    uint32_t* outw = ocg ? out2 : out1;
    #pragma unroll
    for (int m = 0; m < 2; m++) {
        #pragma unroll
        for (int nt = 0; nt < 8; nt++) {
            #pragma unroll
            for (int hh = 0; hh < 2; hh++) {
                int p = pxg * 32 + m * 16 + q + hh * 8;
                int ocl = nt * 8 + 2 * r;
                int ocG = ocg * 64 + ocl;
                float vx = acc[m][nt][hh * 2 + 0] + s_bin[ocG];
                float vy = acc[m][nt][hh * 2 + 1] + s_bin[ocG + 1];
                outw[(p0 + p) * 32 + (ocl >> 1)] = packbf2(vx, vy);
            }
        }
    }
}

// ---------------- dense KxK conv, bf16 MMA, 16x16 tile, MT=4, async B -------
template<int K, int PAD, int KOUT, int KOUTP, int SPAN>
__global__ __launch_bounds__(256) void k_conv_tc(
    const uint32_t* __restrict__ in, const uint32_t* __restrict__ wT,
    const float* __restrict__ bias, float* __restrict__ out)
{
    constexpr int HX = 16 + K - 1, HY = 16 + K - 1, HPX = HX * HY;
    constexpr int NT = SPAN / 16;
    constexpr int SPANP = SPAN + 4;
    constexpr int BW = 32 * SPANP;
    extern __shared__ uint32_t sm[];
    uint32_t* As = sm;                     // [HPX][36]
    uint32_t* B0 = sm + HPX * 36;
    uint32_t* B1 = B0 + BW;
    int tid = threadIdx.x, lane = tid & 31, w = tid >> 5;
    int q = lane >> 2, r = lane & 3;
    int pxg = w >> 1, ocg = w & 1;
    int b = blockIdx.z;
    int ty0 = blockIdx.y * 16, tx0 = blockIdx.x * 16;
    uint32_t b0a = smem_u32(B0), b1a = smem_u32(B1);
    float acc[4][NT][4] = {};

    for (int idx = tid; idx < HPX * 8; idx += 256) {
        int hp = idx >> 3, c8 = idx & 7;
        int hy = hp / HX, hx = hp % HX;
        int yy = ty0 + hy - PAD, xx = tx0 + hx - PAD;
        uint4 val = make_uint4(0u, 0u, 0u, 0u);
        if (yy >= 0 && yy < HH && xx >= 0 && xx < WWID)
            val = *(const uint4*)(in + ((size_t)((b * HH + yy) * WWID + xx)) * 32 + 4 * c8);
        *(uint4*)(As + hp * 36 + 4 * c8) = val;
    }
    for (int idx = tid; idx < 8 * SPAN; idx += 256) {
        int kp = idx / (SPAN / 4), oc4 = idx % (SPAN / 4);
        cpa16(b0a + (uint32_t)(kp * SPANP + 4 * oc4) * 4,
              wT + (size_t)kp * KOUTP + 4 * oc4);
    }
    cpa_commit();
    cpa_wait0();
    __syncthreads();

    for (int tap = 0; tap < K * K; tap++) {
        int ki = tap / K, kj = tap % K;
        if (tap + 1 < K * K) {
            uint32_t dsta = ((tap + 1) & 1) ? b1a : b0a;
            const uint32_t* src = wT + (size_t)(tap + 1) * 32 * KOUTP;
            for (int idx = tid; idx < 8 * SPAN; idx += 256) {
                int kp = idx / (SPAN / 4), oc4 = idx % (SPAN / 4);
                cpa16(dsta + (uint32_t)(kp * SPANP + 4 * oc4) * 4,
                      src + kp * KOUTP + 4 * oc4);
            }
            cpa_commit();
        }
        const uint32_t* Bc = (tap & 1) ? B1 : B0;
        #pragma unroll
        for (int kc = 0; kc < 4; kc++) {
            uint32_t a[4][4];
            #pragma unroll
            for (int m = 0; m < 4; m++) {
                int hbase = (pxg * 4 + m + ki) * HX + kj;
                const uint32_t* Ap = As + (hbase + q) * 36 + kc * 8 + r;
                a[m][0] = Ap[0];
                a[m][1] = Ap[8 * 36];
                a[m][2] = Ap[4];
                a[m][3] = Ap[8 * 36 + 4];
            }
            #pragma unroll
            for (int nt = 0; nt < NT; nt++) {
                uint32_t bb[2];
                int ocb = ocg * (SPAN / 2) + nt * 8 + q;
                bb[0] = Bc[(kc * 8 + r)     * SPANP + ocb];
                bb[1] = Bc[(kc * 8 + r + 4) * SPANP + ocb];
                #pragma unroll
                for (int m = 0; m < 4; m++) mma_bf16(acc[m][nt], a[m], bb);
            }
        }
        cpa_wait0();
        __syncthreads();
    }
    #pragma unroll
    for (int m = 0; m < 4; m++) {
        #pragma unroll
        for (int nt = 0; nt < NT; nt++) {
            #pragma unroll
            for (int hh = 0; hh < 2; hh++) {
                int p  = (pxg * 4 + m) * 16 + q + hh * 8;
                int pg = (b * HH + ty0 + (p >> 4)) * WWID + tx0 + (p & 15);
                int oc = ocg * (SPAN / 2) + nt * 8 + 2 * r;
                float v0 = acc[m][nt][hh * 2 + 0];
                float v1 = acc[m][nt][hh * 2 + 1];
                if (oc     < KOUT) out[(size_t)oc       * BHW + pg] = v0 + bias[oc];
                if (oc + 1 < KOUT) out[(size_t)(oc + 1) * BHW + pg] = v1 + bias[oc + 1];
            }
        }
    }
}

// ---------------- deformable KxK conv; optional fused final projection ------
// FUSE=1: epilogue computes (deform_out + x2) @ wC + b_out + xin -> NCHW fp32
template<int K, int PAD, int FUSE>
__global__ __launch_bounds__(256) void k_deform_tc(
    const uint32_t* __restrict__ in, const float* __restrict__ off,
    const uint32_t* __restrict__ wT, const float* __restrict__ bias,
    uint32_t* __restrict__ outb,
    const uint32_t* __restrict__ x2, const float* __restrict__ xin,
    const uint32_t* __restrict__ wC, const float* __restrict__ b_out,
    float* __restrict__ outf)
{
    extern __shared__ uint32_t sm[];
    uint32_t* As = sm;                       // [128][36] bf16x2
    uint32_t* B0 = sm + 128 * 36;            // [32][68] x2 buffers
    uint32_t* B1 = B0 + 32 * 68;
    int tid = threadIdx.x, lane = tid & 31, w = tid >> 5;
    int q = lane >> 2, r = lane & 3;
    int pxg = w >> 1, ocg = w & 1;
    int b = blockIdx.z;
    int ty0 = blockIdx.y * 8, tx0 = blockIdx.x * 16;
    const uint32_t* base = in + (size_t)b * HW * 32;
    uint32_t b0a = smem_u32(B0), b1a = smem_u32(B1);
    float acc[2][4][4] = {};

    for (int idx = tid; idx < 512; idx += 256) {
        int kp = idx >> 4, oc4 = idx & 15;
        cpa16(b0a + (uint32_t)(kp * 68 + 4 * oc4) * 4,
              wT + (size_t)kp * 64 + 4 * oc4);
    }
    cpa_commit();
    cpa_wait0();
    __syncthreads();

    for (int tap = 0; tap < K * K; tap++) {
        int ki = tap / K, kj = tap % K;
        if (tap + 1 < K * K) {
            uint32_t dsta = ((tap + 1) & 1) ? b1a : b0a;
            const uint32_t* src = wT + (size_t)(tap + 1) * 32 * 64;
            for (int idx = tid; idx < 512; idx += 256) {
                int kp = idx >> 4, oc4 = idx & 15;
                cpa16(dsta + (uint32_t)(kp * 68 + 4 * oc4) * 4,
                      src + kp * 64 + 4 * oc4);
            }
            cpa_commit();
        }
        #pragma unroll
        for (int it = 0; it < 4; it++) {
            int v  = it * 256 + tid;
            int p  = v >> 3, c8 = v & 7;
            int yy = ty0 + (p >> 4), xx = tx0 + (p & 15);
            int pg = (b * HH + yy) * WWID + xx;
            float oy = __ldg(off + (size_t)(2 * tap)     * BHW + pg);
            float ox = __ldg(off + (size_t)(2 * tap + 1) * BHW + pg);
            float py = (float)(yy + ki - PAD) + oy;
            float px = (float)(xx + kj - PAD) + ox;
            float fy = floorf(py), fx = floorf(px);
            int y0 = (int)fy, x0 = (int)fx;
            float wy = py - fy, wx = px - fx;
            float f00 = (1.f - wy) * (1.f - wx);
            float f01 = (1.f - wy) * wx;
            float f10 = wy * (1.f - wx);
            float f11 = wy * wx;
            bool yv0 = (unsigned)y0       < HH;
            bool yv1 = (unsigned)(y0 + 1) < HH;
            bool xv0 = (unsigned)x0       < WWID;
            bool xv1 = (unsigned)(x0 + 1) < WWID;
            long long r0 = ((long long)y0 * WWID + x0) * 32 + 4 * c8;
            uint4 z = make_uint4(0u, 0u, 0u, 0u);
            uint4 u00 = z, u01 = z, u10 = z, u11 = z;
            if (yv0 && xv0) u00 = *(const uint4*)(base + r0);
            if (yv0 && xv1) u01 = *(const uint4*)(base + r0 + 32);
            if (yv1 && xv0) u10 = *(const uint4*)(base + r0 + 32 * WWID);
            if (yv1 && xv1) u11 = *(const uint4*)(base + r0 + 32 * WWID + 32);
            uint4 res;
            res.x = bil1(u00.x, u01.x, u10.x, u11.x, f00, f01, f10, f11);
            res.y = bil1(u00.y, u01.y, u10.y, u11.y, f00, f01, f10, f11);
            res.z = bil1(u00.z, u01.z, u10.z, u11.z, f00, f01, f10, f11);
            res.w = bil1(u00.w, u01.w, u10.w, u11.w, f00, f01, f10, f11);
            *(uint4*)(As + p * 36 + 4 * c8) = res;
        }
        __syncthreads();
        const uint32_t* Bc = (tap & 1) ? B1 : B0;
        #pragma unroll
        for (int kc = 0; kc < 4; kc++) {
            uint32_t a[2][4];
            #pragma unroll
            for (int m = 0; m < 2; m++) {
                int pr = pxg * 32 + m * 16;
                const uint32_t* Ap = As + (pr + q) * 36 + kc * 8 + r;
                a[m][0] = Ap[0];
                a[m][1] = Ap[8 * 36];
                a[m][2] = Ap[4];
                a[m][3] = Ap[8 * 36 + 4];
            }
            #pragma unroll
            for (int nt = 0; nt < 4; nt++) {
                uint32_t bb[2];
                int ocb = ocg * 32 + nt * 8 + q;
                bb[0] = Bc[(kc * 8 + r)     * 68 + ocb];
                bb[1] = Bc[(kc * 8 + r + 4) * 68 + ocb];
                mma_bf16(acc[0][nt], a[0], bb);
                mma_bf16(acc[1][nt], a[1], bb);
            }
        }
        cpa_wait0();
        __syncthreads();
    }

    if (!FUSE) {
        #pragma unroll
        for (int m = 0; m < 2; m++) {
            #pragma unroll
            for (int nt = 0; nt < 4; nt++) {
                #pragma unroll
                for (int hh = 0; hh < 2; hh++) {
                    int p  = pxg * 32 + m * 16 + q + hh * 8;
                    int pg = (b * HH + ty0 + (p >> 4)) * WWID + tx0 + (p & 15);
                    int oc = ocg * 32 + nt * 8 + 2 * r;
                    float vx = acc[m][nt][hh * 2 + 0] + bias[oc];
                    float vy = acc[m][nt][hh * 2 + 1] + bias[oc + 1];
                    outb[(size_t)pg * 32 + (oc >> 1)] = packbf2(vx, vy);
                }
            }
        }
    } else {
        // stage (deform_out + x2) as bf16 A-tile in As
        #pragma unroll
        for (int m = 0; m < 2; m++) {
            #pragma unroll
            for (int nt = 0; nt < 4; nt++) {
                #pragma unroll
                for (int hh = 0; hh < 2; hh++) {
                    int p  = pxg * 32 + m * 16 + q + hh * 8;
                    int pg = (b * HH + ty0 + (p >> 4)) * WWID + tx0 + (p & 15);
                    int oc = ocg * 32 + nt * 8 + 2 * r;
                    float2 xv = unpbf2(x2[(size_t)pg * 32 + (oc >> 1)]);
                    float vx = acc[m][nt][hh * 2 + 0] + bias[oc]     + xv.x;
                    float vy = acc[m][nt][hh * 2 + 1] + bias[oc + 1] + xv.y;
                    As[p * 36 + (oc >> 1)] = packbf2(vx, vy);
                }
            }
        }
        // load wC into B0
        for (int idx = tid; idx < 512; idx += 256) {
            int kp = idx >> 4, oc4 = idx & 15;
            *(uint4*)(B0 + kp * 68 + 4 * oc4) = ((const uint4*)wC)[idx];
        }
        __syncthreads();
        // final GEMM (reuse acc)
        #pragma unroll
        for (int m = 0; m < 2; m++)
            #pragma unroll
            for (int nt = 0; nt < 4; nt++)
                #pragma unroll
                for (int j = 0; j < 4; j++) acc[m][nt][j] = 0.f;
        #pragma unroll
        for (int kc = 0; kc < 4; kc++) {
            uint32_t a[2][4];
            #pragma unroll
            for (int m = 0; m < 2; m++) {
                int pr = pxg * 32 + m * 16;
                const uint32_t* Ap = As + (pr + q) * 36 + kc * 8 + r;
                a[m][0] = Ap[0];
                a[m][1] = Ap[8 * 36];
                a[m][2] = Ap[4];
                a[m][3] = Ap[8 * 36 + 4];
            }
            #pragma unroll
            for (int nt = 0; nt < 4; nt++) {
                uint32_t bb[2];
                int ocb = ocg * 32 + nt * 8 + q;
                bb[0] = B0[(kc * 8 + r)     * 68 + ocb];
                bb[1] = B0[(kc * 8 + r + 4) * 68 + ocb];
                mma_bf16(acc[0][nt], a[0], bb);
                mma_bf16(acc[1][nt], a[1], bb);
            }
        }
        // store NCHW fp32 with b_out + residual
        #pragma unroll
        for (int m = 0; m < 2; m++) {
            #pragma unroll
            for (int nt = 0; nt < 4; nt++) {
                #pragma unroll
                for (int hh = 0; hh < 2; hh++) {
                    int p  = pxg * 32 + m * 16 + q + hh * 8;
                    int hw = (ty0 + (p >> 4)) * WWID + tx0 + (p & 15);
                    int oc = ocg * 32 + nt * 8 + 2 * r;
                    size_t a0 = ((size_t)b * 64 + oc) * HW + hw;
                    size_t a1 = a0 + HW;
                    outf[a0] = acc[m][nt][hh * 2 + 0] + b_out[oc]     + xin[a0];
                    outf[a1] = acc[m][nt][hh * 2 + 1] + b_out[oc + 1] + xin[a1];
                }
            }
        }
    }
}

// ---------------- launch --------------------------------------------------
extern "C" void kernel_launch(void* const* d_in, const int* in_sizes, int n_in,
                              void* d_out, int out_size) {
    const float* x    = (const float*)d_in[0];
    const float* ln_w = (const float*)d_in[1];
    const float* ln_b = (const float*)d_in[2];
    const float* w_in = (const float*)d_in[3];
    const float* b_in = (const float*)d_in[4];
    const float* w_out= (const float*)d_in[5];
    const float* b_out= (const float*)d_in[6];
    const float* dw1  = (const float*)d_in[7];
    const float* db1  = (const float*)d_in[8];
    const float* dw2  = (const float*)d_in[9];
    const float* db2  = (const float*)d_in[10];
    const float* dw3  = (const float*)d_in[11];
    const float* db3  = (const float*)d_in[12];
    const float* ow1  = (const float*)d_in[13];
    const float* ob1  = (const float*)d_in[14];
    const float* ow2  = (const float*)d_in[15];
    const float* ob2  = (const float*)d_in[16];
    const float* ow3  = (const float*)d_in[17];
    const float* ob3  = (const float*)d_in[18];
    float* out = (float*)d_out;

    float *poff;
    uint32_t *px1, *px2, *py, *pwIn, *pwA1, *pwB1, *pwA2, *pwB2, *pwA3, *pwB3, *pwC;
    cudaGetSymbolAddress((void**)&px1,  g_x1);
    cudaGetSymbolAddress((void**)&px2,  g_x2);
    cudaGetSymbolAddress((void**)&py,   g_y);
    cudaGetSymbolAddress((void**)&poff, g_off);
    cudaGetSymbolAddress((void**)&pwIn, g_wIn);
    cudaGetSymbolAddress((void**)&pwA1, g_wA1);
    cudaGetSymbolAddress((void**)&pwB1, g_wB1);
    cudaGetSymbolAddress((void**)&pwA2, g_wA2);
    cudaGetSymbolAddress((void**)&pwB2, g_wB2);
    cudaGetSymbolAddress((void**)&pwA3, g_wA3);
    cudaGetSymbolAddress((void**)&pwB3, g_wB3);
    cudaGetSymbolAddress((void**)&pwC,  g_wC);

    const int SMC1 = (20 * 20 * 36 + 2 * 32 * 132) * 4;   // 91.4 KB
    const int SMC2 = (20 * 20 * 36 + 2 * 32 * 68)  * 4;   // 75.0 KB
    const int SMC3 = (18 * 18 * 36 + 2 * 32 * 36)  * 4;   // 55.9 KB
    const int SMD  = (128 * 36 + 2 * 32 * 68) * 4;        // 35.4 KB

    cudaFuncSetAttribute(k_conv_tc<5,2,98,128,128>, cudaFuncAttributeMaxDynamicSharedMemorySize, SMC1);
    cudaFuncSetAttribute(k_conv_tc<5,2,50,64,64>,   cudaFuncAttributeMaxDynamicSharedMemorySize, SMC2);
    cudaFuncSetAttribute(k_conv_tc<3,1,18,32,32>,   cudaFuncAttributeMaxDynamicSharedMemorySize, SMC3);
    cudaFuncSetAttribute(k_deform_tc<7,3,0>, cudaFuncAttributeMaxDynamicSharedMemorySize, SMD);
    cudaFuncSetAttribute(k_deform_tc<5,2,0>, cudaFuncAttributeMaxDynamicSharedMemorySize, SMD);
    cudaFuncSetAttribute(k_deform_tc<3,1,1>, cudaFuncAttributeMaxDynamicSharedMemorySize, SMD);

    dim3 ctiles(WWID / 16, HH / 16, BATCH);  // convs: 16x16 px tiles
    dim3 dtiles(WWID / 16, HH / 8,  BATCH);  // deforms: 16x8 px tiles

    // all weight packing in ONE launch
    k_pack_all<<<256, 256>>>(w_in, ow1, dw1, ow2, dw2, ow3, dw3, w_out,
                             pwIn, pwA1, pwB1, pwA2, pwB2, pwA3, pwB3, pwC);

    k_ln_win_tc<<<BHW / 128, 256>>>(x, ln_w, ln_b, pwIn, b_in, px1, px2);

    // stage 1
    k_conv_tc<5,2,98,128,128><<<ctiles, 256, SMC1>>>(px1, pwA1, ob1, poff);
    k_deform_tc<7,3,0><<<dtiles, 256, SMD>>>(px1, poff, pwB1, db1, py,
                                             nullptr, nullptr, nullptr, nullptr, nullptr);
    // stage 2
    k_conv_tc<5,2,50,64,64><<<ctiles, 256, SMC2>>>(py, pwA2, ob2, poff);
    k_deform_tc<5,2,0><<<dtiles, 256, SMD>>>(py, poff, pwB2, db2, px1,
                                             nullptr, nullptr, nullptr, nullptr, nullptr);
    // stage 3 (deform fused with final projection + residual)
    k_conv_tc<3,1,18,32,32><<<ctiles, 256, SMC3>>>(px1, pwA3, ob3, poff);
    k_deform_tc<3,1,1><<<dtiles, 256, SMD>>>(px1, poff, pwB3, db3, nullptr,
                                             px2, x, pwC, b_out, out);
}

// round 14
// speedup vs baseline: 2.7610x; 1.1051x over previous
#include <cuda_runtime.h>
#include <cuda_bf16.h>
#include <math.h>
#include <stdint.h>

#define BATCH 4
#define CH    64
#define HH    192
#define WWID  192
#define HW    (HH*WWID)
#define BHW   (BATCH*HW)

// ---------------- device scratch (allocation-free) ----------------
__device__ uint32_t g_x1 [BHW*32];      // bf16x2 NHWC (32 words/px)
__device__ uint32_t g_x2 [BHW*32];      // bf16x2 NHWC
__device__ uint32_t g_y  [BHW*32];      // bf16x2 NHWC ping-pong
__device__ float    g_off[98*BHW];      // PLANAR offsets [ch][pixel], fp32
__device__ uint32_t g_wIn[32*128];      // packed weights (dedicated buffers)
__device__ uint32_t g_wA1[25*32*128];
__device__ uint32_t g_wB1[49*32*64];
__device__ uint32_t g_wA2[25*32*64];
__device__ uint32_t g_wB2[25*32*64];
__device__ uint32_t g_wA3[9*32*32];
__device__ uint32_t g_wB3[9*32*64];
__device__ uint32_t g_wC [32*64];

// ---------------- helpers ---------------------------------------------------
static __device__ __forceinline__ uint32_t packbf2(float lo, float hi) {
    uint32_t r;
    asm("cvt.rn.bf16x2.f32 %0, %1, %2;" : "=r"(r) : "f"(hi), "f"(lo));
    return r;
}
static __device__ __forceinline__ float2 unpbf2(uint32_t u) {
    return __bfloat1622float2(*(__nv_bfloat162*)&u);
}
static __device__ __forceinline__ void mma_bf16(float* d, const uint32_t* a,
                                                const uint32_t* b) {
    asm volatile(
        "mma.sync.aligned.m16n8k16.row.col.f32.bf16.bf16.f32 "
        "{%0,%1,%2,%3},{%4,%5,%6,%7},{%8,%9},{%0,%1,%2,%3};"
        : "+f"(d[0]), "+f"(d[1]), "+f"(d[2]), "+f"(d[3])
        : "r"(a[0]), "r"(a[1]), "r"(a[2]), "r"(a[3]), "r"(b[0]), "r"(b[1]));
}
static __device__ __forceinline__ uint32_t smem_u32(const void* p) {
    uint32_t a;
    asm("{ .reg .u64 t; cvta.to.shared.u64 t, %1; cvt.u32.u64 %0, t; }"
        : "=r"(a) : "l"(p));
    return a;
}
static __device__ __forceinline__ void cpa16(uint32_t dst, const void* src) {
    asm volatile("cp.async.ca.shared.global [%0], [%1], 16;"
                 :: "r"(dst), "l"(src) : "memory");
}
static __device__ __forceinline__ void cpa_commit() {
    asm volatile("cp.async.commit_group;" ::: "memory");
}
static __device__ __forceinline__ void cpa_wait0() {
    asm volatile("cp.async.wait_group 0;" ::: "memory");
}
#define B2REF(u) (*(__nv_bfloat162*)&(u))

// ---------------- single weight-pack kernel (all 8 tensors) ----------------
static __device__ __forceinline__ void pack_one(
    const float* __restrict__ w, uint32_t* __restrict__ out,
    int K2, int KOUT, int KOUTP, int gtid, int gs)
{
    int n = K2 * 32 * KOUTP;
    for (int idx = gtid; idx < n; idx += gs) {
        int oc  = idx % KOUTP;
        int kp  = (idx / KOUTP) % 32;
        int tap = idx / (KOUTP * 32);
        float lo = 0.f, hi = 0.f;
        if (oc < KOUT) {
            lo = w[(oc * 64 + 2 * kp)     * K2 + tap];
            hi = w[(oc * 64 + 2 * kp + 1) * K2 + tap];
        }
        out[idx] = packbf2(lo, hi);
    }
}
__global__ void k_pack_all(
    const float* wIn, const float* ow1, const float* dw1,
    const float* ow2, const float* dw2, const float* ow3, const float* dw3,
    const float* wout,
    uint32_t* oIn, uint32_t* oA1, uint32_t* oB1, uint32_t* oA2,
    uint32_t* oB2, uint32_t* oA3, uint32_t* oB3, uint32_t* oC)
{
    int gtid = blockIdx.x * blockDim.x + threadIdx.x;
    int gs   = gridDim.x * blockDim.x;
    pack_one(wIn,  oIn, 1, 128, 128, gtid, gs);
    pack_one(ow1,  oA1, 25, 98, 128, gtid, gs);
    pack_one(dw1,  oB1, 49, 64, 64,  gtid, gs);
    pack_one(ow2,  oA2, 25, 50, 64,  gtid, gs);
    pack_one(dw2,  oB2, 25, 64, 64,  gtid, gs);
    pack_one(ow3,  oA3, 9,  18, 32,  gtid, gs);
    pack_one(dw3,  oB3, 9,  64, 64,  gtid, gs);
    pack_one(wout, oC,  1,  64, 64,  gtid, gs);
}

// ---------------- fused LayerNorm + 1x1 conv (64->128), bf16 MMA ------------
__global__ __launch_bounds__(256) void k_ln_win_tc(
    const float* __restrict__ x, const float* __restrict__ ln_w,
    const float* __restrict__ ln_b, const uint32_t* __restrict__ wIn,
    const float* __restrict__ b_in, uint32_t* __restrict__ out1,
    uint32_t* __restrict__ out2)
{
    __shared__ uint32_t As[128 * 36];
    __shared__ uint32_t Bs[32 * 132];
    __shared__ float s_sum[2][128], s_sq[2][128];
    __shared__ float s_lw[64], s_lb[64], s_bin[128];
    int tid = threadIdx.x, lane = tid & 31, w = tid >> 5;
    int q = lane >> 2, r = lane & 3;
    int pxg = w >> 1, ocg = w & 1;
    size_t p0 = (size_t)blockIdx.x * 128;
    int b = (int)(p0 / HW);
    int hw0 = (int)(p0 % HW);
    const float* xb = x + (size_t)b * 64 * HW + hw0;

    for (int idx = tid; idx < 1024; idx += 256)
        *(uint4*)(Bs + (idx >> 5) * 132 + 4 * (idx & 31)) =
            ((const uint4*)wIn)[idx];
    if (tid < 64) { s_lw[tid] = ln_w[tid]; s_lb[tid] = ln_b[tid]; }
    if (tid < 128) s_bin[tid] = b_in[tid];

    int px = tid & 127, hi2 = tid >> 7;
    float v[32], s = 0.f, sq = 0.f;
    #pragma unroll
    for (int it = 0; it < 32; it++) {
        int c = 2 * it + hi2;
        float val = xb[(size_t)c * HW + px];
        v[it] = val; s += val; sq += val * val;
    }
    s_sum[hi2][px] = s; s_sq[hi2][px] = sq;
    __syncthreads();
    float S = s_sum[0][px] + s_sum[1][px];
    float Q = s_sq[0][px]  + s_sq[1][px];
    float mu = S * (1.f / 64.f);
    float var = Q * (1.f / 64.f) - mu * mu;
    float rs = rsqrtf(var + 1e-5f);
    __nv_bfloat16* Ah = (__nv_bfloat16*)As;
    #pragma unroll
    for (int it = 0; it < 32; it++) {
        int c = 2 * it + hi2;
        float nv = (v[it] - mu) * rs * s_lw[c] + s_lb[c];
        Ah[px * 72 + c] = __float2bfloat16(nv);
    }
    __syncthreads();

    float acc[2][8][4] = {};
    #pragma unroll
    for (int kc = 0; kc < 4; kc++) {
        uint32_t a[2][4];
        #pragma unroll
        for (int m = 0; m < 2; m++) {
            int pr = pxg * 32 + m * 16;
            const uint32_t* Ap = As + (pr + q) * 36 + kc * 8 + r;
            a[m][0] = Ap[0];
            a[m][1] = Ap[8 * 36];
            a[m][2] = Ap[4];
            a[m][3] = Ap[8 * 36 + 4];
        }
        #pragma unroll
        for (int nt = 0; nt < 8; nt++) {
            uint32_t bb[2];
            int ocb = ocg * 64 + nt * 8 + q;
            bb[0] = Bs[(kc * 8 + r)     * 132 + ocb];
            bb[1] = Bs[(kc * 8 + r + 4) * 132 + ocb];
            mma_bf16(acc[0][nt], a[0], bb);
            mma_bf16(acc[1][nt], a[1], bb);
        }
    }
    uint32_t* outw = ocg ? out2 : out1;
    #pragma unroll
    for (int m = 0; m < 2; m++) {
        #pragma unroll
        for (int nt = 0; nt < 8; nt++) {
            #pragma unroll
            for (int hh = 0; hh < 2; hh++) {
                int p = pxg * 32 + m * 16 + q + hh * 8;
                int ocl = nt * 8 + 2 * r;
                int ocG = ocg * 64 + ocl;
                float vx = acc[m][nt][hh * 2 + 0] + s_bin[ocG];
                float vy = acc[m][nt][hh * 2 + 1] + s_bin[ocG + 1];
                outw[(p0 + p) * 32 + (ocl >> 1)] = packbf2(vx, vy);
            }
        }
    }
}

// ---------------- dense KxK conv, bf16 MMA, 16x16 tile, MT=4, async B -------
template<int K, int PAD, int KOUT, int KOUTP, int SPAN>
__global__ __launch_bounds__(256) void k_conv_tc(
    const uint32_t* __restrict__ in, const uint32_t* __restrict__ wT,
    const float* __restrict__ bias, float* __restrict__ out)
{
    constexpr int HX = 16 + K - 1, HY = 16 + K - 1, HPX = HX * HY;
    constexpr int NT = SPAN / 16;
    constexpr int SPANP = SPAN + 4;
    constexpr int BW = 32 * SPANP;
    extern __shared__ uint32_t sm[];
    uint32_t* As = sm;                     // [HPX][36]
    uint32_t* B0 = sm + HPX * 36;
    uint32_t* B1 = B0 + BW;
    int tid = threadIdx.x, lane = tid & 31, w = tid >> 5;
    int q = lane >> 2, r = lane & 3;
    int pxg = w >> 1, ocg = w & 1;
    int b = blockIdx.z;
    int ty0 = blockIdx.y * 16, tx0 = blockIdx.x * 16;
    uint32_t b0a = smem_u32(B0), b1a = smem_u32(B1);
    float acc[4][NT][4] = {};

    for (int idx = tid; idx < HPX * 8; idx += 256) {
        int hp = idx >> 3, c8 = idx & 7;
        int hy = hp / HX, hx = hp % HX;
        int yy = ty0 + hy - PAD, xx = tx0 + hx - PAD;
        uint4 val = make_uint4(0u, 0u, 0u, 0u);
        if (yy >= 0 && yy < HH && xx >= 0 && xx < WWID)
            val = *(const uint4*)(in + ((size_t)((b * HH + yy) * WWID + xx)) * 32 + 4 * c8);
        *(uint4*)(As + hp * 36 + 4 * c8) = val;
    }
    for (int idx = tid; idx < 8 * SPAN; idx += 256) {
        int kp = idx / (SPAN / 4), oc4 = idx % (SPAN / 4);
        cpa16(b0a + (uint32_t)(kp * SPANP + 4 * oc4) * 4,
              wT + (size_t)kp * KOUTP + 4 * oc4);
    }
    cpa_commit();
    cpa_wait0();
    __syncthreads();

    for (int tap = 0; tap < K * K; tap++) {
        int ki = tap / K, kj = tap % K;
        if (tap + 1 < K * K) {
            uint32_t dsta = ((tap + 1) & 1) ? b1a : b0a;
            const uint32_t* src = wT + (size_t)(tap + 1) * 32 * KOUTP;
            for (int idx = tid; idx < 8 * SPAN; idx += 256) {
                int kp = idx / (SPAN / 4), oc4 = idx % (SPAN / 4);
                cpa16(dsta + (uint32_t)(kp * SPANP + 4 * oc4) * 4,
                      src + kp * KOUTP + 4 * oc4);
            }
            cpa_commit();
        }
        const uint32_t* Bc = (tap & 1) ? B1 : B0;
        #pragma unroll
        for (int kc = 0; kc < 4; kc++) {
            uint32_t a[4][4];
            #pragma unroll
            for (int m = 0; m < 4; m++) {
                int hbase = (pxg * 4 + m + ki) * HX + kj;
                const uint32_t* Ap = As + (hbase + q) * 36 + kc * 8 + r;
                a[m][0] = Ap[0];
                a[m][1] = Ap[8 * 36];
                a[m][2] = Ap[4];
                a[m][3] = Ap[8 * 36 + 4];
            }
            #pragma unroll
            for (int nt = 0; nt < NT; nt++) {
                uint32_t bb[2];
                int ocb = ocg * (SPAN / 2) + nt * 8 + q;
                bb[0] = Bc[(kc * 8 + r)     * SPANP + ocb];
                bb[1] = Bc[(kc * 8 + r + 4) * SPANP + ocb];
                #pragma unroll
                for (int m = 0; m < 4; m++) mma_bf16(acc[m][nt], a[m], bb);
            }
        }
        cpa_wait0();
        __syncthreads();
    }
    #pragma unroll
    for (int m = 0; m < 4; m++) {
        #pragma unroll
        for (int nt = 0; nt < NT; nt++) {
            #pragma unroll
            for (int hh = 0; hh < 2; hh++) {
                int p  = (pxg * 4 + m) * 16 + q + hh * 8;
                int pg = (b * HH + ty0 + (p >> 4)) * WWID + tx0 + (p & 15);
                int oc = ocg * (SPAN / 2) + nt * 8 + 2 * r;
                float v0 = acc[m][nt][hh * 2 + 0];
                float v1 = acc[m][nt][hh * 2 + 1];
                if (oc     < KOUT) out[(size_t)oc       * BHW + pg] = v0 + bias[oc];
                if (oc + 1 < KOUT) out[(size_t)(oc + 1) * BHW + pg] = v1 + bias[oc + 1];
            }
        }
    }
}

// ---------------- deformable KxK conv; optional fused final projection ------
template<int K, int PAD, int FUSE>
__global__ __launch_bounds__(256) void k_deform_tc(
    const uint32_t* __restrict__ in, const float* __restrict__ off,
    const uint32_t* __restrict__ wT, const float* __restrict__ bias,
    uint32_t* __restrict__ outb,
    const uint32_t* __restrict__ x2, const float* __restrict__ xin,
    const uint32_t* __restrict__ wC, const float* __restrict__ b_out,
    float* __restrict__ outf)
{
    extern __shared__ uint32_t sm[];
    uint32_t* As = sm;                       // [128][36] bf16x2
    uint32_t* B0 = sm + 128 * 36;            // [32][68] x2 buffers
    uint32_t* B1 = B0 + 32 * 68;
    int tid = threadIdx.x, lane = tid & 31, w = tid >> 5;
    int q = lane >> 2, r = lane & 3;
    int pxg = w >> 1, ocg = w & 1;
    int b = blockIdx.z;
    int ty0 = blockIdx.y * 8, tx0 = blockIdx.x * 16;
    const uint32_t* base = in + (size_t)b * HW * 32;
    uint32_t b0a = smem_u32(B0), b1a = smem_u32(B1);
    float acc[2][4][4] = {};

    for (int idx = tid; idx < 512; idx += 256) {
        int kp = idx >> 4, oc4 = idx & 15;
        cpa16(b0a + (uint32_t)(kp * 68 + 4 * oc4) * 4,
              wT + (size_t)kp * 64 + 4 * oc4);
    }
    cpa_commit();
    cpa_wait0();
    __syncthreads();

    for (int tap = 0; tap < K * K; tap++) {
        int ki = tap / K, kj = tap % K;
        if (tap + 1 < K * K) {
            uint32_t dsta = ((tap + 1) & 1) ? b1a : b0a;
            const uint32_t* src = wT + (size_t)(tap + 1) * 32 * 64;
            for (int idx = tid; idx < 512; idx += 256) {
                int kp = idx >> 4, oc4 = idx & 15;
                cpa16(dsta + (uint32_t)(kp * 68 + 4 * oc4) * 4,
                      src + kp * 64 + 4 * oc4);
            }
            cpa_commit();
        }
        const float* offy = off + (size_t)(2 * tap)     * BHW;
        const float* offx = off + (size_t)(2 * tap + 1) * BHW;
        #pragma unroll
        for (int it = 0; it < 4; it++) {
            int v  = it * 256 + tid;
            int p  = v >> 3, c8 = v & 7;
            int yy = ty0 + (p >> 4), xx = tx0 + (p & 15);
            int pg = (b * HH + yy) * WWID + xx;
            float oy = __ldg(offy + pg);
            float ox = __ldg(offx + pg);
            float py = (float)(yy + ki - PAD) + oy;
            float px = (float)(xx + kj - PAD) + ox;
            float fy = floorf(py), fx = floorf(px);
            int y0 = (int)fy, x0 = (int)fx;
            // bilinear weights as bf16x2 (packed math)
            float wy = py - fy, wx = px - fx;
            __nv_bfloat162 wa = __float2bfloat162_rn((1.f - wy) * (1.f - wx));
            __nv_bfloat162 wb = __float2bfloat162_rn((1.f - wy) * wx);
            __nv_bfloat162 wc = __float2bfloat162_rn(wy * (1.f - wx));
            __nv_bfloat162 wd = __float2bfloat162_rn(wy * wx);
            bool yv0 = (unsigned)y0       < HH;
            bool yv1 = (unsigned)(y0 + 1) < HH;
            bool xv0 = (unsigned)x0       < WWID;
            bool xv1 = (unsigned)(x0 + 1) < WWID;
            int r0 = (y0 * WWID + x0) * 32 + 4 * c8;   // 32-bit word offset
            const uint32_t* pb = base + r0;
            uint4 z = make_uint4(0u, 0u, 0u, 0u);
            uint4 u00 = z, u01 = z, u10 = z, u11 = z;
            if (yv0 && xv0) u00 = *(const uint4*)(pb);
            if (yv0 && xv1) u01 = *(const uint4*)(pb + 32);
            if (yv1 && xv0) u10 = *(const uint4*)(pb + 32 * WWID);
            if (yv1 && xv1) u11 = *(const uint4*)(pb + 32 * WWID + 32);
            uint4 res;
            __nv_bfloat162 t;
            t = __hmul2(wa, B2REF(u00.x)); t = __hfma2(wb, B2REF(u01.x), t);
            t = __hfma2(wc, B2REF(u10.x), t); t = __hfma2(wd, B2REF(u11.x), t);
            res.x = *(uint32_t*)&t;
            t = __hmul2(wa, B2REF(u00.y)); t = __hfma2(wb, B2REF(u01.y), t);
            t = __hfma2(wc, B2REF(u10.y), t); t = __hfma2(wd, B2REF(u11.y), t);
            res.y = *(uint32_t*)&t;
            t = __hmul2(wa, B2REF(u00.z)); t = __hfma2(wb, B2REF(u01.z), t);
            t = __hfma2(wc, B2REF(u10.z), t); t = __hfma2(wd, B2REF(u11.z), t);
            res.z = *(uint32_t*)&t;
            t = __hmul2(wa, B2REF(u00.w)); t = __hfma2(wb, B2REF(u01.w), t);
            t = __hfma2(wc, B2REF(u10.w), t); t = __hfma2(wd, B2REF(u11.w), t);
            res.w = *(uint32_t*)&t;
            *(uint4*)(As + p * 36 + 4 * c8) = res;
        }
        __syncthreads();
        const uint32_t* Bc = (tap & 1) ? B1 : B0;
        #pragma unroll
        for (int kc = 0; kc < 4; kc++) {
            uint32_t a[2][4];
            #pragma unroll
            for (int m = 0; m < 2; m++) {
                int pr = pxg * 32 + m * 16;
                const uint32_t* Ap = As + (pr + q) * 36 + kc * 8 + r;
                a[m][0] = Ap[0];
                a[m][1] = Ap[8 * 36];
                a[m][2] = Ap[4];
                a[m][3] = Ap[8 * 36 + 4];
            }
            #pragma unroll
            for (int nt = 0; nt < 4; nt++) {
                uint32_t bb[2];
                int ocb = ocg * 32 + nt * 8 + q;
                bb[0] = Bc[(kc * 8 + r)     * 68 + ocb];
                bb[1] = Bc[(kc * 8 + r + 4) * 68 + ocb];
                mma_bf16(acc[0][nt], a[0], bb);
                mma_bf16(acc[1][nt], a[1], bb);
            }
        }
        cpa_wait0();
        __syncthreads();
    }

    if (!FUSE) {
        #pragma unroll
        for (int m = 0; m < 2; m++) {
            #pragma unroll
            for (int nt = 0; nt < 4; nt++) {
                #pragma unroll
                for (int hh = 0; hh < 2; hh++) {
                    int p  = pxg * 32 + m * 16 + q + hh * 8;
                    int pg = (b * HH + ty0 + (p >> 4)) * WWID + tx0 + (p & 15);
                    int oc = ocg * 32 + nt * 8 + 2 * r;
                    float vx = acc[m][nt][hh * 2 + 0] + bias[oc];
                    float vy = acc[m][nt][hh * 2 + 1] + bias[oc + 1];
                    outb[(size_t)pg * 32 + (oc >> 1)] = packbf2(vx, vy);
                }
            }
        }
    } else {
        #pragma unroll
        for (int m = 0; m < 2; m++) {
            #pragma unroll
            for (int nt = 0; nt < 4; nt++) {
                #pragma unroll
                for (int hh = 0; hh < 2; hh++) {
                    int p  = pxg * 32 + m * 16 + q + hh * 8;
                    int pg = (b * HH + ty0 + (p >> 4)) * WWID + tx0 + (p & 15);
                    int oc = ocg * 32 + nt * 8 + 2 * r;
                    float2 xv = unpbf2(x2[(size_t)pg * 32 + (oc >> 1)]);
                    float vx = acc[m][nt][hh * 2 + 0] + bias[oc]     + xv.x;
                    float vy = acc[m][nt][hh * 2 + 1] + bias[oc + 1] + xv.y;
                    As[p * 36 + (oc >> 1)] = packbf2(vx, vy);
                }
            }
        }
        for (int idx = tid; idx < 512; idx += 256) {
            int kp = idx >> 4, oc4 = idx & 15;
            *(uint4*)(B0 + kp * 68 + 4 * oc4) = ((const uint4*)wC)[idx];
        }
        __syncthreads();
        #pragma unroll
        for (int m = 0; m < 2; m++)
            #pragma unroll
            for (int nt = 0; nt < 4; nt++)
                #pragma unroll
                for (int j = 0; j < 4; j++) acc[m][nt][j] = 0.f;
        #pragma unroll
        for (int kc = 0; kc < 4; kc++) {
            uint32_t a[2][4];
            #pragma unroll
            for (int m = 0; m < 2; m++) {
                int pr = pxg * 32 + m * 16;
                const uint32_t* Ap = As + (pr + q) * 36 + kc * 8 + r;
                a[m][0] = Ap[0];
                a[m][1] = Ap[8 * 36];
                a[m][2] = Ap[4];
                a[m][3] = Ap[8 * 36 + 4];
            }
            #pragma unroll
            for (int nt = 0; nt < 4; nt++) {
                uint32_t bb[2];
                int ocb = ocg * 32 + nt * 8 + q;
                bb[0] = B0[(kc * 8 + r)     * 68 + ocb];
                bb[1] = B0[(kc * 8 + r + 4) * 68 + ocb];
                mma_bf16(acc[0][nt], a[0], bb);
                mma_bf16(acc[1][nt], a[1], bb);
            }
        }
        #pragma unroll
        for (int m = 0; m < 2; m++) {
            #pragma unroll
            for (int nt = 0; nt < 4; nt++) {
                #pragma unroll
                for (int hh = 0; hh < 2; hh++) {
                    int p  = pxg * 32 + m * 16 + q + hh * 8;
                    int hw = (ty0 + (p >> 4)) * WWID + tx0 + (p & 15);
                    int oc = ocg * 32 + nt * 8 + 2 * r;
                    size_t a0 = ((size_t)b * 64 + oc) * HW + hw;
                    size_t a1 = a0 + HW;
                    outf[a0] = acc[m][nt][hh * 2 + 0] + b_out[oc]     + xin[a0];
                    outf[a1] = acc[m][nt][hh * 2 + 1] + b_out[oc + 1] + xin[a1];
                }
            }
        }
    }
}

// ---------------- launch --------------------------------------------------
extern "C" void kernel_launch(void* const* d_in, const int* in_sizes, int n_in,
                              void* d_out, int out_size) {
    const float* x    = (const float*)d_in[0];
    const float* ln_w = (const float*)d_in[1];
    const float* ln_b = (const float*)d_in[2];
    const float* w_in = (const float*)d_in[3];
    const float* b_in = (const float*)d_in[4];
    const float* w_out= (const float*)d_in[5];
    const float* b_out= (const float*)d_in[6];
    const float* dw1  = (const float*)d_in[7];
    const float* db1  = (const float*)d_in[8];
    const float* dw2  = (const float*)d_in[9];
    const float* db2  = (const float*)d_in[10];
    const float* dw3  = (const float*)d_in[11];
    const float* db3  = (const float*)d_in[12];
    const float* ow1  = (const float*)d_in[13];
    const float* ob1  = (const float*)d_in[14];
    const float* ow2  = (const float*)d_in[15];
    const float* ob2  = (const float*)d_in[16];
    const float* ow3  = (const float*)d_in[17];
    const float* ob3  = (const float*)d_in[18];
    float* out = (float*)d_out;

    float *poff;
    uint32_t *px1, *px2, *py, *pwIn, *pwA1, *pwB1, *pwA2, *pwB2, *pwA3, *pwB3, *pwC;
    cudaGetSymbolAddress((void**)&px1,  g_x1);
    cudaGetSymbolAddress((void**)&px2,  g_x2);
    cudaGetSymbolAddress((void**)&py,   g_y);
    cudaGetSymbolAddress((void**)&poff, g_off);
    cudaGetSymbolAddress((void**)&pwIn, g_wIn);
    cudaGetSymbolAddress((void**)&pwA1, g_wA1);
    cudaGetSymbolAddress((void**)&pwB1, g_wB1);
    cudaGetSymbolAddress((void**)&pwA2, g_wA2);
    cudaGetSymbolAddress((void**)&pwB2, g_wB2);
    cudaGetSymbolAddress((void**)&pwA3, g_wA3);
    cudaGetSymbolAddress((void**)&pwB3, g_wB3);
    cudaGetSymbolAddress((void**)&pwC,  g_wC);

    const int SMC1 = (20 * 20 * 36 + 2 * 32 * 132) * 4;   // 91.4 KB
    const int SMC2 = (20 * 20 * 36 + 2 * 32 * 68)  * 4;   // 75.0 KB
    const int SMC3 = (18 * 18 * 36 + 2 * 32 * 36)  * 4;   // 55.9 KB
    const int SMD  = (128 * 36 + 2 * 32 * 68) * 4;        // 35.4 KB

    cudaFuncSetAttribute(k_conv_tc<5,2,98,128,128>, cudaFuncAttributeMaxDynamicSharedMemorySize, SMC1);
    cudaFuncSetAttribute(k_conv_tc<5,2,50,64,64>,   cudaFuncAttributeMaxDynamicSharedMemorySize, SMC2);
    cudaFuncSetAttribute(k_conv_tc<3,1,18,32,32>,   cudaFuncAttributeMaxDynamicSharedMemorySize, SMC3);
    cudaFuncSetAttribute(k_deform_tc<7,3,0>, cudaFuncAttributeMaxDynamicSharedMemorySize, SMD);
    cudaFuncSetAttribute(k_deform_tc<5,2,0>, cudaFuncAttributeMaxDynamicSharedMemorySize, SMD);
    cudaFuncSetAttribute(k_deform_tc<3,1,1>, cudaFuncAttributeMaxDynamicSharedMemorySize, SMD);

    dim3 ctiles(WWID / 16, HH / 16, BATCH);  // convs: 16x16 px tiles
    dim3 dtiles(WWID / 16, HH / 8,  BATCH);  // deforms: 16x8 px tiles

    k_pack_all<<<256, 256>>>(w_in, ow1, dw1, ow2, dw2, ow3, dw3, w_out,
                             pwIn, pwA1, pwB1, pwA2, pwB2, pwA3, pwB3, pwC);

    k_ln_win_tc<<<BHW / 128, 256>>>(x, ln_w, ln_b, pwIn, b_in, px1, px2);

    // stage 1
    k_conv_tc<5,2,98,128,128><<<ctiles, 256, SMC1>>>(px1, pwA1, ob1, poff);
    k_deform_tc<7,3,0><<<dtiles, 256, SMD>>>(px1, poff, pwB1, db1, py,
                                             nullptr, nullptr, nullptr, nullptr, nullptr);
    // stage 2
    k_conv_tc<5,2,50,64,64><<<ctiles, 256, SMC2>>>(py, pwA2, ob2, poff);
    k_deform_tc<5,2,0><<<dtiles, 256, SMD>>>(py, poff, pwB2, db2, px1,
                                             nullptr, nullptr, nullptr, nullptr, nullptr);
    // stage 3 (deform fused with final projection + residual)
    k_conv_tc<3,1,18,32,32><<<ctiles, 256, SMC3>>>(px1, pwA3, ob3, poff);
    k_deform_tc<3,1,1><<<dtiles, 256, SMD>>>(px1, poff, pwB3, db3, nullptr,
                                             px2, x, pwC, b_out, out);
}